// round 11
// baseline (speedup 1.0000x reference)
#include <cuda_runtime.h>
#include <cuda_bf16.h>
#include <math.h>
#include <stdint.h>

#define NN 40000
#define NE 640000
#define DIM 128
#define NH 8
#define DH 16

typedef __nv_bfloat16 bf16;

// ---------------- scratch (device globals: allocation-free) ----------------
__device__ float g_Qh[(size_t)NN * DIM];
__device__ float g_Kh[(size_t)NN * DIM];
__device__ float g_Vh[(size_t)NN * DIM];
__device__ float g_lg[(size_t)NE * NH];
__device__ float g_den[(size_t)NN * NH];
__device__ float g_wV[(size_t)NN * DIM];
__device__ float g_rowV[(size_t)NN * DIM];
__device__ float g_v1[(size_t)NN * DIM];
__device__ float g_v2[(size_t)NN * DIM];
__device__ float g_s1[2 * DIM];
__device__ float g_s2[2 * DIM];
__device__ float g_se[2 * DIM];
// bf16 hi/lo pairs
__device__ bf16 g_xhi[(size_t)NN * DIM],  g_xlo[(size_t)NN * DIM];
__device__ bf16 g_eahi[(size_t)NE * DIM], g_ealo[(size_t)NE * DIM];
__device__ bf16 g_ethi[(size_t)NE * DIM], g_etlo[(size_t)NE * DIM];
__device__ bf16 g_hatth[(size_t)NN * DIM], g_hattl[(size_t)NN * DIM];
__device__ bf16 g_hbnh[(size_t)NN * DIM],  g_hbnl[(size_t)NN * DIM];
__device__ bf16 g_h2ah[(size_t)NN * 2 * DIM], g_h2al[(size_t)NN * 2 * DIM];
__device__ bf16 g_wq_h[DIM * DIM], g_wq_l[DIM * DIM];
__device__ bf16 g_wk_h[DIM * DIM], g_wk_l[DIM * DIM];
__device__ bf16 g_wv_h[DIM * DIM], g_wv_l[DIM * DIM];
__device__ bf16 g_we_h[DIM * 2 * DIM], g_we_l[DIM * 2 * DIM];
__device__ bf16 g_woh_h[DIM * DIM], g_woh_l[DIM * DIM];
__device__ bf16 g_woe_h[DIM * DIM], g_woe_l[DIM * DIM];
__device__ bf16 g_w1_h[DIM * 2 * DIM], g_w1_l[DIM * 2 * DIM];
__device__ bf16 g_w2_h[2 * DIM * DIM], g_w2_l[2 * DIM * DIM];

static inline int cdiv(long long a, long long b) { return (int)((a + b - 1) / b); }

// ---------------- helpers ----------------
__device__ __forceinline__ uint32_t smem_u32(const void* p) {
    uint32_t a;
    asm("{ .reg .u64 t; cvta.to.shared.u64 t, %1; cvt.u32.u64 %0, t; }" : "=r"(a) : "l"(p));
    return a;
}
__device__ __forceinline__ void ldsm4(uint32_t (&r)[4], uint32_t addr) {
    asm volatile("ldmatrix.sync.aligned.m8n8.x4.shared.b16 {%0,%1,%2,%3}, [%4];"
                 : "=r"(r[0]), "=r"(r[1]), "=r"(r[2]), "=r"(r[3]) : "r"(addr));
}
__device__ __forceinline__ void ldsm4t(uint32_t (&r)[4], uint32_t addr) {
    asm volatile("ldmatrix.sync.aligned.m8n8.x4.trans.shared.b16 {%0,%1,%2,%3}, [%4];"
                 : "=r"(r[0]), "=r"(r[1]), "=r"(r[2]), "=r"(r[3]) : "r"(addr));
}
__device__ __forceinline__ void mma16816(float (&d)[4], const uint32_t (&a)[4], const uint32_t* b) {
    asm volatile("mma.sync.aligned.m16n8k16.row.col.f32.bf16.bf16.f32 "
                 "{%0,%1,%2,%3}, {%4,%5,%6,%7}, {%8,%9}, {%0,%1,%2,%3};"
                 : "+f"(d[0]), "+f"(d[1]), "+f"(d[2]), "+f"(d[3])
                 : "r"(a[0]), "r"(a[1]), "r"(a[2]), "r"(a[3]), "r"(b[0]), "r"(b[1]));
}
__device__ __forceinline__ uint32_t pack2(bf16 a, bf16 b) {
    return (uint32_t)__bfloat16_as_ushort(a) | ((uint32_t)__bfloat16_as_ushort(b) << 16);
}
__device__ __forceinline__ float2 up2(uint32_t u) {
    return make_float2(__bfloat162float(__ushort_as_bfloat16((unsigned short)(u & 0xffff))),
                       __bfloat162float(__ushort_as_bfloat16((unsigned short)(u >> 16))));
}
__device__ __forceinline__ void split4(float4 v, uint2& hi, uint2& lo) {
    bf16 hx = __float2bfloat16(v.x), hy = __float2bfloat16(v.y);
    bf16 hz = __float2bfloat16(v.z), hw = __float2bfloat16(v.w);
    hi = make_uint2(pack2(hx, hy), pack2(hz, hw));
    lo = make_uint2(pack2(__float2bfloat16(v.x - __bfloat162float(hx)),
                          __float2bfloat16(v.y - __bfloat162float(hy))),
                    pack2(__float2bfloat16(v.z - __bfloat162float(hz)),
                          __float2bfloat16(v.w - __bfloat162float(hw))));
}
__device__ __forceinline__ uint32_t packsplit(float a, float b, uint32_t& lo) {
    bf16 h0 = __float2bfloat16(a), h1 = __float2bfloat16(b);
    lo = pack2(__float2bfloat16(a - __bfloat162float(h0)),
               __float2bfloat16(b - __bfloat162float(h1)));
    return pack2(h0, h1);
}
__device__ __forceinline__ void cp16(uint32_t dst, const void* src, int sz) {
    asm volatile("cp.async.cg.shared.global [%0], [%1], 16, %2;" :: "r"(dst), "l"(src), "r"(sz));
}
#define CP_COMMIT() asm volatile("cp.async.commit_group;" ::: "memory")
#define CP_WAIT0()  asm volatile("cp.async.wait_group 0;" ::: "memory")
#define CP_WAIT1()  asm volatile("cp.async.wait_group 1;" ::: "memory")

__device__ __forceinline__ void red4(float* p, float a, float b, float c, float d) {
    asm volatile("red.global.add.v4.f32 [%0], {%1,%2,%3,%4};"
                 :: "l"(p), "f"(a), "f"(b), "f"(c), "f"(d) : "memory");
}
__device__ __forceinline__ void redf(float* p, float a) {
    asm volatile("red.global.add.f32 [%0], %1;" :: "l"(p), "f"(a) : "memory");
}

// ---------------- bf16-pair GEMM core: 128x128 tile, 256 thr, 2-stage pipe ----
#define STG    37888u
#define AHI_O  0u
#define ALO_O  10240u
#define BHI_O  20480u
#define BLO_O  29184u
#define SMB_TOTAL 75776

struct GemmCoreB {
    uint32_t sb;
    int tid, lid, wm, wn, m0, n0;
    float acc[4][4][4];

    __device__ __forceinline__ void init(uint8_t* smp, int bm, int bn) {
        sb = smem_u32(smp);
        tid = threadIdx.x; lid = tid & 31;
        int wid = tid >> 5;
        wm = wid >> 2; wn = wid & 3;
        m0 = bm * 128; n0 = bn * 128;
#pragma unroll
        for (int i = 0; i < 4; i++)
#pragma unroll
            for (int j = 0; j < 4; j++)
#pragma unroll
                for (int q = 0; q < 4; q++) acc[i][j][q] = 0.f;
    }
    __device__ __forceinline__ void stage(int buf, const bf16* Ahi, const bf16* Alo,
                                          const bf16* Whi, const bf16* Wlo,
                                          int M, int Ncols, int K, int kb) {
        uint32_t base = sb + (uint32_t)buf * STG;
#pragma unroll
        for (int i = 0; i < 2; i++) {
            int c = tid + i * 256;
            int row = c >> 2, gr = c & 3;
            bool ok = (m0 + row) < M;
            size_t go = (size_t)(ok ? m0 + row : 0) * K + kb + gr * 8;
            uint32_t d = base + (uint32_t)row * 80 + (uint32_t)gr * 16;
            cp16(d + AHI_O, Ahi + go, ok ? 16 : 0);
            cp16(d + ALO_O, Alo + go, ok ? 16 : 0);
        }
#pragma unroll
        for (int i = 0; i < 2; i++) {
            int c = tid + i * 256;
            int k = c >> 4, gr = c & 15;
            size_t go = (size_t)(kb + k) * Ncols + n0 + gr * 8;
            uint32_t d = base + (uint32_t)k * 272 + (uint32_t)gr * 16;
            cp16(d + BHI_O, Whi + go, 16);
            cp16(d + BLO_O, Wlo + go, 16);
        }
        CP_COMMIT();
    }
    __device__ __forceinline__ void compute(int buf) {
        uint32_t base = sb + (uint32_t)buf * STG;
#pragma unroll
        for (int ks = 0; ks < 32; ks += 16) {
            uint32_t bhi[4][2], blo[4][2];
            const uint32_t brow = (uint32_t)(ks + (lid & 15)) * 272 + (uint32_t)((lid >> 4) * 16);
#pragma unroll
            for (int p = 0; p < 2; p++) {
                uint32_t baddr = base + brow + (uint32_t)(wn * 32 + p * 16) * 2;
                uint32_t r[4];
                ldsm4t(r, baddr + BHI_O);
                bhi[2 * p][0] = r[0]; bhi[2 * p][1] = r[1];
                bhi[2 * p + 1][0] = r[2]; bhi[2 * p + 1][1] = r[3];
                ldsm4t(r, baddr + BLO_O);
                blo[2 * p][0] = r[0]; blo[2 * p][1] = r[1];
                blo[2 * p + 1][0] = r[2]; blo[2 * p + 1][1] = r[3];
            }
            const uint32_t arow = (uint32_t)(wm * 64 + (lid & 15)) * 80
                                + (uint32_t)ks * 2 + (uint32_t)(lid >> 4) * 16;
#pragma unroll
            for (int mt = 0; mt < 4; mt++) {
                uint32_t aaddr = base + arow + (uint32_t)mt * (16 * 80);
                uint32_t ahi4[4], alo4[4];
                ldsm4(ahi4, aaddr + AHI_O);
                ldsm4(alo4, aaddr + ALO_O);
#pragma unroll
                for (int nt = 0; nt < 4; nt++) {
                    mma16816(acc[mt][nt], ahi4, bhi[nt]);
                    mma16816(acc[mt][nt], ahi4, blo[nt]);
                    mma16816(acc[mt][nt], alo4, bhi[nt]);
                }
            }
        }
    }
    __device__ __forceinline__ void run(const bf16* Ahi, const bf16* Alo,
                                        const bf16* Whi, const bf16* Wlo,
                                        int M, int Ncols, int K) {
        const int nch = K >> 5;
        stage(0, Ahi, Alo, Whi, Wlo, M, Ncols, K, 0);
        if (nch > 1) stage(1, Ahi, Alo, Whi, Wlo, M, Ncols, K, 32);
        for (int i = 0; i < nch; i++) {
            if (i == nch - 1) { CP_WAIT0(); } else { CP_WAIT1(); }
            __syncthreads();
            compute(i & 1);
            if (i + 2 < nch) {
                __syncthreads();
                stage(i & 1, Ahi, Alo, Whi, Wlo, M, Ncols, K, (i + 2) * 32);
            }
        }
    }
};

// ---------------- generic GEMM (m-tile = blockIdx.y, n-tile = blockIdx.x) ----
// RESMODE 0=none 1=f32 2=bf16pair; OUTMODE 0=f32 1=pair; STATS: fused col sums
template <int RESMODE, int OUTMODE, bool RELU, bool STATS>
__global__ void __launch_bounds__(256, 2)
mma_gemmB(const bf16* __restrict__ Ahi, const bf16* __restrict__ Alo,
          const bf16* __restrict__ Whi, const bf16* __restrict__ Wlo,
          const float* __restrict__ bias, const float* __restrict__ resf,
          const bf16* __restrict__ reshi, const bf16* __restrict__ reslo,
          float* __restrict__ Cf, bf16* __restrict__ Chi, bf16* __restrict__ Clo,
          float* __restrict__ stats, int M, int Ncols, int K)
{
    extern __shared__ __align__(16) uint8_t sm[];
    GemmCoreB g;
    g.init(sm, blockIdx.y, blockIdx.x);
    g.run(Ahi, Alo, Whi, Wlo, M, Ncols, K);

    float ts0[4], ts1[4], tq0[4], tq1[4];
    if (STATS) {
#pragma unroll
        for (int nt = 0; nt < 4; nt++) { ts0[nt] = ts1[nt] = tq0[nt] = tq1[nt] = 0.f; }
    }

    const int qr = g.lid >> 2, qc = (g.lid & 3) * 2;
#pragma unroll
    for (int mt = 0; mt < 4; mt++) {
#pragma unroll
        for (int nt = 0; nt < 4; nt++) {
            int col = g.n0 + g.wn * 32 + nt * 8 + qc;
            float b0 = bias[col], b1 = bias[col + 1];
#pragma unroll
            for (int half = 0; half < 2; half++) {
                int row = g.m0 + g.wm * 64 + mt * 16 + qr + half * 8;
                if (row >= M) continue;
                float o0 = g.acc[mt][nt][half * 2 + 0] + b0;
                float o1 = g.acc[mt][nt][half * 2 + 1] + b1;
                size_t off = (size_t)row * Ncols + col;
                if (RESMODE == 1) {
                    float2 rr = *(const float2*)(resf + off);
                    o0 += rr.x; o1 += rr.y;
                } else if (RESMODE == 2) {
                    float2 rh = up2(*(const uint32_t*)(reshi + off));
                    float2 rl = up2(*(const uint32_t*)(reslo + off));
                    o0 += rh.x + rl.x; o1 += rh.y + rl.y;
                }
                if (RELU) { o0 = fmaxf(o0, 0.f); o1 = fmaxf(o1, 0.f); }
                if (STATS) {
                    ts0[nt] += o0; ts1[nt] += o1;
                    tq0[nt] = fmaf(o0, o0, tq0[nt]); tq1[nt] = fmaf(o1, o1, tq1[nt]);
                }
                if (OUTMODE == 0) {
                    *(float2*)(Cf + off) = make_float2(o0, o1);
                } else {
                    uint32_t lw, hw = packsplit(o0, o1, lw);
                    *(uint32_t*)(Chi + off) = hw;
                    *(uint32_t*)(Clo + off) = lw;
                }
            }
        }
    }
    if (STATS) {
#pragma unroll
        for (int nt = 0; nt < 4; nt++) {
            float a = ts0[nt], b = ts1[nt], c = tq0[nt], d = tq1[nt];
#pragma unroll
            for (int m = 4; m <= 16; m <<= 1) {
                a += __shfl_xor_sync(0xffffffff, a, m);
                b += __shfl_xor_sync(0xffffffff, b, m);
                c += __shfl_xor_sync(0xffffffff, c, m);
                d += __shfl_xor_sync(0xffffffff, d, m);
            }
            if (qr == 0) {
                int col = g.n0 + g.wn * 32 + nt * 8 + qc;
                redf(stats + col, a);
                redf(stats + col + 1, b);
                redf(stats + DIM + col, c);
                redf(stats + DIM + col + 1, d);
            }
        }
    }
}

// ---------------- fused QKV (blockIdx.x selects weight, y = m tile) ----------
__global__ void __launch_bounds__(256, 2)
qkv_gemm(const bf16* __restrict__ xhi, const bf16* __restrict__ xlo,
         const bf16* __restrict__ qh, const bf16* __restrict__ ql,
         const bf16* __restrict__ kh, const bf16* __restrict__ kl,
         const bf16* __restrict__ vh, const bf16* __restrict__ vl,
         const float* __restrict__ bq, const float* __restrict__ bk,
         const float* __restrict__ bv,
         float* __restrict__ Qo, float* __restrict__ Ko, float* __restrict__ Vo)
{
    extern __shared__ __align__(16) uint8_t sm[];
    const bf16* Whi = qh; const bf16* Wlo = ql;
    const float* bias = bq; float* C = Qo;
    if (blockIdx.x == 1) { Whi = kh; Wlo = kl; bias = bk; C = Ko; }
    else if (blockIdx.x == 2) { Whi = vh; Wlo = vl; bias = bv; C = Vo; }

    GemmCoreB g;
    g.init(sm, blockIdx.y, 0);
    g.run(xhi, xlo, Whi, Wlo, NN, 128, 128);

    const int qr = g.lid >> 2, qc = (g.lid & 3) * 2;
#pragma unroll
    for (int mt = 0; mt < 4; mt++) {
#pragma unroll
        for (int nt = 0; nt < 4; nt++) {
            int col = g.wn * 32 + nt * 8 + qc;
            float b0 = bias[col], b1 = bias[col + 1];
#pragma unroll
            for (int half = 0; half < 2; half++) {
                int row = g.m0 + g.wm * 64 + mt * 16 + qr + half * 8;
                if (row >= NN) continue;
                *(float2*)(C + (size_t)row * 128 + col) =
                    make_float2(g.acc[mt][nt][half * 2 + 0] + b0,
                                g.acc[mt][nt][half * 2 + 1] + b1);
            }
        }
    }
}

// ---------------- fused Ee GEMM + edge score/logit/exp + rowV/den scatter ---
// grid (2, gE): blockIdx.x = head-half (n-tile), blockIdx.y = edge tile.
// logits clamped to [-5,5] BEFORE segment-max in reference => max-free softmax
// exact; lg stores ex = exp(logit). rowV/den reductions use register-resident
// e_t (no extra loads).
union U16 { float4 q[4]; float f[16]; };

__global__ void __launch_bounds__(256, 2)
edge_gemm_fused(const bf16* __restrict__ eahi, const bf16* __restrict__ ealo,
                const bf16* __restrict__ weh, const bf16* __restrict__ wel,
                const float* __restrict__ bias,
                const int* __restrict__ ei, const float* __restrict__ Aw,
                const float* __restrict__ Qh, const float* __restrict__ Kh,
                bf16* __restrict__ ethi, bf16* __restrict__ etlo,
                float* __restrict__ lg, float* __restrict__ den,
                float* __restrict__ rowV)
{
    extern __shared__ __align__(16) uint8_t sm[];
    __shared__ float sAw[DIM];
    if (threadIdx.x < DIM) sAw[threadIdx.x] = Aw[threadIdx.x];

    GemmCoreB g;
    g.init(sm, blockIdx.y, blockIdx.x);
    g.run(eahi, ealo, weh, wel, NE, 256, 128);

    __syncthreads();   // tiles dead; reuse smem for the output tile
    float* sC = (float*)sm;          // 128 rows x 132 pitch
    const int qr = g.lid >> 2, qc = (g.lid & 3) * 2;
#pragma unroll
    for (int mt = 0; mt < 4; mt++) {
#pragma unroll
        for (int nt = 0; nt < 4; nt++) {
            int col = g.wn * 32 + nt * 8 + qc;
            float b0 = bias[g.n0 + col], b1 = bias[g.n0 + col + 1];
#pragma unroll
            for (int half = 0; half < 2; half++) {
                int row = g.wm * 64 + mt * 16 + qr + half * 8;
                *(float2*)(sC + row * 132 + col) =
                    make_float2(g.acc[mt][nt][half * 2 + 0] + b0,
                                g.acc[mt][nt][half * 2 + 1] + b1);
            }
        }
    }
    __syncthreads();

    const int e = threadIdx.x & 127;
    const int ge = g.m0 + e;                    // NE % 128 == 0
    const int src = ei[ge], dst = ei[NE + ge];
#pragma unroll
    for (int u = 0; u < 2; u++) {
        const int hl = (threadIdx.x >> 7) * 2 + u;
        const int h = blockIdx.x * 4 + hl;
        const float* ew = sC + e * 132 + hl * 32;
        U16 K4, Q4, EW, EB, ET;
        const float4* kp = (const float4*)(Kh + (size_t)src * DIM + h * DH);
        const float4* qp = (const float4*)(Qh + (size_t)dst * DIM + h * DH);
#pragma unroll
        for (int q = 0; q < 4; q++) {
            K4.q[q] = kp[q]; Q4.q[q] = qp[q];
            EW.q[q] = *(const float4*)(ew + q * 4);
            EB.q[q] = *(const float4*)(ew + 16 + q * 4);
        }
        float logit = 0.f;
#pragma unroll
        for (int d = 0; d < 16; d++) {
            float s = (K4.f[d] + Q4.f[d]) * EW.f[d];
            float a = fabsf(s);
            float r = (a > 0.f) ? copysignf(sqrtf(a), s) : 0.f;
            float v = fmaxf(r + EB.f[d], 0.f);
            ET.f[d] = v;
            logit = fmaf(v, sAw[d * NH + h], logit);
        }
        logit = fminf(fmaxf(logit, -5.f), 5.f);
        float ex = expf(logit);

        // write et as bf16 hi/lo (feeds WOe GEMM and wV-scatter is V-only)
        uint32_t hw[8], lw[8];
#pragma unroll
        for (int q = 0; q < 8; q++) hw[q] = packsplit(ET.f[2 * q], ET.f[2 * q + 1], lw[q]);
        bf16* ph = ethi + (size_t)ge * DIM + h * DH;
        bf16* pl = etlo + (size_t)ge * DIM + h * DH;
        *(uint4*)ph       = make_uint4(hw[0], hw[1], hw[2], hw[3]);
        *((uint4*)ph + 1) = make_uint4(hw[4], hw[5], hw[6], hw[7]);
        *(uint4*)pl       = make_uint4(lw[0], lw[1], lw[2], lw[3]);
        *((uint4*)pl + 1) = make_uint4(lw[4], lw[5], lw[6], lw[7]);
        lg[ge * NH + h] = ex;

        // rowV/den reductions from register-resident e_t (no loads)
        redf(&den[dst * NH + h], ex);
        float* rv = rowV + (size_t)dst * DIM + h * DH;
#pragma unroll
        for (int q = 0; q < 4; q++)
            red4(rv + q * 4, ET.f[q * 4] * ex, ET.f[q * 4 + 1] * ex,
                 ET.f[q * 4 + 2] * ex, ET.f[q * 4 + 3] * ex);
    }
}

// ---------------- misc / edge / node / bn kernels ----------------
__global__ void preconv(const float* __restrict__ in, bf16* __restrict__ hi,
                        bf16* __restrict__ lo, long long n)
{
    long long i = ((long long)blockIdx.x * blockDim.x + threadIdx.x) * 4;
    if (i >= n) return;
    float4 v = *(const float4*)(in + i);
    uint2 h, l;
    split4(v, h, l);
    *(uint2*)(hi + i) = h;
    *(uint2*)(lo + i) = l;
}

// V-only scatter: read lg (ex), gather Vh, reduce wV. No et re-read, no den.
__global__ void edge_scatter(const int* __restrict__ ei, const float* __restrict__ lg,
                             const float* __restrict__ Vh, float* __restrict__ wV)
{
    int t = blockIdx.x * blockDim.x + threadIdx.x;
    if (t >= NE * NH) return;
    int e = t >> 3, h = t & 7;
    int src = ei[e], dst = ei[NE + e];
    float ex = lg[t];
    U16 V4;
    const float4* vp = (const float4*)(Vh + (size_t)src * DIM + h * DH);
#pragma unroll
    for (int q = 0; q < 4; q++) V4.q[q] = vp[q];
    float* wv = wV + (size_t)dst * DIM + h * DH;
#pragma unroll
    for (int q = 0; q < 4; q++)
        red4(wv + q * 4, V4.q[q].x * ex, V4.q[q].y * ex, V4.q[q].z * ex, V4.q[q].w * ex);
}

__global__ void node_fix(const float* __restrict__ wV, const float* __restrict__ rowV,
                         const float* __restrict__ den,
                         const float* __restrict__ VeRow, const float* __restrict__ log_deg,
                         const float* __restrict__ deg_coef,
                         bf16* __restrict__ hatth, bf16* __restrict__ hattl)
{
    int t = blockIdx.x * blockDim.x + threadIdx.x;
    if (t >= NN * 64) return;
    int n = t >> 6, c0 = (t & 63) * 2, h = c0 >> 4, co = c0 & 15;
    size_t off = (size_t)n * DIM + c0;
    float inv = 1.f / (den[n * NH + h] + 1e-16f);
    float a0 = wV[off], a1 = wV[off + 1];
    const float* rv = rowV + (size_t)n * DIM + h * DH;
#pragma unroll
    for (int d2 = 0; d2 < 16; d2++) {
        float r = rv[d2];
        a0 = fmaf(r, VeRow[d2 * DIM + h * DH + co], a0);
        a1 = fmaf(r, VeRow[d2 * DIM + h * DH + co + 1], a1);
    }
    a0 *= inv; a1 *= inv;
    float ld = log_deg[n];
    float o0 = a0 * (deg_coef[2 * c0] + ld * deg_coef[2 * c0 + 1]);
    float o1 = a1 * (deg_coef[2 * c0 + 2] + ld * deg_coef[2 * c0 + 3]);
    uint32_t lw, hw = packsplit(o0, o1, lw);
    *(uint32_t*)(hatth + off) = hw;
    *(uint32_t*)(hattl + off) = lw;
}

template <bool PAIR>
__global__ void bn_apply(const float* __restrict__ v, float* __restrict__ outf,
                         bf16* __restrict__ outhi, bf16* __restrict__ outlo, int M,
                         const float* __restrict__ sums,
                         const float* __restrict__ g, const float* __restrict__ b, float invM)
{
    long long i = ((long long)blockIdx.x * blockDim.x + threadIdx.x) * 2;
    if (i >= (long long)M * DIM) return;
    int c = (int)(i & (DIM - 1));
    float m0 = sums[c] * invM, m1 = sums[c + 1] * invM;
    float var0 = fmaf(-m0, m0, sums[DIM + c] * invM);
    float var1 = fmaf(-m1, m1, sums[DIM + c + 1] * invM);
    float2 vv = *(const float2*)(v + i);
    float o0 = (vv.x - m0) * rsqrtf(var0 + 1e-5f) * g[c] + b[c];
    float o1 = (vv.y - m1) * rsqrtf(var1 + 1e-5f) * g[c + 1] + b[c + 1];
    if (!PAIR) {
        *(float2*)(outf + i) = make_float2(o0, o1);
    } else {
        uint32_t lw, hw = packsplit(o0, o1, lw);
        *(uint32_t*)(outhi + i) = hw;
        *(uint32_t*)(outlo + i) = lw;
    }
}

// ---------------- launch ----------------
#define SYM(var, sym) cudaGetSymbolAddress((void**)&var, sym)

extern "C" void kernel_launch(void* const* d_in, const int* in_sizes, int n_in,
                              void* d_out, int out_size)
{
    const float* x         = (const float*)d_in[0];
    const float* edge_attr = (const float*)d_in[1];
    const int*   ei        = (const int*)d_in[2];
    const float* log_deg   = (const float*)d_in[3];
    const float* Wq = (const float*)d_in[4],  *bq  = (const float*)d_in[5];
    const float* Wk = (const float*)d_in[6],  *bk  = (const float*)d_in[7];
    const float* We = (const float*)d_in[8],  *be  = (const float*)d_in[9];
    const float* Wv = (const float*)d_in[10], *bv  = (const float*)d_in[11];
    const float* Aw = (const float*)d_in[12], *VeRow = (const float*)d_in[13];
    const float* WOh = (const float*)d_in[14], *bOh = (const float*)d_in[15];
    const float* WOe = (const float*)d_in[16], *bOe = (const float*)d_in[17];
    const float* deg_coef = (const float*)d_in[18];
    const float* g1h = (const float*)d_in[19], *b1h = (const float*)d_in[20];
    const float* g1e = (const float*)d_in[21], *b1e = (const float*)d_in[22];
    const float* g2h = (const float*)d_in[23], *b2h = (const float*)d_in[24];
    const float* W1 = (const float*)d_in[25], *b1 = (const float*)d_in[26];
    const float* W2 = (const float*)d_in[27], *b2 = (const float*)d_in[28];

    float *Qh, *Kh, *Vh, *lg, *den, *wV, *rowV, *v1, *v2, *s1, *s2, *se;
    SYM(Qh, g_Qh); SYM(Kh, g_Kh); SYM(Vh, g_Vh);
    SYM(lg, g_lg); SYM(den, g_den);
    SYM(wV, g_wV); SYM(rowV, g_rowV);
    SYM(v1, g_v1); SYM(v2, g_v2);
    SYM(s1, g_s1); SYM(s2, g_s2); SYM(se, g_se);
    bf16 *xhi, *xlo, *eahi, *ealo, *ethi, *etlo, *hatth, *hattl, *hbnh, *hbnl, *h2ah, *h2al;
    SYM(xhi, g_xhi); SYM(xlo, g_xlo); SYM(eahi, g_eahi); SYM(ealo, g_ealo);
    SYM(ethi, g_ethi); SYM(etlo, g_etlo);
    SYM(hatth, g_hatth); SYM(hattl, g_hattl);
    SYM(hbnh, g_hbnh); SYM(hbnl, g_hbnl);
    SYM(h2ah, g_h2ah); SYM(h2al, g_h2al);
    bf16 *wq_h, *wq_l, *wk_h, *wk_l, *wv_h, *wv_l, *we_h, *we_l;
    bf16 *woh_h, *woh_l, *woe_h, *woe_l, *w1_h, *w1_l, *w2_h, *w2_l;
    SYM(wq_h, g_wq_h); SYM(wq_l, g_wq_l); SYM(wk_h, g_wk_h); SYM(wk_l, g_wk_l);
    SYM(wv_h, g_wv_h); SYM(wv_l, g_wv_l); SYM(we_h, g_we_h); SYM(we_l, g_we_l);
    SYM(woh_h, g_woh_h); SYM(woh_l, g_woh_l); SYM(woe_h, g_woe_h); SYM(woe_l, g_woe_l);
    SYM(w1_h, g_w1_h); SYM(w1_l, g_w1_l); SYM(w2_h, g_w2_h); SYM(w2_l, g_w2_l);

    float* hout = (float*)d_out;
    float* eout = (float*)d_out + (size_t)NN * DIM;

    cudaFuncSetAttribute(mma_gemmB<1, 0, false, true >, cudaFuncAttributeMaxDynamicSharedMemorySize, SMB_TOTAL);
    cudaFuncSetAttribute(mma_gemmB<0, 1, true,  false>, cudaFuncAttributeMaxDynamicSharedMemorySize, SMB_TOTAL);
    cudaFuncSetAttribute(mma_gemmB<2, 0, false, true >, cudaFuncAttributeMaxDynamicSharedMemorySize, SMB_TOTAL);
    cudaFuncSetAttribute(qkv_gemm, cudaFuncAttributeMaxDynamicSharedMemorySize, SMB_TOTAL);
    cudaFuncSetAttribute(edge_gemm_fused, cudaFuncAttributeMaxDynamicSharedMemorySize, SMB_TOTAL);

    // ---- pre-convert fp32 -> bf16 hi/lo ----
    auto pc = [&](const float* in, bf16* h, bf16* l, long long n) {
        preconv<<<cdiv(n / 4, 256), 256>>>(in, h, l, n);
    };
    pc(x, xhi, xlo, (long long)NN * DIM);
    pc(edge_attr, eahi, ealo, (long long)NE * DIM);
    pc(Wq, wq_h, wq_l, DIM * DIM);
    pc(Wk, wk_h, wk_l, DIM * DIM);
    pc(Wv, wv_h, wv_l, DIM * DIM);
    pc(We, we_h, we_l, DIM * 2 * DIM);
    pc(WOh, woh_h, woh_l, DIM * DIM);
    pc(WOe, woe_h, woe_l, DIM * DIM);
    pc(W1, w1_h, w1_l, DIM * 2 * DIM);
    pc(W2, w2_h, w2_l, 2 * DIM * DIM);

    // init accumulators
    cudaMemsetAsync(wV, 0, (size_t)NN * DIM * sizeof(float));
    cudaMemsetAsync(rowV, 0, (size_t)NN * DIM * sizeof(float));
    cudaMemsetAsync(den, 0, (size_t)NN * NH * sizeof(float));
    cudaMemsetAsync(s1, 0, 2 * DIM * sizeof(float));
    cudaMemsetAsync(s2, 0, 2 * DIM * sizeof(float));
    cudaMemsetAsync(se, 0, 2 * DIM * sizeof(float));

    const int gN = cdiv(NN, 128), gE = cdiv(NE, 128);

    // Q/K/V in one launch (x-tile L2 reuse across the 3 sibling blocks)
    qkv_gemm<<<dim3(3, gN), 256, SMB_TOTAL>>>(xhi, xlo, wq_h, wq_l, wk_h, wk_l,
                                              wv_h, wv_l, bq, bk, bv, Qh, Kh, Vh);

    // fused Ee GEMM + score/logit/exp + rowV/den scatter (max-free softmax)
    edge_gemm_fused<<<dim3(2, gE), 256, SMB_TOTAL>>>(eahi, ealo, we_h, we_l, be,
                                                     ei, Aw, Qh, Kh, ethi, etlo,
                                                     lg, den, rowV);

    // V-only attention scatter
    edge_scatter<<<cdiv(NE * NH, 256), 256>>>(ei, lg, Vh, wV);

    node_fix<<<cdiv(NN * 64, 256), 256>>>(wV, rowV, den, VeRow, log_deg, deg_coef, hatth, hattl);

    // h path: WOh + residual(x) -> v1 with fused stats; BN1 -> hbn pair
    mma_gemmB<1, 0, false, true><<<dim3(1, gN), 256, SMB_TOTAL>>>(
        hatth, hattl, woh_h, woh_l, bOh, x, nullptr, nullptr, v1, nullptr, nullptr, s1, NN, 128, 128);
    bn_apply<true><<<cdiv((long long)NN * 64, 256), 256>>>(v1, nullptr, hbnh, hbnl, NN, s1, g1h, b1h, 1.f / NN);

    // e path: WOe + residual(edge_attr) -> eout with fused stats; BN apply
    mma_gemmB<1, 0, false, true><<<dim3(1, gE), 256, SMB_TOTAL>>>(
        ethi, etlo, woe_h, woe_l, bOe, edge_attr, nullptr, nullptr, eout, nullptr, nullptr, se, NE, 128, 128);
    bn_apply<false><<<cdiv((long long)NE * 64, 256), 256>>>(eout, eout, nullptr, nullptr, NE, se, g1e, b1e, 1.f / NE);

    // FFN: W1(relu) -> h2a pair; W2 + residual(hbn pair) -> v2 with stats; BN2 -> hout
    mma_gemmB<0, 1, true, false><<<dim3(2, gN), 256, SMB_TOTAL>>>(
        hbnh, hbnl, w1_h, w1_l, b1, nullptr, nullptr, nullptr, nullptr, h2ah, h2al, nullptr, NN, 256, 128);
    mma_gemmB<2, 0, false, true><<<dim3(1, gN), 256, SMB_TOTAL>>>(
        h2ah, h2al, w2_h, w2_l, b2, nullptr, hbnh, hbnl, v2, nullptr, nullptr, s2, NN, 128, 256);
    bn_apply<false><<<cdiv((long long)NN * 64, 256), 256>>>(v2, hout, nullptr, nullptr, NN, s2, g2h, b2h, 1.f / NN);
}

// round 12
// speedup vs baseline: 1.0279x; 1.0279x over previous
#include <cuda_runtime.h>
#include <cuda_bf16.h>
#include <math.h>
#include <stdint.h>

#define NN 40000
#define NE 640000
#define DIM 128
#define NH 8
#define DH 16

typedef __nv_bfloat16 bf16;

// ---------------- scratch (device globals: allocation-free) ----------------
__device__ float g_Qh[(size_t)NN * DIM];
__device__ float g_Kh[(size_t)NN * DIM];
__device__ float g_Vh[(size_t)NN * DIM];
__device__ float g_lg[(size_t)NE * NH];
__device__ float g_den[(size_t)NN * NH];
__device__ float g_wV[(size_t)NN * DIM];
__device__ float g_rowV[(size_t)NN * DIM];
__device__ float g_v1[(size_t)NN * DIM];
__device__ float g_v2[(size_t)NN * DIM];
__device__ float g_s1[2 * DIM];
__device__ float g_s2[2 * DIM];
__device__ float g_se[2 * DIM];
// bf16 hi/lo pairs
__device__ bf16 g_xhi[(size_t)NN * DIM],  g_xlo[(size_t)NN * DIM];
__device__ bf16 g_eahi[(size_t)NE * DIM], g_ealo[(size_t)NE * DIM];
__device__ bf16 g_ethi[(size_t)NE * DIM], g_etlo[(size_t)NE * DIM];
__device__ bf16 g_hatth[(size_t)NN * DIM], g_hattl[(size_t)NN * DIM];
__device__ bf16 g_hbnh[(size_t)NN * DIM],  g_hbnl[(size_t)NN * DIM];
__device__ bf16 g_h2ah[(size_t)NN * 2 * DIM], g_h2al[(size_t)NN * 2 * DIM];
__device__ bf16 g_wq_h[DIM * DIM], g_wq_l[DIM * DIM];
__device__ bf16 g_wk_h[DIM * DIM], g_wk_l[DIM * DIM];
__device__ bf16 g_wv_h[DIM * DIM], g_wv_l[DIM * DIM];
__device__ bf16 g_we_h[DIM * 2 * DIM], g_we_l[DIM * 2 * DIM];
__device__ bf16 g_woh_h[DIM * DIM], g_woh_l[DIM * DIM];
__device__ bf16 g_woe_h[DIM * DIM], g_woe_l[DIM * DIM];
__device__ bf16 g_w1_h[DIM * 2 * DIM], g_w1_l[DIM * 2 * DIM];
__device__ bf16 g_w2_h[2 * DIM * DIM], g_w2_l[2 * DIM * DIM];

static inline int cdiv(long long a, long long b) { return (int)((a + b - 1) / b); }

// ---------------- helpers ----------------
__device__ __forceinline__ uint32_t smem_u32(const void* p) {
    uint32_t a;
    asm("{ .reg .u64 t; cvta.to.shared.u64 t, %1; cvt.u32.u64 %0, t; }" : "=r"(a) : "l"(p));
    return a;
}
__device__ __forceinline__ void ldsm4(uint32_t (&r)[4], uint32_t addr) {
    asm volatile("ldmatrix.sync.aligned.m8n8.x4.shared.b16 {%0,%1,%2,%3}, [%4];"
                 : "=r"(r[0]), "=r"(r[1]), "=r"(r[2]), "=r"(r[3]) : "r"(addr));
}
__device__ __forceinline__ void ldsm4t(uint32_t (&r)[4], uint32_t addr) {
    asm volatile("ldmatrix.sync.aligned.m8n8.x4.trans.shared.b16 {%0,%1,%2,%3}, [%4];"
                 : "=r"(r[0]), "=r"(r[1]), "=r"(r[2]), "=r"(r[3]) : "r"(addr));
}
__device__ __forceinline__ void mma16816(float (&d)[4], const uint32_t (&a)[4], const uint32_t* b) {
    asm volatile("mma.sync.aligned.m16n8k16.row.col.f32.bf16.bf16.f32 "
                 "{%0,%1,%2,%3}, {%4,%5,%6,%7}, {%8,%9}, {%0,%1,%2,%3};"
                 : "+f"(d[0]), "+f"(d[1]), "+f"(d[2]), "+f"(d[3])
                 : "r"(a[0]), "r"(a[1]), "r"(a[2]), "r"(a[3]), "r"(b[0]), "r"(b[1]));
}
__device__ __forceinline__ uint32_t pack2(bf16 a, bf16 b) {
    return (uint32_t)__bfloat16_as_ushort(a) | ((uint32_t)__bfloat16_as_ushort(b) << 16);
}
__device__ __forceinline__ float2 up2(uint32_t u) {
    return make_float2(__bfloat162float(__ushort_as_bfloat16((unsigned short)(u & 0xffff))),
                       __bfloat162float(__ushort_as_bfloat16((unsigned short)(u >> 16))));
}
__device__ __forceinline__ void split4(float4 v, uint2& hi, uint2& lo) {
    bf16 hx = __float2bfloat16(v.x), hy = __float2bfloat16(v.y);
    bf16 hz = __float2bfloat16(v.z), hw = __float2bfloat16(v.w);
    hi = make_uint2(pack2(hx, hy), pack2(hz, hw));
    lo = make_uint2(pack2(__float2bfloat16(v.x - __bfloat162float(hx)),
                          __float2bfloat16(v.y - __bfloat162float(hy))),
                    pack2(__float2bfloat16(v.z - __bfloat162float(hz)),
                          __float2bfloat16(v.w - __bfloat162float(hw))));
}
__device__ __forceinline__ uint32_t packsplit(float a, float b, uint32_t& lo) {
    bf16 h0 = __float2bfloat16(a), h1 = __float2bfloat16(b);
    lo = pack2(__float2bfloat16(a - __bfloat162float(h0)),
               __float2bfloat16(b - __bfloat162float(h1)));
    return pack2(h0, h1);
}
__device__ __forceinline__ void cp16(uint32_t dst, const void* src, int sz) {
    asm volatile("cp.async.cg.shared.global [%0], [%1], 16, %2;" :: "r"(dst), "l"(src), "r"(sz));
}
#define CP_COMMIT() asm volatile("cp.async.commit_group;" ::: "memory")
#define CP_WAIT0()  asm volatile("cp.async.wait_group 0;" ::: "memory")
#define CP_WAIT1()  asm volatile("cp.async.wait_group 1;" ::: "memory")

__device__ __forceinline__ void red4(float* p, float a, float b, float c, float d) {
    asm volatile("red.global.add.v4.f32 [%0], {%1,%2,%3,%4};"
                 :: "l"(p), "f"(a), "f"(b), "f"(c), "f"(d) : "memory");
}
__device__ __forceinline__ void redf(float* p, float a) {
    asm volatile("red.global.add.f32 [%0], %1;" :: "l"(p), "f"(a) : "memory");
}

// ---------------- bf16-pair GEMM core: 128x128 tile, 256 thr, 2-stage pipe ----
#define STG    37888u
#define AHI_O  0u
#define ALO_O  10240u
#define BHI_O  20480u
#define BLO_O  29184u
#define SMB_TOTAL 75776

struct GemmCoreB {
    uint32_t sb;
    int tid, lid, wm, wn, m0, n0;
    float acc[4][4][4];

    __device__ __forceinline__ void init(uint8_t* smp, int bm, int bn) {
        sb = smem_u32(smp);
        tid = threadIdx.x; lid = tid & 31;
        int wid = tid >> 5;
        wm = wid >> 2; wn = wid & 3;
        m0 = bm * 128; n0 = bn * 128;
#pragma unroll
        for (int i = 0; i < 4; i++)
#pragma unroll
            for (int j = 0; j < 4; j++)
#pragma unroll
                for (int q = 0; q < 4; q++) acc[i][j][q] = 0.f;
    }
    __device__ __forceinline__ void stage(int buf, const bf16* Ahi, const bf16* Alo,
                                          const bf16* Whi, const bf16* Wlo,
                                          int M, int Ncols, int K, int kb) {
        uint32_t base = sb + (uint32_t)buf * STG;
#pragma unroll
        for (int i = 0; i < 2; i++) {
            int c = tid + i * 256;
            int row = c >> 2, gr = c & 3;
            bool ok = (m0 + row) < M;
            size_t go = (size_t)(ok ? m0 + row : 0) * K + kb + gr * 8;
            uint32_t d = base + (uint32_t)row * 80 + (uint32_t)gr * 16;
            cp16(d + AHI_O, Ahi + go, ok ? 16 : 0);
            cp16(d + ALO_O, Alo + go, ok ? 16 : 0);
        }
#pragma unroll
        for (int i = 0; i < 2; i++) {
            int c = tid + i * 256;
            int k = c >> 4, gr = c & 15;
            size_t go = (size_t)(kb + k) * Ncols + n0 + gr * 8;
            uint32_t d = base + (uint32_t)k * 272 + (uint32_t)gr * 16;
            cp16(d + BHI_O, Whi + go, 16);
            cp16(d + BLO_O, Wlo + go, 16);
        }
        CP_COMMIT();
    }
    __device__ __forceinline__ void compute(int buf) {
        uint32_t base = sb + (uint32_t)buf * STG;
#pragma unroll
        for (int ks = 0; ks < 32; ks += 16) {
            uint32_t bhi[4][2], blo[4][2];
            const uint32_t brow = (uint32_t)(ks + (lid & 15)) * 272 + (uint32_t)((lid >> 4) * 16);
#pragma unroll
            for (int p = 0; p < 2; p++) {
                uint32_t baddr = base + brow + (uint32_t)(wn * 32 + p * 16) * 2;
                uint32_t r[4];
                ldsm4t(r, baddr + BHI_O);
                bhi[2 * p][0] = r[0]; bhi[2 * p][1] = r[1];
                bhi[2 * p + 1][0] = r[2]; bhi[2 * p + 1][1] = r[3];
                ldsm4t(r, baddr + BLO_O);
                blo[2 * p][0] = r[0]; blo[2 * p][1] = r[1];
                blo[2 * p + 1][0] = r[2]; blo[2 * p + 1][1] = r[3];
            }
            const uint32_t arow = (uint32_t)(wm * 64 + (lid & 15)) * 80
                                + (uint32_t)ks * 2 + (uint32_t)(lid >> 4) * 16;
#pragma unroll
            for (int mt = 0; mt < 4; mt++) {
                uint32_t aaddr = base + arow + (uint32_t)mt * (16 * 80);
                uint32_t ahi4[4], alo4[4];
                ldsm4(ahi4, aaddr + AHI_O);
                ldsm4(alo4, aaddr + ALO_O);
#pragma unroll
                for (int nt = 0; nt < 4; nt++) {
                    mma16816(acc[mt][nt], ahi4, bhi[nt]);
                    mma16816(acc[mt][nt], ahi4, blo[nt]);
                    mma16816(acc[mt][nt], alo4, bhi[nt]);
                }
            }
        }
    }
    __device__ __forceinline__ void run(const bf16* Ahi, const bf16* Alo,
                                        const bf16* Whi, const bf16* Wlo,
                                        int M, int Ncols, int K) {
        const int nch = K >> 5;
        stage(0, Ahi, Alo, Whi, Wlo, M, Ncols, K, 0);
        if (nch > 1) stage(1, Ahi, Alo, Whi, Wlo, M, Ncols, K, 32);
        for (int i = 0; i < nch; i++) {
            if (i == nch - 1) { CP_WAIT0(); } else { CP_WAIT1(); }
            __syncthreads();
            compute(i & 1);
            if (i + 2 < nch) {
                __syncthreads();
                stage(i & 1, Ahi, Alo, Whi, Wlo, M, Ncols, K, (i + 2) * 32);
            }
        }
    }
};

// ---------------- generic GEMM (m-tile = blockIdx.y, n-tile = blockIdx.x) ----
template <int RESMODE, int OUTMODE, bool RELU, bool STATS>
__global__ void __launch_bounds__(256, 2)
mma_gemmB(const bf16* __restrict__ Ahi, const bf16* __restrict__ Alo,
          const bf16* __restrict__ Whi, const bf16* __restrict__ Wlo,
          const float* __restrict__ bias, const float* __restrict__ resf,
          const bf16* __restrict__ reshi, const bf16* __restrict__ reslo,
          float* __restrict__ Cf, bf16* __restrict__ Chi, bf16* __restrict__ Clo,
          float* __restrict__ stats, int M, int Ncols, int K)
{
    extern __shared__ __align__(16) uint8_t sm[];
    GemmCoreB g;
    g.init(sm, blockIdx.y, blockIdx.x);
    g.run(Ahi, Alo, Whi, Wlo, M, Ncols, K);

    float ts0[4], ts1[4], tq0[4], tq1[4];
    if (STATS) {
#pragma unroll
        for (int nt = 0; nt < 4; nt++) { ts0[nt] = ts1[nt] = tq0[nt] = tq1[nt] = 0.f; }
    }

    const int qr = g.lid >> 2, qc = (g.lid & 3) * 2;
#pragma unroll
    for (int mt = 0; mt < 4; mt++) {
#pragma unroll
        for (int nt = 0; nt < 4; nt++) {
            int col = g.n0 + g.wn * 32 + nt * 8 + qc;
            float b0 = bias[col], b1 = bias[col + 1];
#pragma unroll
            for (int half = 0; half < 2; half++) {
                int row = g.m0 + g.wm * 64 + mt * 16 + qr + half * 8;
                if (row >= M) continue;
                float o0 = g.acc[mt][nt][half * 2 + 0] + b0;
                float o1 = g.acc[mt][nt][half * 2 + 1] + b1;
                size_t off = (size_t)row * Ncols + col;
                if (RESMODE == 1) {
                    float2 rr = *(const float2*)(resf + off);
                    o0 += rr.x; o1 += rr.y;
                } else if (RESMODE == 2) {
                    float2 rh = up2(*(const uint32_t*)(reshi + off));
                    float2 rl = up2(*(const uint32_t*)(reslo + off));
                    o0 += rh.x + rl.x; o1 += rh.y + rl.y;
                }
                if (RELU) { o0 = fmaxf(o0, 0.f); o1 = fmaxf(o1, 0.f); }
                if (STATS) {
                    ts0[nt] += o0; ts1[nt] += o1;
                    tq0[nt] = fmaf(o0, o0, tq0[nt]); tq1[nt] = fmaf(o1, o1, tq1[nt]);
                }
                if (OUTMODE == 0) {
                    *(float2*)(Cf + off) = make_float2(o0, o1);
                } else {
                    uint32_t lw, hw = packsplit(o0, o1, lw);
                    *(uint32_t*)(Chi + off) = hw;
                    *(uint32_t*)(Clo + off) = lw;
                }
            }
        }
    }
    if (STATS) {
#pragma unroll
        for (int nt = 0; nt < 4; nt++) {
            float a = ts0[nt], b = ts1[nt], c = tq0[nt], d = tq1[nt];
#pragma unroll
            for (int m = 4; m <= 16; m <<= 1) {
                a += __shfl_xor_sync(0xffffffff, a, m);
                b += __shfl_xor_sync(0xffffffff, b, m);
                c += __shfl_xor_sync(0xffffffff, c, m);
                d += __shfl_xor_sync(0xffffffff, d, m);
            }
            if (qr == 0) {
                int col = g.n0 + g.wn * 32 + nt * 8 + qc;
                redf(stats + col, a);
                redf(stats + col + 1, b);
                redf(stats + DIM + col, c);
                redf(stats + DIM + col + 1, d);
            }
        }
    }
}

// ---------------- fused QKV (blockIdx.x selects weight, y = m tile) ----------
__global__ void __launch_bounds__(256, 2)
qkv_gemm(const bf16* __restrict__ xhi, const bf16* __restrict__ xlo,
         const bf16* __restrict__ qh, const bf16* __restrict__ ql,
         const bf16* __restrict__ kh, const bf16* __restrict__ kl,
         const bf16* __restrict__ vh, const bf16* __restrict__ vl,
         const float* __restrict__ bq, const float* __restrict__ bk,
         const float* __restrict__ bv,
         float* __restrict__ Qo, float* __restrict__ Ko, float* __restrict__ Vo)
{
    extern __shared__ __align__(16) uint8_t sm[];
    const bf16* Whi = qh; const bf16* Wlo = ql;
    const float* bias = bq; float* C = Qo;
    if (blockIdx.x == 1) { Whi = kh; Wlo = kl; bias = bk; C = Ko; }
    else if (blockIdx.x == 2) { Whi = vh; Wlo = vl; bias = bv; C = Vo; }

    GemmCoreB g;
    g.init(sm, blockIdx.y, 0);
    g.run(xhi, xlo, Whi, Wlo, NN, 128, 128);

    const int qr = g.lid >> 2, qc = (g.lid & 3) * 2;
#pragma unroll
    for (int mt = 0; mt < 4; mt++) {
#pragma unroll
        for (int nt = 0; nt < 4; nt++) {
            int col = g.wn * 32 + nt * 8 + qc;
            float b0 = bias[col], b1 = bias[col + 1];
#pragma unroll
            for (int half = 0; half < 2; half++) {
                int row = g.m0 + g.wm * 64 + mt * 16 + qr + half * 8;
                if (row >= NN) continue;
                *(float2*)(C + (size_t)row * 128 + col) =
                    make_float2(g.acc[mt][nt][half * 2 + 0] + b0,
                                g.acc[mt][nt][half * 2 + 1] + b1);
            }
        }
    }
}

// ---------------- fused Ee GEMM + edge score/logit/exp ----------------
union U16 { float4 q[4]; float f[16]; };

__global__ void __launch_bounds__(256, 2)
edge_gemm_fused(const bf16* __restrict__ eahi, const bf16* __restrict__ ealo,
                const bf16* __restrict__ weh, const bf16* __restrict__ wel,
                const float* __restrict__ bias,
                const int* __restrict__ ei, const float* __restrict__ Aw,
                const float* __restrict__ Qh, const float* __restrict__ Kh,
                bf16* __restrict__ ethi, bf16* __restrict__ etlo,
                float* __restrict__ lg)
{
    extern __shared__ __align__(16) uint8_t sm[];
    __shared__ float sAw[DIM];
    if (threadIdx.x < DIM) sAw[threadIdx.x] = Aw[threadIdx.x];

    GemmCoreB g;
    g.init(sm, blockIdx.y, blockIdx.x);
    g.run(eahi, ealo, weh, wel, NE, 256, 128);

    __syncthreads();
    float* sC = (float*)sm;
    const int qr = g.lid >> 2, qc = (g.lid & 3) * 2;
#pragma unroll
    for (int mt = 0; mt < 4; mt++) {
#pragma unroll
        for (int nt = 0; nt < 4; nt++) {
            int col = g.wn * 32 + nt * 8 + qc;
            float b0 = bias[g.n0 + col], b1 = bias[g.n0 + col + 1];
#pragma unroll
            for (int half = 0; half < 2; half++) {
                int row = g.wm * 64 + mt * 16 + qr + half * 8;
                *(float2*)(sC + row * 132 + col) =
                    make_float2(g.acc[mt][nt][half * 2 + 0] + b0,
                                g.acc[mt][nt][half * 2 + 1] + b1);
            }
        }
    }
    __syncthreads();

    const int e = threadIdx.x & 127;
    const int ge = g.m0 + e;
    const int src = ei[ge], dst = ei[NE + ge];
#pragma unroll
    for (int u = 0; u < 2; u++) {
        const int hl = (threadIdx.x >> 7) * 2 + u;
        const int h = blockIdx.x * 4 + hl;
        const float* ew = sC + e * 132 + hl * 32;
        U16 K4, Q4, EW, EB, ET;
        const float4* kp = (const float4*)(Kh + (size_t)src * DIM + h * DH);
        const float4* qp = (const float4*)(Qh + (size_t)dst * DIM + h * DH);
#pragma unroll
        for (int q = 0; q < 4; q++) {
            K4.q[q] = kp[q]; Q4.q[q] = qp[q];
            EW.q[q] = *(const float4*)(ew + q * 4);
            EB.q[q] = *(const float4*)(ew + 16 + q * 4);
        }
        float logit = 0.f;
#pragma unroll
        for (int d = 0; d < 16; d++) {
            float s = (K4.f[d] + Q4.f[d]) * EW.f[d];
            float a = fabsf(s);
            float r = (a > 0.f) ? copysignf(sqrtf(a), s) : 0.f;
            float v = fmaxf(r + EB.f[d], 0.f);
            ET.f[d] = v;
            logit = fmaf(v, sAw[d * NH + h], logit);
        }
        logit = fminf(fmaxf(logit, -5.f), 5.f);
        uint32_t hw[8], lw[8];
#pragma unroll
        for (int q = 0; q < 8; q++) hw[q] = packsplit(ET.f[2 * q], ET.f[2 * q + 1], lw[q]);
        bf16* ph = ethi + (size_t)ge * DIM + h * DH;
        bf16* pl = etlo + (size_t)ge * DIM + h * DH;
        *(uint4*)ph       = make_uint4(hw[0], hw[1], hw[2], hw[3]);
        *((uint4*)ph + 1) = make_uint4(hw[4], hw[5], hw[6], hw[7]);
        *(uint4*)pl       = make_uint4(lw[0], lw[1], lw[2], lw[3]);
        *((uint4*)pl + 1) = make_uint4(lw[4], lw[5], lw[6], lw[7]);
        lg[ge * NH + h] = expf(logit);
    }
}

// ---------------- misc / edge / node / bn kernels ----------------
__global__ void preconv(const float* __restrict__ in, bf16* __restrict__ hi,
                        bf16* __restrict__ lo, long long n)
{
    long long i = ((long long)blockIdx.x * blockDim.x + threadIdx.x) * 4;
    if (i >= n) return;
    float4 v = *(const float4*)(in + i);
    uint2 h, l;
    split4(v, h, l);
    *(uint2*)(hi + i) = h;
    *(uint2*)(lo + i) = l;
}

__global__ void edge_scatter(const int* __restrict__ ei, const float* __restrict__ lg,
                             float* __restrict__ den, const float* __restrict__ Vh,
                             const bf16* __restrict__ ethi, const bf16* __restrict__ etlo,
                             float* __restrict__ wV, float* __restrict__ rowV)
{
    int t = blockIdx.x * blockDim.x + threadIdx.x;
    if (t >= NE * NH) return;
    int e = t >> 3, h = t & 7;
    int src = ei[e], dst = ei[NE + e];
    float ex = lg[t];
    redf(&den[dst * NH + h], ex);
    U16 V4, E4;
    const float4* vp = (const float4*)(Vh + (size_t)src * DIM + h * DH);
#pragma unroll
    for (int q = 0; q < 4; q++) V4.q[q] = vp[q];
    const uint4* ph = (const uint4*)(ethi + (size_t)e * DIM + h * DH);
    const uint4* pl = (const uint4*)(etlo + (size_t)e * DIM + h * DH);
#pragma unroll
    for (int half = 0; half < 2; half++) {
        uint4 H = ph[half], L = pl[half];
        uint32_t hw[4] = {H.x, H.y, H.z, H.w}, lw[4] = {L.x, L.y, L.z, L.w};
#pragma unroll
        for (int q = 0; q < 4; q++) {
            float2 fh = up2(hw[q]), fl = up2(lw[q]);
            E4.f[half * 8 + q * 2 + 0] = fh.x + fl.x;
            E4.f[half * 8 + q * 2 + 1] = fh.y + fl.y;
        }
    }
    float* wv = wV + (size_t)dst * DIM + h * DH;
    float* rv = rowV + (size_t)dst * DIM + h * DH;
#pragma unroll
    for (int q = 0; q < 4; q++) {
        red4(wv + q * 4, V4.q[q].x * ex, V4.q[q].y * ex, V4.q[q].z * ex, V4.q[q].w * ex);
        red4(rv + q * 4, E4.f[q * 4] * ex, E4.f[q * 4 + 1] * ex,
             E4.f[q * 4 + 2] * ex, E4.f[q * 4 + 3] * ex);
    }
}

__global__ void node_fix(const float* __restrict__ wV, const float* __restrict__ rowV,
                         const float* __restrict__ den,
                         const float* __restrict__ VeRow, const float* __restrict__ log_deg,
                         const float* __restrict__ deg_coef,
                         bf16* __restrict__ hatth, bf16* __restrict__ hattl)
{
    int t = blockIdx.x * blockDim.x + threadIdx.x;
    if (t >= NN * 64) return;
    int n = t >> 6, c0 = (t & 63) * 2, h = c0 >> 4, co = c0 & 15;
    size_t off = (size_t)n * DIM + c0;
    float inv = 1.f / (den[n * NH + h] + 1e-16f);
    float a0 = wV[off], a1 = wV[off + 1];
    const float* rv = rowV + (size_t)n * DIM + h * DH;
#pragma unroll
    for (int d2 = 0; d2 < 16; d2++) {
        float r = rv[d2];
        a0 = fmaf(r, VeRow[d2 * DIM + h * DH + co], a0);
        a1 = fmaf(r, VeRow[d2 * DIM + h * DH + co + 1], a1);
    }
    a0 *= inv; a1 *= inv;
    float ld = log_deg[n];
    float o0 = a0 * (deg_coef[2 * c0] + ld * deg_coef[2 * c0 + 1]);
    float o1 = a1 * (deg_coef[2 * c0 + 2] + ld * deg_coef[2 * c0 + 3]);
    uint32_t lw, hw = packsplit(o0, o1, lw);
    *(uint32_t*)(hatth + off) = hw;
    *(uint32_t*)(hattl + off) = lw;
}

template <bool PAIR>
__global__ void bn_apply(const float* __restrict__ v, float* __restrict__ outf,
                         bf16* __restrict__ outhi, bf16* __restrict__ outlo, int M,
                         const float* __restrict__ sums,
                         const float* __restrict__ g, const float* __restrict__ b, float invM)
{
    long long i = ((long long)blockIdx.x * blockDim.x + threadIdx.x) * 2;
    if (i >= (long long)M * DIM) return;
    int c = (int)(i & (DIM - 1));
    float m0 = sums[c] * invM, m1 = sums[c + 1] * invM;
    float var0 = fmaf(-m0, m0, sums[DIM + c] * invM);
    float var1 = fmaf(-m1, m1, sums[DIM + c + 1] * invM);
    float2 vv = *(const float2*)(v + i);
    float o0 = (vv.x - m0) * rsqrtf(var0 + 1e-5f) * g[c] + b[c];
    float o1 = (vv.y - m1) * rsqrtf(var1 + 1e-5f) * g[c + 1] + b[c + 1];
    if (!PAIR) {
        *(float2*)(outf + i) = make_float2(o0, o1);
    } else {
        uint32_t lw, hw = packsplit(o0, o1, lw);
        *(uint32_t*)(outhi + i) = hw;
        *(uint32_t*)(outlo + i) = lw;
    }
}

// ---------------- launch ----------------
#define SYM(var, sym) cudaGetSymbolAddress((void**)&var, sym)

extern "C" void kernel_launch(void* const* d_in, const int* in_sizes, int n_in,
                              void* d_out, int out_size)
{
    const float* x         = (const float*)d_in[0];
    const float* edge_attr = (const float*)d_in[1];
    const int*   ei        = (const int*)d_in[2];
    const float* log_deg   = (const float*)d_in[3];
    const float* Wq = (const float*)d_in[4],  *bq  = (const float*)d_in[5];
    const float* Wk = (const float*)d_in[6],  *bk  = (const float*)d_in[7];
    const float* We = (const float*)d_in[8],  *be  = (const float*)d_in[9];
    const float* Wv = (const float*)d_in[10], *bv  = (const float*)d_in[11];
    const float* Aw = (const float*)d_in[12], *VeRow = (const float*)d_in[13];
    const float* WOh = (const float*)d_in[14], *bOh = (const float*)d_in[15];
    const float* WOe = (const float*)d_in[16], *bOe = (const float*)d_in[17];
    const float* deg_coef = (const float*)d_in[18];
    const float* g1h = (const float*)d_in[19], *b1h = (const float*)d_in[20];
    const float* g1e = (const float*)d_in[21], *b1e = (const float*)d_in[22];
    const float* g2h = (const float*)d_in[23], *b2h = (const float*)d_in[24];
    const float* W1 = (const float*)d_in[25], *b1 = (const float*)d_in[26];
    const float* W2 = (const float*)d_in[27], *b2 = (const float*)d_in[28];

    float *Qh, *Kh, *Vh, *lg, *den, *wV, *rowV, *v1, *v2, *s1, *s2buf, *se;
    SYM(Qh, g_Qh); SYM(Kh, g_Kh); SYM(Vh, g_Vh);
    SYM(lg, g_lg); SYM(den, g_den);
    SYM(wV, g_wV); SYM(rowV, g_rowV);
    SYM(v1, g_v1); SYM(v2, g_v2);
    SYM(s1, g_s1); SYM(s2buf, g_s2); SYM(se, g_se);
    bf16 *xhi, *xlo, *eahi, *ealo, *ethi, *etlo, *hatth, *hattl, *hbnh, *hbnl, *h2ah, *h2al;
    SYM(xhi, g_xhi); SYM(xlo, g_xlo); SYM(eahi, g_eahi); SYM(ealo, g_ealo);
    SYM(ethi, g_ethi); SYM(etlo, g_etlo);
    SYM(hatth, g_hatth); SYM(hattl, g_hattl);
    SYM(hbnh, g_hbnh); SYM(hbnl, g_hbnl);
    SYM(h2ah, g_h2ah); SYM(h2al, g_h2al);
    bf16 *wq_h, *wq_l, *wk_h, *wk_l, *wv_h, *wv_l, *we_h, *we_l;
    bf16 *woh_h, *woh_l, *woe_h, *woe_l, *w1_h, *w1_l, *w2_h, *w2_l;
    SYM(wq_h, g_wq_h); SYM(wq_l, g_wq_l); SYM(wk_h, g_wk_h); SYM(wk_l, g_wk_l);
    SYM(wv_h, g_wv_h); SYM(wv_l, g_wv_l); SYM(we_h, g_we_h); SYM(we_l, g_we_l);
    SYM(woh_h, g_woh_h); SYM(woh_l, g_woh_l); SYM(woe_h, g_woe_h); SYM(woe_l, g_woe_l);
    SYM(w1_h, g_w1_h); SYM(w1_l, g_w1_l); SYM(w2_h, g_w2_h); SYM(w2_l, g_w2_l);

    float* hout = (float*)d_out;
    float* eout = (float*)d_out + (size_t)NN * DIM;

    cudaFuncSetAttribute(mma_gemmB<1, 0, false, true >, cudaFuncAttributeMaxDynamicSharedMemorySize, SMB_TOTAL);
    cudaFuncSetAttribute(mma_gemmB<0, 1, true,  false>, cudaFuncAttributeMaxDynamicSharedMemorySize, SMB_TOTAL);
    cudaFuncSetAttribute(mma_gemmB<2, 0, false, true >, cudaFuncAttributeMaxDynamicSharedMemorySize, SMB_TOTAL);
    cudaFuncSetAttribute(qkv_gemm, cudaFuncAttributeMaxDynamicSharedMemorySize, SMB_TOTAL);
    cudaFuncSetAttribute(edge_gemm_fused, cudaFuncAttributeMaxDynamicSharedMemorySize, SMB_TOTAL);

    // lazily-created side stream + events (host objects; GPU work identical each call)
    static cudaStream_t sside = nullptr;
    static cudaEvent_t ev0 = nullptr, evA = nullptr, ev1 = nullptr, ev2 = nullptr;
    if (!sside) {
        cudaStreamCreateWithFlags(&sside, cudaStreamNonBlocking);
        cudaEventCreateWithFlags(&ev0, cudaEventDisableTiming);
        cudaEventCreateWithFlags(&evA, cudaEventDisableTiming);
        cudaEventCreateWithFlags(&ev1, cudaEventDisableTiming);
        cudaEventCreateWithFlags(&ev2, cudaEventDisableTiming);
    }

    auto pc = [&](const float* in, bf16* h, bf16* l, long long n, cudaStream_t st) {
        preconv<<<cdiv(n / 4, 256), 256, 0, st>>>(in, h, l, n);
    };

    // fork side stream; run the big edge_attr preconv there
    cudaEventRecord(ev0, 0);
    cudaStreamWaitEvent(sside, ev0, 0);
    pc(edge_attr, eahi, ealo, (long long)NE * DIM, sside);
    cudaEventRecord(evA, sside);

    // main: small preconvs + memsets + QKV
    pc(x, xhi, xlo, (long long)NN * DIM, 0);
    pc(Wq, wq_h, wq_l, DIM * DIM, 0);
    pc(Wk, wk_h, wk_l, DIM * DIM, 0);
    pc(Wv, wv_h, wv_l, DIM * DIM, 0);
    pc(We, we_h, we_l, DIM * 2 * DIM, 0);
    pc(WOh, woh_h, woh_l, DIM * DIM, 0);
    pc(WOe, woe_h, woe_l, DIM * DIM, 0);
    pc(W1, w1_h, w1_l, DIM * 2 * DIM, 0);
    pc(W2, w2_h, w2_l, 2 * DIM * DIM, 0);

    cudaMemsetAsync(wV, 0, (size_t)NN * DIM * sizeof(float));
    cudaMemsetAsync(rowV, 0, (size_t)NN * DIM * sizeof(float));
    cudaMemsetAsync(den, 0, (size_t)NN * NH * sizeof(float));
    cudaMemsetAsync(s1, 0, 2 * DIM * sizeof(float));
    cudaMemsetAsync(s2buf, 0, 2 * DIM * sizeof(float));
    cudaMemsetAsync(se, 0, 2 * DIM * sizeof(float));

    const int gN = cdiv(NN, 128), gE = cdiv(NE, 128);

    qkv_gemm<<<dim3(3, gN), 256, SMB_TOTAL>>>(xhi, xlo, wq_h, wq_l, wk_h, wk_l,
                                              wv_h, wv_l, bq, bk, bv, Qh, Kh, Vh);

    cudaStreamWaitEvent(0, evA, 0);
    edge_gemm_fused<<<dim3(2, gE), 256, SMB_TOTAL>>>(eahi, ealo, we_h, we_l, be,
                                                     ei, Aw, Qh, Kh, ethi, etlo, lg);
    cudaEventRecord(ev1, 0);

    // side stream: e-path (WOe + stats, BN apply into eout)
    cudaStreamWaitEvent(sside, ev1, 0);
    mma_gemmB<1, 0, false, true><<<dim3(1, gE), 256, SMB_TOTAL, sside>>>(
        ethi, etlo, woe_h, woe_l, bOe, edge_attr, nullptr, nullptr, eout, nullptr, nullptr, se, NE, 128, 128);
    bn_apply<false><<<cdiv((long long)NE * 64, 256), 256, 0, sside>>>(
        eout, eout, nullptr, nullptr, NE, se, g1e, b1e, 1.f / NE);
    cudaEventRecord(ev2, sside);

    // main stream: h-path
    edge_scatter<<<cdiv(NE * NH, 256), 256>>>(ei, lg, den, Vh, ethi, etlo, wV, rowV);
    node_fix<<<cdiv(NN * 64, 256), 256>>>(wV, rowV, den, VeRow, log_deg, deg_coef, hatth, hattl);
    mma_gemmB<1, 0, false, true><<<dim3(1, gN), 256, SMB_TOTAL>>>(
        hatth, hattl, woh_h, woh_l, bOh, x, nullptr, nullptr, v1, nullptr, nullptr, s1, NN, 128, 128);
    bn_apply<true><<<cdiv((long long)NN * 64, 256), 256>>>(v1, nullptr, hbnh, hbnl, NN, s1, g1h, b1h, 1.f / NN);
    mma_gemmB<0, 1, true, false><<<dim3(2, gN), 256, SMB_TOTAL>>>(
        hbnh, hbnl, w1_h, w1_l, b1, nullptr, nullptr, nullptr, nullptr, h2ah, h2al, nullptr, NN, 256, 128);
    mma_gemmB<2, 0, false, true><<<dim3(1, gN), 256, SMB_TOTAL>>>(
        h2ah, h2al, w2_h, w2_l, b2, nullptr, hbnh, hbnl, v2, nullptr, nullptr, s2buf, NN, 128, 256);
    bn_apply<false><<<cdiv((long long)NN * 64, 256), 256>>>(v2, hout, nullptr, nullptr, NN, s2buf, g2h, b2h, 1.f / NN);

    // join side stream back into the captured main stream
    cudaStreamWaitEvent(0, ev2, 0);
}

// round 13
// speedup vs baseline: 1.1735x; 1.1417x over previous
#include <cuda_runtime.h>
#include <cuda_bf16.h>
#include <cuda_fp16.h>
#include <math.h>
#include <stdint.h>

#define NN 40000
#define NE 640000
#define DIM 128
#define NH 8
#define DH 16

typedef __nv_bfloat16 bf16;

// ---------------- scratch (device globals: allocation-free) ----------------
__device__ float g_Qh[(size_t)NN * DIM];
__device__ float g_Kh[(size_t)NN * DIM];
__device__ float g_Vh[(size_t)NN * DIM];
__device__ float g_lg[(size_t)NE * NH];
__device__ float g_den[(size_t)NN * NH];
__device__ float g_wV[(size_t)NN * DIM];
__device__ float g_rowV[(size_t)NN * DIM];
__device__ float g_v1[(size_t)NN * DIM];
__device__ float g_v2[(size_t)NN * DIM];
__device__ float g_s1[2 * DIM];
__device__ float g_s2[2 * DIM];
__device__ float g_se[2 * DIM];
// fp16 (edge path)
__device__ __half g_ea16[(size_t)NE * DIM];
__device__ __half g_et16[(size_t)NE * DIM];
__device__ __half g_we16h[DIM * 2 * DIM], g_we16l[DIM * 2 * DIM];
__device__ __half g_woe16h[DIM * DIM], g_woe16l[DIM * DIM];
// bf16 hi/lo pairs (node path)
__device__ bf16 g_xhi[(size_t)NN * DIM],  g_xlo[(size_t)NN * DIM];
__device__ bf16 g_hatth[(size_t)NN * DIM], g_hattl[(size_t)NN * DIM];
__device__ bf16 g_hbnh[(size_t)NN * DIM],  g_hbnl[(size_t)NN * DIM];
__device__ bf16 g_h2ah[(size_t)NN * 2 * DIM], g_h2al[(size_t)NN * 2 * DIM];
__device__ bf16 g_wq_h[DIM * DIM], g_wq_l[DIM * DIM];
__device__ bf16 g_wk_h[DIM * DIM], g_wk_l[DIM * DIM];
__device__ bf16 g_wv_h[DIM * DIM], g_wv_l[DIM * DIM];
__device__ bf16 g_woh_h[DIM * DIM], g_woh_l[DIM * DIM];
__device__ bf16 g_w1_h[DIM * 2 * DIM], g_w1_l[DIM * 2 * DIM];
__device__ bf16 g_w2_h[2 * DIM * DIM], g_w2_l[2 * DIM * DIM];

static inline int cdiv(long long a, long long b) { return (int)((a + b - 1) / b); }

// ---------------- helpers ----------------
__device__ __forceinline__ uint32_t smem_u32(const void* p) {
    uint32_t a;
    asm("{ .reg .u64 t; cvta.to.shared.u64 t, %1; cvt.u32.u64 %0, t; }" : "=r"(a) : "l"(p));
    return a;
}
__device__ __forceinline__ void ldsm4(uint32_t (&r)[4], uint32_t addr) {
    asm volatile("ldmatrix.sync.aligned.m8n8.x4.shared.b16 {%0,%1,%2,%3}, [%4];"
                 : "=r"(r[0]), "=r"(r[1]), "=r"(r[2]), "=r"(r[3]) : "r"(addr));
}
__device__ __forceinline__ void ldsm4t(uint32_t (&r)[4], uint32_t addr) {
    asm volatile("ldmatrix.sync.aligned.m8n8.x4.trans.shared.b16 {%0,%1,%2,%3}, [%4];"
                 : "=r"(r[0]), "=r"(r[1]), "=r"(r[2]), "=r"(r[3]) : "r"(addr));
}
__device__ __forceinline__ void mma16816(float (&d)[4], const uint32_t (&a)[4], const uint32_t* b) {
    asm volatile("mma.sync.aligned.m16n8k16.row.col.f32.bf16.bf16.f32 "
                 "{%0,%1,%2,%3}, {%4,%5,%6,%7}, {%8,%9}, {%0,%1,%2,%3};"
                 : "+f"(d[0]), "+f"(d[1]), "+f"(d[2]), "+f"(d[3])
                 : "r"(a[0]), "r"(a[1]), "r"(a[2]), "r"(a[3]), "r"(b[0]), "r"(b[1]));
}
__device__ __forceinline__ void mma16816h(float (&d)[4], const uint32_t (&a)[4], const uint32_t* b) {
    asm volatile("mma.sync.aligned.m16n8k16.row.col.f32.f16.f16.f32 "
                 "{%0,%1,%2,%3}, {%4,%5,%6,%7}, {%8,%9}, {%0,%1,%2,%3};"
                 : "+f"(d[0]), "+f"(d[1]), "+f"(d[2]), "+f"(d[3])
                 : "r"(a[0]), "r"(a[1]), "r"(a[2]), "r"(a[3]), "r"(b[0]), "r"(b[1]));
}
__device__ __forceinline__ uint32_t pack2(bf16 a, bf16 b) {
    return (uint32_t)__bfloat16_as_ushort(a) | ((uint32_t)__bfloat16_as_ushort(b) << 16);
}
__device__ __forceinline__ uint32_t pack2h(__half a, __half b) {
    return (uint32_t)__half_as_ushort(a) | ((uint32_t)__half_as_ushort(b) << 16);
}
__device__ __forceinline__ float2 up2(uint32_t u) {
    return make_float2(__bfloat162float(__ushort_as_bfloat16((unsigned short)(u & 0xffff))),
                       __bfloat162float(__ushort_as_bfloat16((unsigned short)(u >> 16))));
}
__device__ __forceinline__ float2 up2h(uint32_t u) {
    __half2 h = *(__half2*)&u;
    return __half22float2(h);
}
__device__ __forceinline__ void split4(float4 v, uint2& hi, uint2& lo) {
    bf16 hx = __float2bfloat16(v.x), hy = __float2bfloat16(v.y);
    bf16 hz = __float2bfloat16(v.z), hw = __float2bfloat16(v.w);
    hi = make_uint2(pack2(hx, hy), pack2(hz, hw));
    lo = make_uint2(pack2(__float2bfloat16(v.x - __bfloat162float(hx)),
                          __float2bfloat16(v.y - __bfloat162float(hy))),
                    pack2(__float2bfloat16(v.z - __bfloat162float(hz)),
                          __float2bfloat16(v.w - __bfloat162float(hw))));
}
__device__ __forceinline__ uint32_t packsplit(float a, float b, uint32_t& lo) {
    bf16 h0 = __float2bfloat16(a), h1 = __float2bfloat16(b);
    lo = pack2(__float2bfloat16(a - __bfloat162float(h0)),
               __float2bfloat16(b - __bfloat162float(h1)));
    return pack2(h0, h1);
}
__device__ __forceinline__ void cp16(uint32_t dst, const void* src, int sz) {
    asm volatile("cp.async.cg.shared.global [%0], [%1], 16, %2;" :: "r"(dst), "l"(src), "r"(sz));
}
#define CP_COMMIT() asm volatile("cp.async.commit_group;" ::: "memory")
#define CP_WAIT0()  asm volatile("cp.async.wait_group 0;" ::: "memory")
#define CP_WAIT1()  asm volatile("cp.async.wait_group 1;" ::: "memory")

__device__ __forceinline__ void red4(float* p, float a, float b, float c, float d) {
    asm volatile("red.global.add.v4.f32 [%0], {%1,%2,%3,%4};"
                 :: "l"(p), "f"(a), "f"(b), "f"(c), "f"(d) : "memory");
}
__device__ __forceinline__ void redf(float* p, float a) {
    asm volatile("red.global.add.f32 [%0], %1;" :: "l"(p), "f"(a) : "memory");
}

// ---------------- bf16-pair GEMM core (node path): 128x128, 2-stage --------
#define STG    37888u
#define AHI_O  0u
#define ALO_O  10240u
#define BHI_O  20480u
#define BLO_O  29184u
#define SMB_TOTAL 75776

struct GemmCoreB {
    uint32_t sb;
    int tid, lid, wm, wn, m0, n0;
    float acc[4][4][4];

    __device__ __forceinline__ void init(uint8_t* smp, int bm, int bn) {
        sb = smem_u32(smp);
        tid = threadIdx.x; lid = tid & 31;
        int wid = tid >> 5;
        wm = wid >> 2; wn = wid & 3;
        m0 = bm * 128; n0 = bn * 128;
#pragma unroll
        for (int i = 0; i < 4; i++)
#pragma unroll
            for (int j = 0; j < 4; j++)
#pragma unroll
                for (int q = 0; q < 4; q++) acc[i][j][q] = 0.f;
    }
    __device__ __forceinline__ void stage(int buf, const bf16* Ahi, const bf16* Alo,
                                          const bf16* Whi, const bf16* Wlo,
                                          int M, int Ncols, int K, int kb) {
        uint32_t base = sb + (uint32_t)buf * STG;
#pragma unroll
        for (int i = 0; i < 2; i++) {
            int c = tid + i * 256;
            int row = c >> 2, gr = c & 3;
            bool ok = (m0 + row) < M;
            size_t go = (size_t)(ok ? m0 + row : 0) * K + kb + gr * 8;
            uint32_t d = base + (uint32_t)row * 80 + (uint32_t)gr * 16;
            cp16(d + AHI_O, Ahi + go, ok ? 16 : 0);
            cp16(d + ALO_O, Alo + go, ok ? 16 : 0);
        }
#pragma unroll
        for (int i = 0; i < 2; i++) {
            int c = tid + i * 256;
            int k = c >> 4, gr = c & 15;
            size_t go = (size_t)(kb + k) * Ncols + n0 + gr * 8;
            uint32_t d = base + (uint32_t)k * 272 + (uint32_t)gr * 16;
            cp16(d + BHI_O, Whi + go, 16);
            cp16(d + BLO_O, Wlo + go, 16);
        }
        CP_COMMIT();
    }
    __device__ __forceinline__ void compute(int buf) {
        uint32_t base = sb + (uint32_t)buf * STG;
#pragma unroll
        for (int ks = 0; ks < 32; ks += 16) {
            uint32_t bhi[4][2], blo[4][2];
            const uint32_t brow = (uint32_t)(ks + (lid & 15)) * 272 + (uint32_t)((lid >> 4) * 16);
#pragma unroll
            for (int p = 0; p < 2; p++) {
                uint32_t baddr = base + brow + (uint32_t)(wn * 32 + p * 16) * 2;
                uint32_t r[4];
                ldsm4t(r, baddr + BHI_O);
                bhi[2 * p][0] = r[0]; bhi[2 * p][1] = r[1];
                bhi[2 * p + 1][0] = r[2]; bhi[2 * p + 1][1] = r[3];
                ldsm4t(r, baddr + BLO_O);
                blo[2 * p][0] = r[0]; blo[2 * p][1] = r[1];
                blo[2 * p + 1][0] = r[2]; blo[2 * p + 1][1] = r[3];
            }
            const uint32_t arow = (uint32_t)(wm * 64 + (lid & 15)) * 80
                                + (uint32_t)ks * 2 + (uint32_t)(lid >> 4) * 16;
#pragma unroll
            for (int mt = 0; mt < 4; mt++) {
                uint32_t aaddr = base + arow + (uint32_t)mt * (16 * 80);
                uint32_t ahi4[4], alo4[4];
                ldsm4(ahi4, aaddr + AHI_O);
                ldsm4(alo4, aaddr + ALO_O);
#pragma unroll
                for (int nt = 0; nt < 4; nt++) {
                    mma16816(acc[mt][nt], ahi4, bhi[nt]);
                    mma16816(acc[mt][nt], ahi4, blo[nt]);
                    mma16816(acc[mt][nt], alo4, bhi[nt]);
                }
            }
        }
    }
    __device__ __forceinline__ void run(const bf16* Ahi, const bf16* Alo,
                                        const bf16* Whi, const bf16* Wlo,
                                        int M, int Ncols, int K) {
        const int nch = K >> 5;
        stage(0, Ahi, Alo, Whi, Wlo, M, Ncols, K, 0);
        if (nch > 1) stage(1, Ahi, Alo, Whi, Wlo, M, Ncols, K, 32);
        for (int i = 0; i < nch; i++) {
            if (i == nch - 1) { CP_WAIT0(); } else { CP_WAIT1(); }
            __syncthreads();
            compute(i & 1);
            if (i + 2 < nch) {
                __syncthreads();
                stage(i & 1, Ahi, Alo, Whi, Wlo, M, Ncols, K, (i + 2) * 32);
            }
        }
    }
};

// ---------------- fp16 GEMM core (edge path): single A, hi/lo W, 2 products -
#define HSTG   27648u
#define HA_O   0u
#define HBHI_O 10240u
#define HBLO_O 18944u
#define SMH_GEMM 55296
#define SMH_EDGE 67584   /* core uses 55296; epilogue stash needs 128*132*4 */

struct GemmCoreH {
    uint32_t sb;
    int tid, lid, wm, wn, m0, n0;
    float acc[4][4][4];

    __device__ __forceinline__ void init(uint8_t* smp, int bm, int bn) {
        sb = smem_u32(smp);
        tid = threadIdx.x; lid = tid & 31;
        int wid = tid >> 5;
        wm = wid >> 2; wn = wid & 3;
        m0 = bm * 128; n0 = bn * 128;
#pragma unroll
        for (int i = 0; i < 4; i++)
#pragma unroll
            for (int j = 0; j < 4; j++)
#pragma unroll
                for (int q = 0; q < 4; q++) acc[i][j][q] = 0.f;
    }
    __device__ __forceinline__ void stage(int buf, const __half* A,
                                          const __half* Whi, const __half* Wlo,
                                          int M, int Ncols, int K, int kb) {
        uint32_t base = sb + (uint32_t)buf * HSTG;
#pragma unroll
        for (int i = 0; i < 2; i++) {
            int c = tid + i * 256;
            int row = c >> 2, gr = c & 3;
            bool ok = (m0 + row) < M;
            size_t go = (size_t)(ok ? m0 + row : 0) * K + kb + gr * 8;
            cp16(base + HA_O + (uint32_t)row * 80 + (uint32_t)gr * 16, A + go, ok ? 16 : 0);
        }
#pragma unroll
        for (int i = 0; i < 2; i++) {
            int c = tid + i * 256;
            int k = c >> 4, gr = c & 15;
            size_t go = (size_t)(kb + k) * Ncols + n0 + gr * 8;
            uint32_t d = base + (uint32_t)k * 272 + (uint32_t)gr * 16;
            cp16(d + HBHI_O, Whi + go, 16);
            cp16(d + HBLO_O, Wlo + go, 16);
        }
        CP_COMMIT();
    }
    __device__ __forceinline__ void compute(int buf) {
        uint32_t base = sb + (uint32_t)buf * HSTG;
#pragma unroll
        for (int ks = 0; ks < 32; ks += 16) {
            uint32_t bhi[4][2], blo[4][2];
            const uint32_t brow = (uint32_t)(ks + (lid & 15)) * 272 + (uint32_t)((lid >> 4) * 16);
#pragma unroll
            for (int p = 0; p < 2; p++) {
                uint32_t baddr = base + brow + (uint32_t)(wn * 32 + p * 16) * 2;
                uint32_t r[4];
                ldsm4t(r, baddr + HBHI_O);
                bhi[2 * p][0] = r[0]; bhi[2 * p][1] = r[1];
                bhi[2 * p + 1][0] = r[2]; bhi[2 * p + 1][1] = r[3];
                ldsm4t(r, baddr + HBLO_O);
                blo[2 * p][0] = r[0]; blo[2 * p][1] = r[1];
                blo[2 * p + 1][0] = r[2]; blo[2 * p + 1][1] = r[3];
            }
            const uint32_t arow = (uint32_t)(wm * 64 + (lid & 15)) * 80
                                + (uint32_t)ks * 2 + (uint32_t)(lid >> 4) * 16;
#pragma unroll
            for (int mt = 0; mt < 4; mt++) {
                uint32_t a4[4];
                ldsm4(a4, base + HA_O + arow + (uint32_t)mt * (16 * 80));
#pragma unroll
                for (int nt = 0; nt < 4; nt++) {
                    mma16816h(acc[mt][nt], a4, bhi[nt]);
                    mma16816h(acc[mt][nt], a4, blo[nt]);
                }
            }
        }
    }
    __device__ __forceinline__ void run(const __half* A, const __half* Whi, const __half* Wlo,
                                        int M, int Ncols, int K) {
        const int nch = K >> 5;
        stage(0, A, Whi, Wlo, M, Ncols, K, 0);
        if (nch > 1) stage(1, A, Whi, Wlo, M, Ncols, K, 32);
        for (int i = 0; i < nch; i++) {
            if (i == nch - 1) { CP_WAIT0(); } else { CP_WAIT1(); }
            __syncthreads();
            compute(i & 1);
            if (i + 2 < nch) {
                __syncthreads();
                stage(i & 1, A, Whi, Wlo, M, Ncols, K, (i + 2) * 32);
            }
        }
    }
};

// ---------------- generic bf16-pair GEMM (node path) ----------------
template <int RESMODE, int OUTMODE, bool RELU, bool STATS>
__global__ void __launch_bounds__(256, 2)
mma_gemmB(const bf16* __restrict__ Ahi, const bf16* __restrict__ Alo,
          const bf16* __restrict__ Whi, const bf16* __restrict__ Wlo,
          const float* __restrict__ bias, const float* __restrict__ resf,
          const bf16* __restrict__ reshi, const bf16* __restrict__ reslo,
          float* __restrict__ Cf, bf16* __restrict__ Chi, bf16* __restrict__ Clo,
          float* __restrict__ stats, int M, int Ncols, int K)
{
    extern __shared__ __align__(16) uint8_t sm[];
    GemmCoreB g;
    g.init(sm, blockIdx.y, blockIdx.x);
    g.run(Ahi, Alo, Whi, Wlo, M, Ncols, K);

    float ts0[4], ts1[4], tq0[4], tq1[4];
    if (STATS) {
#pragma unroll
        for (int nt = 0; nt < 4; nt++) { ts0[nt] = ts1[nt] = tq0[nt] = tq1[nt] = 0.f; }
    }

    const int qr = g.lid >> 2, qc = (g.lid & 3) * 2;
#pragma unroll
    for (int mt = 0; mt < 4; mt++) {
#pragma unroll
        for (int nt = 0; nt < 4; nt++) {
            int col = g.n0 + g.wn * 32 + nt * 8 + qc;
            float b0 = bias[col], b1 = bias[col + 1];
#pragma unroll
            for (int half = 0; half < 2; half++) {
                int row = g.m0 + g.wm * 64 + mt * 16 + qr + half * 8;
                if (row >= M) continue;
                float o0 = g.acc[mt][nt][half * 2 + 0] + b0;
                float o1 = g.acc[mt][nt][half * 2 + 1] + b1;
                size_t off = (size_t)row * Ncols + col;
                if (RESMODE == 1) {
                    float2 rr = *(const float2*)(resf + off);
                    o0 += rr.x; o1 += rr.y;
                } else if (RESMODE == 2) {
                    float2 rh = up2(*(const uint32_t*)(reshi + off));
                    float2 rl = up2(*(const uint32_t*)(reslo + off));
                    o0 += rh.x + rl.x; o1 += rh.y + rl.y;
                }
                if (RELU) { o0 = fmaxf(o0, 0.f); o1 = fmaxf(o1, 0.f); }
                if (STATS) {
                    ts0[nt] += o0; ts1[nt] += o1;
                    tq0[nt] = fmaf(o0, o0, tq0[nt]); tq1[nt] = fmaf(o1, o1, tq1[nt]);
                }
                if (OUTMODE == 0) {
                    *(float2*)(Cf + off) = make_float2(o0, o1);
                } else {
                    uint32_t lw, hw = packsplit(o0, o1, lw);
                    *(uint32_t*)(Chi + off) = hw;
                    *(uint32_t*)(Clo + off) = lw;
                }
            }
        }
    }
    if (STATS) {
#pragma unroll
        for (int nt = 0; nt < 4; nt++) {
            float a = ts0[nt], b = ts1[nt], c = tq0[nt], d = tq1[nt];
#pragma unroll
            for (int m = 4; m <= 16; m <<= 1) {
                a += __shfl_xor_sync(0xffffffff, a, m);
                b += __shfl_xor_sync(0xffffffff, b, m);
                c += __shfl_xor_sync(0xffffffff, c, m);
                d += __shfl_xor_sync(0xffffffff, d, m);
            }
            if (qr == 0) {
                int col = g.n0 + g.wn * 32 + nt * 8 + qc;
                redf(stats + col, a);
                redf(stats + col + 1, b);
                redf(stats + DIM + col, c);
                redf(stats + DIM + col + 1, d);
            }
        }
    }
}

// ---------------- fused QKV (bf16-pair; blockIdx.x selects weight) ----------
__global__ void __launch_bounds__(256, 2)
qkv_gemm(const bf16* __restrict__ xhi, const bf16* __restrict__ xlo,
         const bf16* __restrict__ qh, const bf16* __restrict__ ql,
         const bf16* __restrict__ kh, const bf16* __restrict__ kl,
         const bf16* __restrict__ vh, const bf16* __restrict__ vl,
         const float* __restrict__ bq, const float* __restrict__ bk,
         const float* __restrict__ bv,
         float* __restrict__ Qo, float* __restrict__ Ko, float* __restrict__ Vo)
{
    extern __shared__ __align__(16) uint8_t sm[];
    const bf16* Whi = qh; const bf16* Wlo = ql;
    const float* bias = bq; float* C = Qo;
    if (blockIdx.x == 1) { Whi = kh; Wlo = kl; bias = bk; C = Ko; }
    else if (blockIdx.x == 2) { Whi = vh; Wlo = vl; bias = bv; C = Vo; }

    GemmCoreB g;
    g.init(sm, blockIdx.y, 0);
    g.run(xhi, xlo, Whi, Wlo, NN, 128, 128);

    const int qr = g.lid >> 2, qc = (g.lid & 3) * 2;
#pragma unroll
    for (int mt = 0; mt < 4; mt++) {
#pragma unroll
        for (int nt = 0; nt < 4; nt++) {
            int col = g.wn * 32 + nt * 8 + qc;
            float b0 = bias[col], b1 = bias[col + 1];
#pragma unroll
            for (int half = 0; half < 2; half++) {
                int row = g.m0 + g.wm * 64 + mt * 16 + qr + half * 8;
                if (row >= NN) continue;
                *(float2*)(C + (size_t)row * 128 + col) =
                    make_float2(g.acc[mt][nt][half * 2 + 0] + b0,
                                g.acc[mt][nt][half * 2 + 1] + b1);
            }
        }
    }
}

// ---------------- fused Ee GEMM (fp16) + edge score/logit/exp ----------------
union U16 { float4 q[4]; float f[16]; };

__global__ void __launch_bounds__(256, 2)
edge_gemm_fused(const __half* __restrict__ ea16,
                const __half* __restrict__ weh, const __half* __restrict__ wel,
                const float* __restrict__ bias,
                const int* __restrict__ ei, const float* __restrict__ Aw,
                const float* __restrict__ Qh, const float* __restrict__ Kh,
                __half* __restrict__ et16, float* __restrict__ lg)
{
    extern __shared__ __align__(16) uint8_t sm[];
    __shared__ float sAw[DIM];
    if (threadIdx.x < DIM) sAw[threadIdx.x] = Aw[threadIdx.x];

    GemmCoreH g;
    g.init(sm, blockIdx.y, blockIdx.x);
    g.run(ea16, weh, wel, NE, 256, 128);

    __syncthreads();
    float* sC = (float*)sm;
    const int qr = g.lid >> 2, qc = (g.lid & 3) * 2;
#pragma unroll
    for (int mt = 0; mt < 4; mt++) {
#pragma unroll
        for (int nt = 0; nt < 4; nt++) {
            int col = g.wn * 32 + nt * 8 + qc;
            float b0 = bias[g.n0 + col], b1 = bias[g.n0 + col + 1];
#pragma unroll
            for (int half = 0; half < 2; half++) {
                int row = g.wm * 64 + mt * 16 + qr + half * 8;
                *(float2*)(sC + row * 132 + col) =
                    make_float2(g.acc[mt][nt][half * 2 + 0] + b0,
                                g.acc[mt][nt][half * 2 + 1] + b1);
            }
        }
    }
    __syncthreads();

    const int e = threadIdx.x & 127;
    const int ge = g.m0 + e;                    // NE % 128 == 0
    const int src = ei[ge], dst = ei[NE + ge];
#pragma unroll
    for (int u = 0; u < 2; u++) {
        const int hl = (threadIdx.x >> 7) * 2 + u;
        const int h = blockIdx.x * 4 + hl;
        const float* ew = sC + e * 132 + hl * 32;
        U16 K4, Q4, EW, EB, ET;
        const float4* kp = (const float4*)(Kh + (size_t)src * DIM + h * DH);
        const float4* qp = (const float4*)(Qh + (size_t)dst * DIM + h * DH);
#pragma unroll
        for (int q = 0; q < 4; q++) {
            K4.q[q] = kp[q]; Q4.q[q] = qp[q];
            EW.q[q] = *(const float4*)(ew + q * 4);
            EB.q[q] = *(const float4*)(ew + 16 + q * 4);
        }
        float logit = 0.f;
#pragma unroll
        for (int d = 0; d < 16; d++) {
            float s = (K4.f[d] + Q4.f[d]) * EW.f[d];
            float a = fabsf(s);
            float r = (a > 0.f) ? copysignf(sqrtf(a), s) : 0.f;
            float v = fmaxf(r + EB.f[d], 0.f);
            ET.f[d] = v;
            logit = fmaf(v, sAw[d * NH + h], logit);
        }
        logit = fminf(fmaxf(logit, -5.f), 5.f);
        // write et as single fp16
        uint32_t hw[8];
#pragma unroll
        for (int q = 0; q < 8; q++)
            hw[q] = pack2h(__float2half_rn(ET.f[2 * q]), __float2half_rn(ET.f[2 * q + 1]));
        __half* pe = et16 + (size_t)ge * DIM + h * DH;
        *(uint4*)pe       = make_uint4(hw[0], hw[1], hw[2], hw[3]);
        *((uint4*)pe + 1) = make_uint4(hw[4], hw[5], hw[6], hw[7]);
        lg[ge * NH + h] = expf(logit);
    }
}

// ---------------- WOe GEMM (fp16 core) + residual + fused BN stats ----------
__global__ void __launch_bounds__(256, 2)
woe_gemm(const __half* __restrict__ et16,
         const __half* __restrict__ weh, const __half* __restrict__ wel,
         const float* __restrict__ bias, const float* __restrict__ resf,
         float* __restrict__ Cf, float* __restrict__ stats)
{
    extern __shared__ __align__(16) uint8_t sm[];
    GemmCoreH g;
    g.init(sm, blockIdx.y, 0);
    g.run(et16, weh, wel, NE, 128, 128);

    float ts0[4], ts1[4], tq0[4], tq1[4];
#pragma unroll
    for (int nt = 0; nt < 4; nt++) { ts0[nt] = ts1[nt] = tq0[nt] = tq1[nt] = 0.f; }

    const int qr = g.lid >> 2, qc = (g.lid & 3) * 2;
#pragma unroll
    for (int mt = 0; mt < 4; mt++) {
#pragma unroll
        for (int nt = 0; nt < 4; nt++) {
            int col = g.wn * 32 + nt * 8 + qc;
            float b0 = bias[col], b1 = bias[col + 1];
#pragma unroll
            for (int half = 0; half < 2; half++) {
                int row = g.m0 + g.wm * 64 + mt * 16 + qr + half * 8;
                float o0 = g.acc[mt][nt][half * 2 + 0] + b0;
                float o1 = g.acc[mt][nt][half * 2 + 1] + b1;
                size_t off = (size_t)row * 128 + col;
                float2 rr = *(const float2*)(resf + off);
                o0 += rr.x; o1 += rr.y;
                ts0[nt] += o0; ts1[nt] += o1;
                tq0[nt] = fmaf(o0, o0, tq0[nt]); tq1[nt] = fmaf(o1, o1, tq1[nt]);
                *(float2*)(Cf + off) = make_float2(o0, o1);
            }
        }
    }
#pragma unroll
    for (int nt = 0; nt < 4; nt++) {
        float a = ts0[nt], b = ts1[nt], c = tq0[nt], d = tq1[nt];
#pragma unroll
        for (int m = 4; m <= 16; m <<= 1) {
            a += __shfl_xor_sync(0xffffffff, a, m);
            b += __shfl_xor_sync(0xffffffff, b, m);
            c += __shfl_xor_sync(0xffffffff, c, m);
            d += __shfl_xor_sync(0xffffffff, d, m);
        }
        if (qr == 0) {
            int col = g.wn * 32 + nt * 8 + qc;
            redf(stats + col, a);
            redf(stats + col + 1, b);
            redf(stats + DIM + col, c);
            redf(stats + DIM + col + 1, d);
        }
    }
}

// ---------------- misc / edge / node / bn kernels ----------------
__global__ void preconv(const float* __restrict__ in, bf16* __restrict__ hi,
                        bf16* __restrict__ lo, long long n)
{
    long long i = ((long long)blockIdx.x * blockDim.x + threadIdx.x) * 4;
    if (i >= n) return;
    float4 v = *(const float4*)(in + i);
    uint2 h, l;
    split4(v, h, l);
    *(uint2*)(hi + i) = h;
    *(uint2*)(lo + i) = l;
}

__global__ void preconv_h(const float* __restrict__ in, __half* __restrict__ out, long long n)
{
    long long i = ((long long)blockIdx.x * blockDim.x + threadIdx.x) * 4;
    if (i >= n) return;
    float4 v = *(const float4*)(in + i);
    uint2 o;
    o.x = pack2h(__float2half_rn(v.x), __float2half_rn(v.y));
    o.y = pack2h(__float2half_rn(v.z), __float2half_rn(v.w));
    *(uint2*)(out + i) = o;
}

__global__ void preconv_hpair(const float* __restrict__ in, __half* __restrict__ hi,
                              __half* __restrict__ lo, long long n)
{
    long long i = ((long long)blockIdx.x * blockDim.x + threadIdx.x) * 4;
    if (i >= n) return;
    float4 v = *(const float4*)(in + i);
    float vv[4] = {v.x, v.y, v.z, v.w};
    __half hh[4], ll[4];
#pragma unroll
    for (int q = 0; q < 4; q++) {
        hh[q] = __float2half_rn(vv[q]);
        ll[q] = __float2half_rn(vv[q] - __half2float(hh[q]));
    }
    *(uint2*)(hi + i) = make_uint2(pack2h(hh[0], hh[1]), pack2h(hh[2], hh[3]));
    *(uint2*)(lo + i) = make_uint2(pack2h(ll[0], ll[1]), pack2h(ll[2], ll[3]));
}

// denominator + unnormalized scatter; lg holds ex; et single fp16.
__global__ void edge_scatter(const int* __restrict__ ei, const float* __restrict__ lg,
                             float* __restrict__ den, const float* __restrict__ Vh,
                             const __half* __restrict__ et16,
                             float* __restrict__ wV, float* __restrict__ rowV)
{
    int t = blockIdx.x * blockDim.x + threadIdx.x;
    if (t >= NE * NH) return;
    int e = t >> 3, h = t & 7;
    int src = ei[e], dst = ei[NE + e];
    float ex = lg[t];
    redf(&den[dst * NH + h], ex);
    U16 V4, E4;
    const float4* vp = (const float4*)(Vh + (size_t)src * DIM + h * DH);
#pragma unroll
    for (int q = 0; q < 4; q++) V4.q[q] = vp[q];
    const uint4* pe = (const uint4*)(et16 + (size_t)e * DIM + h * DH);
#pragma unroll
    for (int half = 0; half < 2; half++) {
        uint4 E = pe[half];
        uint32_t ew[4] = {E.x, E.y, E.z, E.w};
#pragma unroll
        for (int q = 0; q < 4; q++) {
            float2 f = up2h(ew[q]);
            E4.f[half * 8 + q * 2 + 0] = f.x;
            E4.f[half * 8 + q * 2 + 1] = f.y;
        }
    }
    float* wv = wV + (size_t)dst * DIM + h * DH;
    float* rv = rowV + (size_t)dst * DIM + h * DH;
#pragma unroll
    for (int q = 0; q < 4; q++) {
        red4(wv + q * 4, V4.q[q].x * ex, V4.q[q].y * ex, V4.q[q].z * ex, V4.q[q].w * ex);
        red4(rv + q * 4, E4.f[q * 4] * ex, E4.f[q * 4 + 1] * ex,
             E4.f[q * 4 + 2] * ex, E4.f[q * 4 + 3] * ex);
    }
}

__global__ void node_fix(const float* __restrict__ wV, const float* __restrict__ rowV,
                         const float* __restrict__ den,
                         const float* __restrict__ VeRow, const float* __restrict__ log_deg,
                         const float* __restrict__ deg_coef,
                         bf16* __restrict__ hatth, bf16* __restrict__ hattl)
{
    int t = blockIdx.x * blockDim.x + threadIdx.x;
    if (t >= NN * 64) return;
    int n = t >> 6, c0 = (t & 63) * 2, h = c0 >> 4, co = c0 & 15;
    size_t off = (size_t)n * DIM + c0;
    float inv = 1.f / (den[n * NH + h] + 1e-16f);
    float a0 = wV[off], a1 = wV[off + 1];
    const float* rv = rowV + (size_t)n * DIM + h * DH;
#pragma unroll
    for (int d2 = 0; d2 < 16; d2++) {
        float r = rv[d2];
        a0 = fmaf(r, VeRow[d2 * DIM + h * DH + co], a0);
        a1 = fmaf(r, VeRow[d2 * DIM + h * DH + co + 1], a1);
    }
    a0 *= inv; a1 *= inv;
    float ld = log_deg[n];
    float o0 = a0 * (deg_coef[2 * c0] + ld * deg_coef[2 * c0 + 1]);
    float o1 = a1 * (deg_coef[2 * c0 + 2] + ld * deg_coef[2 * c0 + 3]);
    uint32_t lw, hw = packsplit(o0, o1, lw);
    *(uint32_t*)(hatth + off) = hw;
    *(uint32_t*)(hattl + off) = lw;
}

template <bool PAIR>
__global__ void bn_apply(const float* __restrict__ v, float* __restrict__ outf,
                         bf16* __restrict__ outhi, bf16* __restrict__ outlo, int M,
                         const float* __restrict__ sums,
                         const float* __restrict__ g, const float* __restrict__ b, float invM)
{
    long long i = ((long long)blockIdx.x * blockDim.x + threadIdx.x) * 2;
    if (i >= (long long)M * DIM) return;
    int c = (int)(i & (DIM - 1));
    float m0 = sums[c] * invM, m1 = sums[c + 1] * invM;
    float var0 = fmaf(-m0, m0, sums[DIM + c] * invM);
    float var1 = fmaf(-m1, m1, sums[DIM + c + 1] * invM);
    float2 vv = *(const float2*)(v + i);
    float o0 = (vv.x - m0) * rsqrtf(var0 + 1e-5f) * g[c] + b[c];
    float o1 = (vv.y - m1) * rsqrtf(var1 + 1e-5f) * g[c + 1] + b[c + 1];
    if (!PAIR) {
        *(float2*)(outf + i) = make_float2(o0, o1);
    } else {
        uint32_t lw, hw = packsplit(o0, o1, lw);
        *(uint32_t*)(outhi + i) = hw;
        *(uint32_t*)(outlo + i) = lw;
    }
}

// ---------------- launch ----------------
#define SYM(var, sym) cudaGetSymbolAddress((void**)&var, sym)

extern "C" void kernel_launch(void* const* d_in, const int* in_sizes, int n_in,
                              void* d_out, int out_size)
{
    const float* x         = (const float*)d_in[0];
    const float* edge_attr = (const float*)d_in[1];
    const int*   ei        = (const int*)d_in[2];
    const float* log_deg   = (const float*)d_in[3];
    const float* Wq = (const float*)d_in[4],  *bq  = (const float*)d_in[5];
    const float* Wk = (const float*)d_in[6],  *bk  = (const float*)d_in[7];
    const float* We = (const float*)d_in[8],  *be  = (const float*)d_in[9];
    const float* Wv = (const float*)d_in[10], *bv  = (const float*)d_in[11];
    const float* Aw = (const float*)d_in[12], *VeRow = (const float*)d_in[13];
    const float* WOh = (const float*)d_in[14], *bOh = (const float*)d_in[15];
    const float* WOe = (const float*)d_in[16], *bOe = (const float*)d_in[17];
    const float* deg_coef = (const float*)d_in[18];
    const float* g1h = (const float*)d_in[19], *b1h = (const float*)d_in[20];
    const float* g1e = (const float*)d_in[21], *b1e = (const float*)d_in[22];
    const float* g2h = (const float*)d_in[23], *b2h = (const float*)d_in[24];
    const float* W1 = (const float*)d_in[25], *b1 = (const float*)d_in[26];
    const float* W2 = (const float*)d_in[27], *b2 = (const float*)d_in[28];

    float *Qh, *Kh, *Vh, *lg, *den, *wV, *rowV, *v1, *v2, *s1, *s2buf, *se;
    SYM(Qh, g_Qh); SYM(Kh, g_Kh); SYM(Vh, g_Vh);
    SYM(lg, g_lg); SYM(den, g_den);
    SYM(wV, g_wV); SYM(rowV, g_rowV);
    SYM(v1, g_v1); SYM(v2, g_v2);
    SYM(s1, g_s1); SYM(s2buf, g_s2); SYM(se, g_se);
    __half *ea16, *et16, *we16h, *we16l, *woe16h, *woe16l;
    SYM(ea16, g_ea16); SYM(et16, g_et16);
    SYM(we16h, g_we16h); SYM(we16l, g_we16l);
    SYM(woe16h, g_woe16h); SYM(woe16l, g_woe16l);
    bf16 *xhi, *xlo, *hatth, *hattl, *hbnh, *hbnl, *h2ah, *h2al;
    SYM(xhi, g_xhi); SYM(xlo, g_xlo);
    SYM(hatth, g_hatth); SYM(hattl, g_hattl);
    SYM(hbnh, g_hbnh); SYM(hbnl, g_hbnl);
    SYM(h2ah, g_h2ah); SYM(h2al, g_h2al);
    bf16 *wq_h, *wq_l, *wk_h, *wk_l, *wv_h, *wv_l;
    bf16 *woh_h, *woh_l, *w1_h, *w1_l, *w2_h, *w2_l;
    SYM(wq_h, g_wq_h); SYM(wq_l, g_wq_l); SYM(wk_h, g_wk_h); SYM(wk_l, g_wk_l);
    SYM(wv_h, g_wv_h); SYM(wv_l, g_wv_l);
    SYM(woh_h, g_woh_h); SYM(woh_l, g_woh_l);
    SYM(w1_h, g_w1_h); SYM(w1_l, g_w1_l); SYM(w2_h, g_w2_h); SYM(w2_l, g_w2_l);

    float* hout = (float*)d_out;
    float* eout = (float*)d_out + (size_t)NN * DIM;

    cudaFuncSetAttribute(mma_gemmB<1, 0, false, true >, cudaFuncAttributeMaxDynamicSharedMemorySize, SMB_TOTAL);
    cudaFuncSetAttribute(mma_gemmB<0, 1, true,  false>, cudaFuncAttributeMaxDynamicSharedMemorySize, SMB_TOTAL);
    cudaFuncSetAttribute(mma_gemmB<2, 0, false, true >, cudaFuncAttributeMaxDynamicSharedMemorySize, SMB_TOTAL);
    cudaFuncSetAttribute(qkv_gemm, cudaFuncAttributeMaxDynamicSharedMemorySize, SMB_TOTAL);
    cudaFuncSetAttribute(edge_gemm_fused, cudaFuncAttributeMaxDynamicSharedMemorySize, SMH_EDGE);
    cudaFuncSetAttribute(woe_gemm, cudaFuncAttributeMaxDynamicSharedMemorySize, SMH_GEMM);

    // lazily-created side stream + events
    static cudaStream_t sside = nullptr;
    static cudaEvent_t ev0 = nullptr, evA = nullptr, ev1 = nullptr, ev2 = nullptr;
    if (!sside) {
        cudaStreamCreateWithFlags(&sside, cudaStreamNonBlocking);
        cudaEventCreateWithFlags(&ev0, cudaEventDisableTiming);
        cudaEventCreateWithFlags(&evA, cudaEventDisableTiming);
        cudaEventCreateWithFlags(&ev1, cudaEventDisableTiming);
        cudaEventCreateWithFlags(&ev2, cudaEventDisableTiming);
    }

    auto pc = [&](const float* in, bf16* h, bf16* l, long long n, cudaStream_t st) {
        preconv<<<cdiv(n / 4, 256), 256, 0, st>>>(in, h, l, n);
    };

    // fork side stream; big edge_attr fp16 preconv there
    cudaEventRecord(ev0, 0);
    cudaStreamWaitEvent(sside, ev0, 0);
    preconv_h<<<cdiv((long long)NE * DIM / 4, 256), 256, 0, sside>>>(edge_attr, ea16, (long long)NE * DIM);
    cudaEventRecord(evA, sside);

    // main: small preconvs + memsets + QKV
    pc(x, xhi, xlo, (long long)NN * DIM, 0);
    pc(Wq, wq_h, wq_l, DIM * DIM, 0);
    pc(Wk, wk_h, wk_l, DIM * DIM, 0);
    pc(Wv, wv_h, wv_l, DIM * DIM, 0);
    preconv_hpair<<<cdiv(DIM * 2 * DIM / 4, 256), 256>>>(We, we16h, we16l, DIM * 2 * DIM);
    preconv_hpair<<<cdiv(DIM * DIM / 4, 256), 256>>>(WOe, woe16h, woe16l, DIM * DIM);
    pc(WOh, woh_h, woh_l, DIM * DIM, 0);
    pc(W1, w1_h, w1_l, DIM * 2 * DIM, 0);
    pc(W2, w2_h, w2_l, 2 * DIM * DIM, 0);

    cudaMemsetAsync(wV, 0, (size_t)NN * DIM * sizeof(float));
    cudaMemsetAsync(rowV, 0, (size_t)NN * DIM * sizeof(float));
    cudaMemsetAsync(den, 0, (size_t)NN * NH * sizeof(float));
    cudaMemsetAsync(s1, 0, 2 * DIM * sizeof(float));
    cudaMemsetAsync(s2buf, 0, 2 * DIM * sizeof(float));
    cudaMemsetAsync(se, 0, 2 * DIM * sizeof(float));

    const int gN = cdiv(NN, 128), gE = cdiv(NE, 128);

    qkv_gemm<<<dim3(3, gN), 256, SMB_TOTAL>>>(xhi, xlo, wq_h, wq_l, wk_h, wk_l,
                                              wv_h, wv_l, bq, bk, bv, Qh, Kh, Vh);

    cudaStreamWaitEvent(0, evA, 0);
    edge_gemm_fused<<<dim3(2, gE), 256, SMH_EDGE>>>(ea16, we16h, we16l, be,
                                                    ei, Aw, Qh, Kh, et16, lg);
    cudaEventRecord(ev1, 0);

    // side stream: e-path (WOe fp16 + stats, BN apply into eout)
    cudaStreamWaitEvent(sside, ev1, 0);
    woe_gemm<<<dim3(1, gE), 256, SMH_GEMM, sside>>>(et16, woe16h, woe16l, bOe, edge_attr, eout, se);
    bn_apply<false><<<cdiv((long long)NE * 64, 256), 256, 0, sside>>>(
        eout, eout, nullptr, nullptr, NE, se, g1e, b1e, 1.f / NE);
    cudaEventRecord(ev2, sside);

    // main stream: h-path
    edge_scatter<<<cdiv(NE * NH, 256), 256>>>(ei, lg, den, Vh, et16, wV, rowV);
    node_fix<<<cdiv(NN * 64, 256), 256>>>(wV, rowV, den, VeRow, log_deg, deg_coef, hatth, hattl);
    mma_gemmB<1, 0, false, true><<<dim3(1, gN), 256, SMB_TOTAL>>>(
        hatth, hattl, woh_h, woh_l, bOh, x, nullptr, nullptr, v1, nullptr, nullptr, s1, NN, 128, 128);
    bn_apply<true><<<cdiv((long long)NN * 64, 256), 256>>>(v1, nullptr, hbnh, hbnl, NN, s1, g1h, b1h, 1.f / NN);
    mma_gemmB<0, 1, true, false><<<dim3(2, gN), 256, SMB_TOTAL>>>(
        hbnh, hbnl, w1_h, w1_l, b1, nullptr, nullptr, nullptr, nullptr, h2ah, h2al, nullptr, NN, 256, 128);
    mma_gemmB<2, 0, false, true><<<dim3(1, gN), 256, SMB_TOTAL>>>(
        h2ah, h2al, w2_h, w2_l, b2, nullptr, hbnh, hbnl, v2, nullptr, nullptr, s2buf, NN, 128, 256);
    bn_apply<false><<<cdiv((long long)NN * 64, 256), 256>>>(v2, hout, nullptr, nullptr, NN, s2buf, g2h, b2h, 1.f / NN);

    // join side stream back into the captured main stream
    cudaStreamWaitEvent(0, ev2, 0);
}

// round 14
// speedup vs baseline: 1.1941x; 1.0175x over previous
#include <cuda_runtime.h>
#include <cuda_bf16.h>
#include <cuda_fp16.h>
#include <math.h>
#include <stdint.h>

#define NN 40000
#define NE 640000
#define DIM 128
#define NH 8
#define DH 16

typedef __nv_bfloat16 bf16;

// ---------------- scratch (device globals: allocation-free) ----------------
__device__ float g_Qh[(size_t)NN * DIM];
__device__ float g_Kh[(size_t)NN * DIM];
__device__ float g_Vh[(size_t)NN * DIM];
__device__ float g_lg[(size_t)NE * NH];
__device__ float g_den[(size_t)NN * NH];
__device__ float g_wV[(size_t)NN * DIM];
__device__ float g_rowV[(size_t)NN * DIM];
__device__ float g_v1[(size_t)NN * DIM];
__device__ float g_v2[(size_t)NN * DIM];
__device__ float g_s1[2 * DIM];
__device__ float g_s2[2 * DIM];
__device__ float g_se[2 * DIM];
// fp16 (edge path)
__device__ __half g_ea16[(size_t)NE * DIM];
__device__ __half g_et16[(size_t)NE * DIM];
__device__ __half g_we16h[DIM * 2 * DIM], g_we16l[DIM * 2 * DIM];
__device__ __half g_woe16h[DIM * DIM], g_woe16l[DIM * DIM];
// fp16 (node h-path)
__device__ __half g_hatt16[(size_t)NN * DIM];
__device__ __half g_hbn16h[(size_t)NN * DIM], g_hbn16l[(size_t)NN * DIM];
__device__ __half g_h2a16[(size_t)NN * 2 * DIM];
__device__ __half g_woh16h[DIM * DIM], g_woh16l[DIM * DIM];
__device__ __half g_w116h[DIM * 2 * DIM], g_w116l[DIM * 2 * DIM];
__device__ __half g_w216h[2 * DIM * DIM], g_w216l[2 * DIM * DIM];
// bf16 hi/lo pairs (QKV path — protects logit precision)
__device__ bf16 g_xhi[(size_t)NN * DIM],  g_xlo[(size_t)NN * DIM];
__device__ bf16 g_wq_h[DIM * DIM], g_wq_l[DIM * DIM];
__device__ bf16 g_wk_h[DIM * DIM], g_wk_l[DIM * DIM];
__device__ bf16 g_wv_h[DIM * DIM], g_wv_l[DIM * DIM];

static inline int cdiv(long long a, long long b) { return (int)((a + b - 1) / b); }

// ---------------- helpers ----------------
__device__ __forceinline__ uint32_t smem_u32(const void* p) {
    uint32_t a;
    asm("{ .reg .u64 t; cvta.to.shared.u64 t, %1; cvt.u32.u64 %0, t; }" : "=r"(a) : "l"(p));
    return a;
}
__device__ __forceinline__ void ldsm4(uint32_t (&r)[4], uint32_t addr) {
    asm volatile("ldmatrix.sync.aligned.m8n8.x4.shared.b16 {%0,%1,%2,%3}, [%4];"
                 : "=r"(r[0]), "=r"(r[1]), "=r"(r[2]), "=r"(r[3]) : "r"(addr));
}
__device__ __forceinline__ void ldsm4t(uint32_t (&r)[4], uint32_t addr) {
    asm volatile("ldmatrix.sync.aligned.m8n8.x4.trans.shared.b16 {%0,%1,%2,%3}, [%4];"
                 : "=r"(r[0]), "=r"(r[1]), "=r"(r[2]), "=r"(r[3]) : "r"(addr));
}
__device__ __forceinline__ void mma16816(float (&d)[4], const uint32_t (&a)[4], const uint32_t* b) {
    asm volatile("mma.sync.aligned.m16n8k16.row.col.f32.bf16.bf16.f32 "
                 "{%0,%1,%2,%3}, {%4,%5,%6,%7}, {%8,%9}, {%0,%1,%2,%3};"
                 : "+f"(d[0]), "+f"(d[1]), "+f"(d[2]), "+f"(d[3])
                 : "r"(a[0]), "r"(a[1]), "r"(a[2]), "r"(a[3]), "r"(b[0]), "r"(b[1]));
}
__device__ __forceinline__ void mma16816h(float (&d)[4], const uint32_t (&a)[4], const uint32_t* b) {
    asm volatile("mma.sync.aligned.m16n8k16.row.col.f32.f16.f16.f32 "
                 "{%0,%1,%2,%3}, {%4,%5,%6,%7}, {%8,%9}, {%0,%1,%2,%3};"
                 : "+f"(d[0]), "+f"(d[1]), "+f"(d[2]), "+f"(d[3])
                 : "r"(a[0]), "r"(a[1]), "r"(a[2]), "r"(a[3]), "r"(b[0]), "r"(b[1]));
}
__device__ __forceinline__ uint32_t pack2(bf16 a, bf16 b) {
    return (uint32_t)__bfloat16_as_ushort(a) | ((uint32_t)__bfloat16_as_ushort(b) << 16);
}
__device__ __forceinline__ uint32_t pack2h(__half a, __half b) {
    return (uint32_t)__half_as_ushort(a) | ((uint32_t)__half_as_ushort(b) << 16);
}
__device__ __forceinline__ float2 up2h(uint32_t u) {
    __half2 h = *(__half2*)&u;
    return __half22float2(h);
}
__device__ __forceinline__ void split4(float4 v, uint2& hi, uint2& lo) {
    bf16 hx = __float2bfloat16(v.x), hy = __float2bfloat16(v.y);
    bf16 hz = __float2bfloat16(v.z), hw = __float2bfloat16(v.w);
    hi = make_uint2(pack2(hx, hy), pack2(hz, hw));
    lo = make_uint2(pack2(__float2bfloat16(v.x - __bfloat162float(hx)),
                          __float2bfloat16(v.y - __bfloat162float(hy))),
                    pack2(__float2bfloat16(v.z - __bfloat162float(hz)),
                          __float2bfloat16(v.w - __bfloat162float(hw))));
}
__device__ __forceinline__ uint32_t packsplith(float a, float b, uint32_t& lo) {
    __half h0 = __float2half_rn(a), h1 = __float2half_rn(b);
    lo = pack2h(__float2half_rn(a - __half2float(h0)),
                __float2half_rn(b - __half2float(h1)));
    return pack2h(h0, h1);
}
__device__ __forceinline__ void cp16(uint32_t dst, const void* src, int sz) {
    asm volatile("cp.async.cg.shared.global [%0], [%1], 16, %2;" :: "r"(dst), "l"(src), "r"(sz));
}
#define CP_COMMIT() asm volatile("cp.async.commit_group;" ::: "memory")
#define CP_WAIT0()  asm volatile("cp.async.wait_group 0;" ::: "memory")
#define CP_WAIT1()  asm volatile("cp.async.wait_group 1;" ::: "memory")

__device__ __forceinline__ void red4(float* p, float a, float b, float c, float d) {
    asm volatile("red.global.add.v4.f32 [%0], {%1,%2,%3,%4};"
                 :: "l"(p), "f"(a), "f"(b), "f"(c), "f"(d) : "memory");
}
__device__ __forceinline__ void redf(float* p, float a) {
    asm volatile("red.global.add.f32 [%0], %1;" :: "l"(p), "f"(a) : "memory");
}

// ---------------- bf16-pair GEMM core (QKV path): 128x128, 2-stage ---------
#define STG    37888u
#define AHI_O  0u
#define ALO_O  10240u
#define BHI_O  20480u
#define BLO_O  29184u
#define SMB_TOTAL 75776

struct GemmCoreB {
    uint32_t sb;
    int tid, lid, wm, wn, m0, n0;
    float acc[4][4][4];

    __device__ __forceinline__ void init(uint8_t* smp, int bm, int bn) {
        sb = smem_u32(smp);
        tid = threadIdx.x; lid = tid & 31;
        int wid = tid >> 5;
        wm = wid >> 2; wn = wid & 3;
        m0 = bm * 128; n0 = bn * 128;
#pragma unroll
        for (int i = 0; i < 4; i++)
#pragma unroll
            for (int j = 0; j < 4; j++)
#pragma unroll
                for (int q = 0; q < 4; q++) acc[i][j][q] = 0.f;
    }
    __device__ __forceinline__ void stage(int buf, const bf16* Ahi, const bf16* Alo,
                                          const bf16* Whi, const bf16* Wlo,
                                          int M, int Ncols, int K, int kb) {
        uint32_t base = sb + (uint32_t)buf * STG;
#pragma unroll
        for (int i = 0; i < 2; i++) {
            int c = tid + i * 256;
            int row = c >> 2, gr = c & 3;
            bool ok = (m0 + row) < M;
            size_t go = (size_t)(ok ? m0 + row : 0) * K + kb + gr * 8;
            uint32_t d = base + (uint32_t)row * 80 + (uint32_t)gr * 16;
            cp16(d + AHI_O, Ahi + go, ok ? 16 : 0);
            cp16(d + ALO_O, Alo + go, ok ? 16 : 0);
        }
#pragma unroll
        for (int i = 0; i < 2; i++) {
            int c = tid + i * 256;
            int k = c >> 4, gr = c & 15;
            size_t go = (size_t)(kb + k) * Ncols + n0 + gr * 8;
            uint32_t d = base + (uint32_t)k * 272 + (uint32_t)gr * 16;
            cp16(d + BHI_O, Whi + go, 16);
            cp16(d + BLO_O, Wlo + go, 16);
        }
        CP_COMMIT();
    }
    __device__ __forceinline__ void compute(int buf) {
        uint32_t base = sb + (uint32_t)buf * STG;
#pragma unroll
        for (int ks = 0; ks < 32; ks += 16) {
            uint32_t bhi[4][2], blo[4][2];
            const uint32_t brow = (uint32_t)(ks + (lid & 15)) * 272 + (uint32_t)((lid >> 4) * 16);
#pragma unroll
            for (int p = 0; p < 2; p++) {
                uint32_t baddr = base + brow + (uint32_t)(wn * 32 + p * 16) * 2;
                uint32_t r[4];
                ldsm4t(r, baddr + BHI_O);
                bhi[2 * p][0] = r[0]; bhi[2 * p][1] = r[1];
                bhi[2 * p + 1][0] = r[2]; bhi[2 * p + 1][1] = r[3];
                ldsm4t(r, baddr + BLO_O);
                blo[2 * p][0] = r[0]; blo[2 * p][1] = r[1];
                blo[2 * p + 1][0] = r[2]; blo[2 * p + 1][1] = r[3];
            }
            const uint32_t arow = (uint32_t)(wm * 64 + (lid & 15)) * 80
                                + (uint32_t)ks * 2 + (uint32_t)(lid >> 4) * 16;
#pragma unroll
            for (int mt = 0; mt < 4; mt++) {
                uint32_t aaddr = base + arow + (uint32_t)mt * (16 * 80);
                uint32_t ahi4[4], alo4[4];
                ldsm4(ahi4, aaddr + AHI_O);
                ldsm4(alo4, aaddr + ALO_O);
#pragma unroll
                for (int nt = 0; nt < 4; nt++) {
                    mma16816(acc[mt][nt], ahi4, bhi[nt]);
                    mma16816(acc[mt][nt], ahi4, blo[nt]);
                    mma16816(acc[mt][nt], alo4, bhi[nt]);
                }
            }
        }
    }
    __device__ __forceinline__ void run(const bf16* Ahi, const bf16* Alo,
                                        const bf16* Whi, const bf16* Wlo,
                                        int M, int Ncols, int K) {
        const int nch = K >> 5;
        stage(0, Ahi, Alo, Whi, Wlo, M, Ncols, K, 0);
        if (nch > 1) stage(1, Ahi, Alo, Whi, Wlo, M, Ncols, K, 32);
        for (int i = 0; i < nch; i++) {
            if (i == nch - 1) { CP_WAIT0(); } else { CP_WAIT1(); }
            __syncthreads();
            compute(i & 1);
            if (i + 2 < nch) {
                __syncthreads();
                stage(i & 1, Ahi, Alo, Whi, Wlo, M, Ncols, K, (i + 2) * 32);
            }
        }
    }
};

// ---------------- fp16 GEMM core: single A, hi/lo W, 2 products ------------
#define HSTG   27648u
#define HA_O   0u
#define HBHI_O 10240u
#define HBLO_O 18944u
#define SMH_GEMM 55296
#define SMH_EDGE 67584

struct GemmCoreH {
    uint32_t sb;
    int tid, lid, wm, wn, m0, n0;
    float acc[4][4][4];

    __device__ __forceinline__ void init(uint8_t* smp, int bm, int bn) {
        sb = smem_u32(smp);
        tid = threadIdx.x; lid = tid & 31;
        int wid = tid >> 5;
        wm = wid >> 2; wn = wid & 3;
        m0 = bm * 128; n0 = bn * 128;
#pragma unroll
        for (int i = 0; i < 4; i++)
#pragma unroll
            for (int j = 0; j < 4; j++)
#pragma unroll
                for (int q = 0; q < 4; q++) acc[i][j][q] = 0.f;
    }
    __device__ __forceinline__ void stage(int buf, const __half* A,
                                          const __half* Whi, const __half* Wlo,
                                          int M, int Ncols, int K, int kb) {
        uint32_t base = sb + (uint32_t)buf * HSTG;
#pragma unroll
        for (int i = 0; i < 2; i++) {
            int c = tid + i * 256;
            int row = c >> 2, gr = c & 3;
            bool ok = (m0 + row) < M;
            size_t go = (size_t)(ok ? m0 + row : 0) * K + kb + gr * 8;
            cp16(base + HA_O + (uint32_t)row * 80 + (uint32_t)gr * 16, A + go, ok ? 16 : 0);
        }
#pragma unroll
        for (int i = 0; i < 2; i++) {
            int c = tid + i * 256;
            int k = c >> 4, gr = c & 15;
            size_t go = (size_t)(kb + k) * Ncols + n0 + gr * 8;
            uint32_t d = base + (uint32_t)k * 272 + (uint32_t)gr * 16;
            cp16(d + HBHI_O, Whi + go, 16);
            cp16(d + HBLO_O, Wlo + go, 16);
        }
        CP_COMMIT();
    }
    __device__ __forceinline__ void compute(int buf) {
        uint32_t base = sb + (uint32_t)buf * HSTG;
#pragma unroll
        for (int ks = 0; ks < 32; ks += 16) {
            uint32_t bhi[4][2], blo[4][2];
            const uint32_t brow = (uint32_t)(ks + (lid & 15)) * 272 + (uint32_t)((lid >> 4) * 16);
#pragma unroll
            for (int p = 0; p < 2; p++) {
                uint32_t baddr = base + brow + (uint32_t)(wn * 32 + p * 16) * 2;
                uint32_t r[4];
                ldsm4t(r, baddr + HBHI_O);
                bhi[2 * p][0] = r[0]; bhi[2 * p][1] = r[1];
                bhi[2 * p + 1][0] = r[2]; bhi[2 * p + 1][1] = r[3];
                ldsm4t(r, baddr + HBLO_O);
                blo[2 * p][0] = r[0]; blo[2 * p][1] = r[1];
                blo[2 * p + 1][0] = r[2]; blo[2 * p + 1][1] = r[3];
            }
            const uint32_t arow = (uint32_t)(wm * 64 + (lid & 15)) * 80
                                + (uint32_t)ks * 2 + (uint32_t)(lid >> 4) * 16;
#pragma unroll
            for (int mt = 0; mt < 4; mt++) {
                uint32_t a4[4];
                ldsm4(a4, base + HA_O + arow + (uint32_t)mt * (16 * 80));
#pragma unroll
                for (int nt = 0; nt < 4; nt++) {
                    mma16816h(acc[mt][nt], a4, bhi[nt]);
                    mma16816h(acc[mt][nt], a4, blo[nt]);
                }
            }
        }
    }
    __device__ __forceinline__ void run(const __half* A, const __half* Whi, const __half* Wlo,
                                        int M, int Ncols, int K) {
        const int nch = K >> 5;
        stage(0, A, Whi, Wlo, M, Ncols, K, 0);
        if (nch > 1) stage(1, A, Whi, Wlo, M, Ncols, K, 32);
        for (int i = 0; i < nch; i++) {
            if (i == nch - 1) { CP_WAIT0(); } else { CP_WAIT1(); }
            __syncthreads();
            compute(i & 1);
            if (i + 2 < nch) {
                __syncthreads();
                stage(i & 1, A, Whi, Wlo, M, Ncols, K, (i + 2) * 32);
            }
        }
    }
};

// ---------------- generic fp16 GEMM (node h-path) ----------------
// RESMODE 0=none 1=f32 2=fp16pair; OUTMODE 0=f32 1=fp16 single; STATS col sums
template <int RESMODE, int OUTMODE, bool RELU, bool STATS>
__global__ void __launch_bounds__(256, 2)
mma_gemmH(const __half* __restrict__ A,
          const __half* __restrict__ Whi, const __half* __restrict__ Wlo,
          const float* __restrict__ bias, const float* __restrict__ resf,
          const __half* __restrict__ reshi, const __half* __restrict__ reslo,
          float* __restrict__ Cf, __half* __restrict__ Ch,
          float* __restrict__ stats, int M, int Ncols, int K)
{
    extern __shared__ __align__(16) uint8_t sm[];
    GemmCoreH g;
    g.init(sm, blockIdx.y, blockIdx.x);
    g.run(A, Whi, Wlo, M, Ncols, K);

    float ts0[4], ts1[4], tq0[4], tq1[4];
    if (STATS) {
#pragma unroll
        for (int nt = 0; nt < 4; nt++) { ts0[nt] = ts1[nt] = tq0[nt] = tq1[nt] = 0.f; }
    }

    const int qr = g.lid >> 2, qc = (g.lid & 3) * 2;
#pragma unroll
    for (int mt = 0; mt < 4; mt++) {
#pragma unroll
        for (int nt = 0; nt < 4; nt++) {
            int col = g.n0 + g.wn * 32 + nt * 8 + qc;
            float b0 = bias[col], b1 = bias[col + 1];
#pragma unroll
            for (int half = 0; half < 2; half++) {
                int row = g.m0 + g.wm * 64 + mt * 16 + qr + half * 8;
                if (row >= M) continue;
                float o0 = g.acc[mt][nt][half * 2 + 0] + b0;
                float o1 = g.acc[mt][nt][half * 2 + 1] + b1;
                size_t off = (size_t)row * Ncols + col;
                if (RESMODE == 1) {
                    float2 rr = *(const float2*)(resf + off);
                    o0 += rr.x; o1 += rr.y;
                } else if (RESMODE == 2) {
                    float2 rh = up2h(*(const uint32_t*)(reshi + off));
                    float2 rl = up2h(*(const uint32_t*)(reslo + off));
                    o0 += rh.x + rl.x; o1 += rh.y + rl.y;
                }
                if (RELU) { o0 = fmaxf(o0, 0.f); o1 = fmaxf(o1, 0.f); }
                if (STATS) {
                    ts0[nt] += o0; ts1[nt] += o1;
                    tq0[nt] = fmaf(o0, o0, tq0[nt]); tq1[nt] = fmaf(o1, o1, tq1[nt]);
                }
                if (OUTMODE == 0) {
                    *(float2*)(Cf + off) = make_float2(o0, o1);
                } else {
                    *(uint32_t*)(Ch + off) = pack2h(__float2half_rn(o0), __float2half_rn(o1));
                }
            }
        }
    }
    if (STATS) {
#pragma unroll
        for (int nt = 0; nt < 4; nt++) {
            float a = ts0[nt], b = ts1[nt], c = tq0[nt], d = tq1[nt];
#pragma unroll
            for (int m = 4; m <= 16; m <<= 1) {
                a += __shfl_xor_sync(0xffffffff, a, m);
                b += __shfl_xor_sync(0xffffffff, b, m);
                c += __shfl_xor_sync(0xffffffff, c, m);
                d += __shfl_xor_sync(0xffffffff, d, m);
            }
            if (qr == 0) {
                int col = g.n0 + g.wn * 32 + nt * 8 + qc;
                redf(stats + col, a);
                redf(stats + col + 1, b);
                redf(stats + DIM + col, c);
                redf(stats + DIM + col + 1, d);
            }
        }
    }
}

// ---------------- fused QKV (bf16-pair; blockIdx.x selects weight) ----------
__global__ void __launch_bounds__(256, 2)
qkv_gemm(const bf16* __restrict__ xhi, const bf16* __restrict__ xlo,
         const bf16* __restrict__ qh, const bf16* __restrict__ ql,
         const bf16* __restrict__ kh, const bf16* __restrict__ kl,
         const bf16* __restrict__ vh, const bf16* __restrict__ vl,
         const float* __restrict__ bq, const float* __restrict__ bk,
         const float* __restrict__ bv,
         float* __restrict__ Qo, float* __restrict__ Ko, float* __restrict__ Vo)
{
    extern __shared__ __align__(16) uint8_t sm[];
    const bf16* Whi = qh; const bf16* Wlo = ql;
    const float* bias = bq; float* C = Qo;
    if (blockIdx.x == 1) { Whi = kh; Wlo = kl; bias = bk; C = Ko; }
    else if (blockIdx.x == 2) { Whi = vh; Wlo = vl; bias = bv; C = Vo; }

    GemmCoreB g;
    g.init(sm, blockIdx.y, 0);
    g.run(xhi, xlo, Whi, Wlo, NN, 128, 128);

    const int qr = g.lid >> 2, qc = (g.lid & 3) * 2;
#pragma unroll
    for (int mt = 0; mt < 4; mt++) {
#pragma unroll
        for (int nt = 0; nt < 4; nt++) {
            int col = g.wn * 32 + nt * 8 + qc;
            float b0 = bias[col], b1 = bias[col + 1];
#pragma unroll
            for (int half = 0; half < 2; half++) {
                int row = g.m0 + g.wm * 64 + mt * 16 + qr + half * 8;
                if (row >= NN) continue;
                *(float2*)(C + (size_t)row * 128 + col) =
                    make_float2(g.acc[mt][nt][half * 2 + 0] + b0,
                                g.acc[mt][nt][half * 2 + 1] + b1);
            }
        }
    }
}

// ---------------- fused Ee GEMM (fp16) + edge score/logit/exp ----------------
union U16 { float4 q[4]; float f[16]; };

__global__ void __launch_bounds__(256, 2)
edge_gemm_fused(const __half* __restrict__ ea16,
                const __half* __restrict__ weh, const __half* __restrict__ wel,
                const float* __restrict__ bias,
                const int* __restrict__ ei, const float* __restrict__ Aw,
                const float* __restrict__ Qh, const float* __restrict__ Kh,
                __half* __restrict__ et16, float* __restrict__ lg)
{
    extern __shared__ __align__(16) uint8_t sm[];
    __shared__ float sAw[DIM];
    if (threadIdx.x < DIM) sAw[threadIdx.x] = Aw[threadIdx.x];

    GemmCoreH g;
    g.init(sm, blockIdx.y, blockIdx.x);
    g.run(ea16, weh, wel, NE, 256, 128);

    __syncthreads();
    float* sC = (float*)sm;
    const int qr = g.lid >> 2, qc = (g.lid & 3) * 2;
#pragma unroll
    for (int mt = 0; mt < 4; mt++) {
#pragma unroll
        for (int nt = 0; nt < 4; nt++) {
            int col = g.wn * 32 + nt * 8 + qc;
            float b0 = bias[g.n0 + col], b1 = bias[g.n0 + col + 1];
#pragma unroll
            for (int half = 0; half < 2; half++) {
                int row = g.wm * 64 + mt * 16 + qr + half * 8;
                *(float2*)(sC + row * 132 + col) =
                    make_float2(g.acc[mt][nt][half * 2 + 0] + b0,
                                g.acc[mt][nt][half * 2 + 1] + b1);
            }
        }
    }
    __syncthreads();

    const int e = threadIdx.x & 127;
    const int ge = g.m0 + e;                    // NE % 128 == 0
    const int src = ei[ge], dst = ei[NE + ge];
#pragma unroll
    for (int u = 0; u < 2; u++) {
        const int hl = (threadIdx.x >> 7) * 2 + u;
        const int h = blockIdx.x * 4 + hl;
        const float* ew = sC + e * 132 + hl * 32;
        U16 K4, Q4, EW, EB, ET;
        const float4* kp = (const float4*)(Kh + (size_t)src * DIM + h * DH);
        const float4* qp = (const float4*)(Qh + (size_t)dst * DIM + h * DH);
#pragma unroll
        for (int q = 0; q < 4; q++) {
            K4.q[q] = kp[q]; Q4.q[q] = qp[q];
            EW.q[q] = *(const float4*)(ew + q * 4);
            EB.q[q] = *(const float4*)(ew + 16 + q * 4);
        }
        float logit = 0.f;
#pragma unroll
        for (int d = 0; d < 16; d++) {
            float s = (K4.f[d] + Q4.f[d]) * EW.f[d];
            float a = fabsf(s);
            float r = (a > 0.f) ? copysignf(sqrtf(a), s) : 0.f;
            float v = fmaxf(r + EB.f[d], 0.f);
            ET.f[d] = v;
            logit = fmaf(v, sAw[d * NH + h], logit);
        }
        logit = fminf(fmaxf(logit, -5.f), 5.f);
        uint32_t hw[8];
#pragma unroll
        for (int q = 0; q < 8; q++)
            hw[q] = pack2h(__float2half_rn(ET.f[2 * q]), __float2half_rn(ET.f[2 * q + 1]));
        __half* pe = et16 + (size_t)ge * DIM + h * DH;
        *(uint4*)pe       = make_uint4(hw[0], hw[1], hw[2], hw[3]);
        *((uint4*)pe + 1) = make_uint4(hw[4], hw[5], hw[6], hw[7]);
        lg[ge * NH + h] = expf(logit);
    }
}

// ---------------- WOe GEMM (fp16 core) + residual + fused BN stats ----------
__global__ void __launch_bounds__(256, 2)
woe_gemm(const __half* __restrict__ et16,
         const __half* __restrict__ weh, const __half* __restrict__ wel,
         const float* __restrict__ bias, const float* __restrict__ resf,
         float* __restrict__ Cf, float* __restrict__ stats)
{
    extern __shared__ __align__(16) uint8_t sm[];
    GemmCoreH g;
    g.init(sm, blockIdx.y, 0);
    g.run(et16, weh, wel, NE, 128, 128);

    float ts0[4], ts1[4], tq0[4], tq1[4];
#pragma unroll
    for (int nt = 0; nt < 4; nt++) { ts0[nt] = ts1[nt] = tq0[nt] = tq1[nt] = 0.f; }

    const int qr = g.lid >> 2, qc = (g.lid & 3) * 2;
#pragma unroll
    for (int mt = 0; mt < 4; mt++) {
#pragma unroll
        for (int nt = 0; nt < 4; nt++) {
            int col = g.wn * 32 + nt * 8 + qc;
            float b0 = bias[col], b1 = bias[col + 1];
#pragma unroll
            for (int half = 0; half < 2; half++) {
                int row = g.m0 + g.wm * 64 + mt * 16 + qr + half * 8;
                float o0 = g.acc[mt][nt][half * 2 + 0] + b0;
                float o1 = g.acc[mt][nt][half * 2 + 1] + b1;
                size_t off = (size_t)row * 128 + col;
                float2 rr = *(const float2*)(resf + off);
                o0 += rr.x; o1 += rr.y;
                ts0[nt] += o0; ts1[nt] += o1;
                tq0[nt] = fmaf(o0, o0, tq0[nt]); tq1[nt] = fmaf(o1, o1, tq1[nt]);
                *(float2*)(Cf + off) = make_float2(o0, o1);
            }
        }
    }
#pragma unroll
    for (int nt = 0; nt < 4; nt++) {
        float a = ts0[nt], b = ts1[nt], c = tq0[nt], d = tq1[nt];
#pragma unroll
        for (int m = 4; m <= 16; m <<= 1) {
            a += __shfl_xor_sync(0xffffffff, a, m);
            b += __shfl_xor_sync(0xffffffff, b, m);
            c += __shfl_xor_sync(0xffffffff, c, m);
            d += __shfl_xor_sync(0xffffffff, d, m);
        }
        if (qr == 0) {
            int col = g.wn * 32 + nt * 8 + qc;
            redf(stats + col, a);
            redf(stats + col + 1, b);
            redf(stats + DIM + col, c);
            redf(stats + DIM + col + 1, d);
        }
    }
}

// ---------------- misc / edge / node / bn kernels ----------------
__global__ void preconv(const float* __restrict__ in, bf16* __restrict__ hi,
                        bf16* __restrict__ lo, long long n)
{
    long long i = ((long long)blockIdx.x * blockDim.x + threadIdx.x) * 4;
    if (i >= n) return;
    float4 v = *(const float4*)(in + i);
    uint2 h, l;
    split4(v, h, l);
    *(uint2*)(hi + i) = h;
    *(uint2*)(lo + i) = l;
}

__global__ void preconv_h(const float* __restrict__ in, __half* __restrict__ out, long long n)
{
    long long i = ((long long)blockIdx.x * blockDim.x + threadIdx.x) * 4;
    if (i >= n) return;
    float4 v = *(const float4*)(in + i);
    uint2 o;
    o.x = pack2h(__float2half_rn(v.x), __float2half_rn(v.y));
    o.y = pack2h(__float2half_rn(v.z), __float2half_rn(v.w));
    *(uint2*)(out + i) = o;
}

__global__ void preconv_hpair(const float* __restrict__ in, __half* __restrict__ hi,
                              __half* __restrict__ lo, long long n)
{
    long long i = ((long long)blockIdx.x * blockDim.x + threadIdx.x) * 4;
    if (i >= n) return;
    float4 v = *(const float4*)(in + i);
    float vv[4] = {v.x, v.y, v.z, v.w};
    __half hh[4], ll[4];
#pragma unroll
    for (int q = 0; q < 4; q++) {
        hh[q] = __float2half_rn(vv[q]);
        ll[q] = __float2half_rn(vv[q] - __half2float(hh[q]));
    }
    *(uint2*)(hi + i) = make_uint2(pack2h(hh[0], hh[1]), pack2h(hh[2], hh[3]));
    *(uint2*)(lo + i) = make_uint2(pack2h(ll[0], ll[1]), pack2h(ll[2], ll[3]));
}

// denominator + unnormalized scatter; lg holds ex; et single fp16.
__global__ void edge_scatter(const int* __restrict__ ei, const float* __restrict__ lg,
                             float* __restrict__ den, const float* __restrict__ Vh,
                             const __half* __restrict__ et16,
                             float* __restrict__ wV, float* __restrict__ rowV)
{
    int t = blockIdx.x * blockDim.x + threadIdx.x;
    if (t >= NE * NH) return;
    int e = t >> 3, h = t & 7;
    int src = ei[e], dst = ei[NE + e];
    float ex = lg[t];
    redf(&den[dst * NH + h], ex);
    U16 V4, E4;
    const float4* vp = (const float4*)(Vh + (size_t)src * DIM + h * DH);
#pragma unroll
    for (int q = 0; q < 4; q++) V4.q[q] = vp[q];
    const uint4* pe = (const uint4*)(et16 + (size_t)e * DIM + h * DH);
#pragma unroll
    for (int half = 0; half < 2; half++) {
        uint4 E = pe[half];
        uint32_t ew[4] = {E.x, E.y, E.z, E.w};
#pragma unroll
        for (int q = 0; q < 4; q++) {
            float2 f = up2h(ew[q]);
            E4.f[half * 8 + q * 2 + 0] = f.x;
            E4.f[half * 8 + q * 2 + 1] = f.y;
        }
    }
    float* wv = wV + (size_t)dst * DIM + h * DH;
    float* rv = rowV + (size_t)dst * DIM + h * DH;
#pragma unroll
    for (int q = 0; q < 4; q++) {
        red4(wv + q * 4, V4.q[q].x * ex, V4.q[q].y * ex, V4.q[q].z * ex, V4.q[q].w * ex);
        red4(rv + q * 4, E4.f[q * 4] * ex, E4.f[q * 4 + 1] * ex,
             E4.f[q * 4 + 2] * ex, E4.f[q * 4 + 3] * ex);
    }
}

__global__ void node_fix(const float* __restrict__ wV, const float* __restrict__ rowV,
                         const float* __restrict__ den,
                         const float* __restrict__ VeRow, const float* __restrict__ log_deg,
                         const float* __restrict__ deg_coef, __half* __restrict__ hatt16)
{
    int t = blockIdx.x * blockDim.x + threadIdx.x;
    if (t >= NN * 64) return;
    int n = t >> 6, c0 = (t & 63) * 2, h = c0 >> 4, co = c0 & 15;
    size_t off = (size_t)n * DIM + c0;
    float inv = 1.f / (den[n * NH + h] + 1e-16f);
    float a0 = wV[off], a1 = wV[off + 1];
    const float* rv = rowV + (size_t)n * DIM + h * DH;
#pragma unroll
    for (int d2 = 0; d2 < 16; d2++) {
        float r = rv[d2];
        a0 = fmaf(r, VeRow[d2 * DIM + h * DH + co], a0);
        a1 = fmaf(r, VeRow[d2 * DIM + h * DH + co + 1], a1);
    }
    a0 *= inv; a1 *= inv;
    float ld = log_deg[n];
    float o0 = a0 * (deg_coef[2 * c0] + ld * deg_coef[2 * c0 + 1]);
    float o1 = a1 * (deg_coef[2 * c0 + 2] + ld * deg_coef[2 * c0 + 3]);
    *(uint32_t*)(hatt16 + off) = pack2h(__float2half_rn(o0), __float2half_rn(o1));
}

// OUTM 0 = fp32, 1 = fp16 hi/lo pair
template <int OUTM>
__global__ void bn_apply(const float* __restrict__ v, float* __restrict__ outf,
                         __half* __restrict__ outhi, __half* __restrict__ outlo, int M,
                         const float* __restrict__ sums,
                         const float* __restrict__ g, const float* __restrict__ b, float invM)
{
    long long i = ((long long)blockIdx.x * blockDim.x + threadIdx.x) * 2;
    if (i >= (long long)M * DIM) return;
    int c = (int)(i & (DIM - 1));
    float m0 = sums[c] * invM, m1 = sums[c + 1] * invM;
    float var0 = fmaf(-m0, m0, sums[DIM + c] * invM);
    float var1 = fmaf(-m1, m1, sums[DIM + c + 1] * invM);
    float2 vv = *(const float2*)(v + i);
    float o0 = (vv.x - m0) * rsqrtf(var0 + 1e-5f) * g[c] + b[c];
    float o1 = (vv.y - m1) * rsqrtf(var1 + 1e-5f) * g[c + 1] + b[c + 1];
    if (OUTM == 0) {
        *(float2*)(outf + i) = make_float2(o0, o1);
    } else {
        uint32_t lw, hw = packsplith(o0, o1, lw);
        *(uint32_t*)(outhi + i) = hw;
        *(uint32_t*)(outlo + i) = lw;
    }
}

// ---------------- launch ----------------
#define SYM(var, sym) cudaGetSymbolAddress((void**)&var, sym)

extern "C" void kernel_launch(void* const* d_in, const int* in_sizes, int n_in,
                              void* d_out, int out_size)
{
    const float* x         = (const float*)d_in[0];
    const float* edge_attr = (const float*)d_in[1];
    const int*   ei        = (const int*)d_in[2];
    const float* log_deg   = (const float*)d_in[3];
    const float* Wq = (const float*)d_in[4],  *bq  = (const float*)d_in[5];
    const float* Wk = (const float*)d_in[6],  *bk  = (const float*)d_in[7];
    const float* We = (const float*)d_in[8],  *be  = (const float*)d_in[9];
    const float* Wv = (const float*)d_in[10], *bv  = (const float*)d_in[11];
    const float* Aw = (const float*)d_in[12], *VeRow = (const float*)d_in[13];
    const float* WOh = (const float*)d_in[14], *bOh = (const float*)d_in[15];
    const float* WOe = (const float*)d_in[16], *bOe = (const float*)d_in[17];
    const float* deg_coef = (const float*)d_in[18];
    const float* g1h = (const float*)d_in[19], *b1h = (const float*)d_in[20];
    const float* g1e = (const float*)d_in[21], *b1e = (const float*)d_in[22];
    const float* g2h = (const float*)d_in[23], *b2h = (const float*)d_in[24];
    const float* W1 = (const float*)d_in[25], *b1 = (const float*)d_in[26];
    const float* W2 = (const float*)d_in[27], *b2 = (const float*)d_in[28];

    float *Qh, *Kh, *Vh, *lg, *den, *wV, *rowV, *v1, *v2, *s1, *s2buf, *se;
    SYM(Qh, g_Qh); SYM(Kh, g_Kh); SYM(Vh, g_Vh);
    SYM(lg, g_lg); SYM(den, g_den);
    SYM(wV, g_wV); SYM(rowV, g_rowV);
    SYM(v1, g_v1); SYM(v2, g_v2);
    SYM(s1, g_s1); SYM(s2buf, g_s2); SYM(se, g_se);
    __half *ea16, *et16, *we16h, *we16l, *woe16h, *woe16l;
    SYM(ea16, g_ea16); SYM(et16, g_et16);
    SYM(we16h, g_we16h); SYM(we16l, g_we16l);
    SYM(woe16h, g_woe16h); SYM(woe16l, g_woe16l);
    __half *hatt16, *hbn16h, *hbn16l, *h2a16, *woh16h, *woh16l, *w116h, *w116l, *w216h, *w216l;
    SYM(hatt16, g_hatt16); SYM(hbn16h, g_hbn16h); SYM(hbn16l, g_hbn16l);
    SYM(h2a16, g_h2a16);
    SYM(woh16h, g_woh16h); SYM(woh16l, g_woh16l);
    SYM(w116h, g_w116h); SYM(w116l, g_w116l);
    SYM(w216h, g_w216h); SYM(w216l, g_w216l);
    bf16 *xhi, *xlo, *wq_h, *wq_l, *wk_h, *wk_l, *wv_h, *wv_l;
    SYM(xhi, g_xhi); SYM(xlo, g_xlo);
    SYM(wq_h, g_wq_h); SYM(wq_l, g_wq_l); SYM(wk_h, g_wk_h); SYM(wk_l, g_wk_l);
    SYM(wv_h, g_wv_h); SYM(wv_l, g_wv_l);

    float* hout = (float*)d_out;
    float* eout = (float*)d_out + (size_t)NN * DIM;

    cudaFuncSetAttribute(qkv_gemm, cudaFuncAttributeMaxDynamicSharedMemorySize, SMB_TOTAL);
    cudaFuncSetAttribute(edge_gemm_fused, cudaFuncAttributeMaxDynamicSharedMemorySize, SMH_EDGE);
    cudaFuncSetAttribute(woe_gemm, cudaFuncAttributeMaxDynamicSharedMemorySize, SMH_GEMM);
    cudaFuncSetAttribute(mma_gemmH<1, 0, false, true >, cudaFuncAttributeMaxDynamicSharedMemorySize, SMH_GEMM);
    cudaFuncSetAttribute(mma_gemmH<0, 1, true,  false>, cudaFuncAttributeMaxDynamicSharedMemorySize, SMH_GEMM);
    cudaFuncSetAttribute(mma_gemmH<2, 0, false, true >, cudaFuncAttributeMaxDynamicSharedMemorySize, SMH_GEMM);

    // lazily-created side stream + events
    static cudaStream_t sside = nullptr;
    static cudaEvent_t ev0 = nullptr, evA = nullptr, ev1 = nullptr, ev2 = nullptr;
    if (!sside) {
        cudaStreamCreateWithFlags(&sside, cudaStreamNonBlocking);
        cudaEventCreateWithFlags(&ev0, cudaEventDisableTiming);
        cudaEventCreateWithFlags(&evA, cudaEventDisableTiming);
        cudaEventCreateWithFlags(&ev1, cudaEventDisableTiming);
        cudaEventCreateWithFlags(&ev2, cudaEventDisableTiming);
    }

    // fork side stream; big edge_attr fp16 preconv there
    cudaEventRecord(ev0, 0);
    cudaStreamWaitEvent(sside, ev0, 0);
    preconv_h<<<cdiv((long long)NE * DIM / 4, 256), 256, 0, sside>>>(edge_attr, ea16, (long long)NE * DIM);
    cudaEventRecord(evA, sside);

    // main: small preconvs + memsets + QKV
    preconv<<<cdiv((long long)NN * DIM / 4, 256), 256>>>(x, xhi, xlo, (long long)NN * DIM);
    preconv<<<cdiv(DIM * DIM / 4, 256), 256>>>(Wq, wq_h, wq_l, DIM * DIM);
    preconv<<<cdiv(DIM * DIM / 4, 256), 256>>>(Wk, wk_h, wk_l, DIM * DIM);
    preconv<<<cdiv(DIM * DIM / 4, 256), 256>>>(Wv, wv_h, wv_l, DIM * DIM);
    preconv_hpair<<<cdiv(DIM * 2 * DIM / 4, 256), 256>>>(We, we16h, we16l, DIM * 2 * DIM);
    preconv_hpair<<<cdiv(DIM * DIM / 4, 256), 256>>>(WOe, woe16h, woe16l, DIM * DIM);
    preconv_hpair<<<cdiv(DIM * DIM / 4, 256), 256>>>(WOh, woh16h, woh16l, DIM * DIM);
    preconv_hpair<<<cdiv(DIM * 2 * DIM / 4, 256), 256>>>(W1, w116h, w116l, DIM * 2 * DIM);
    preconv_hpair<<<cdiv(2 * DIM * DIM / 4, 256), 256>>>(W2, w216h, w216l, 2 * DIM * DIM);

    cudaMemsetAsync(wV, 0, (size_t)NN * DIM * sizeof(float));
    cudaMemsetAsync(rowV, 0, (size_t)NN * DIM * sizeof(float));
    cudaMemsetAsync(den, 0, (size_t)NN * NH * sizeof(float));
    cudaMemsetAsync(s1, 0, 2 * DIM * sizeof(float));
    cudaMemsetAsync(s2buf, 0, 2 * DIM * sizeof(float));
    cudaMemsetAsync(se, 0, 2 * DIM * sizeof(float));

    const int gN = cdiv(NN, 128), gE = cdiv(NE, 128);

    qkv_gemm<<<dim3(3, gN), 256, SMB_TOTAL>>>(xhi, xlo, wq_h, wq_l, wk_h, wk_l,
                                              wv_h, wv_l, bq, bk, bv, Qh, Kh, Vh);

    cudaStreamWaitEvent(0, evA, 0);
    edge_gemm_fused<<<dim3(2, gE), 256, SMH_EDGE>>>(ea16, we16h, we16l, be,
                                                    ei, Aw, Qh, Kh, et16, lg);
    cudaEventRecord(ev1, 0);

    // side stream: e-path (WOe fp16 + stats, BN apply into eout)
    cudaStreamWaitEvent(sside, ev1, 0);
    woe_gemm<<<dim3(1, gE), 256, SMH_GEMM, sside>>>(et16, woe16h, woe16l, bOe, edge_attr, eout, se);
    bn_apply<0><<<cdiv((long long)NE * 64, 256), 256, 0, sside>>>(
        eout, eout, nullptr, nullptr, NE, se, g1e, b1e, 1.f / NE);
    cudaEventRecord(ev2, sside);

    // main stream: h-path (all fp16 single-A GEMMs)
    edge_scatter<<<cdiv(NE * NH, 256), 256>>>(ei, lg, den, Vh, et16, wV, rowV);
    node_fix<<<cdiv(NN * 64, 256), 256>>>(wV, rowV, den, VeRow, log_deg, deg_coef, hatt16);
    mma_gemmH<1, 0, false, true><<<dim3(1, gN), 256, SMH_GEMM>>>(
        hatt16, woh16h, woh16l, bOh, x, nullptr, nullptr, v1, nullptr, s1, NN, 128, 128);
    bn_apply<1><<<cdiv((long long)NN * 64, 256), 256>>>(v1, nullptr, hbn16h, hbn16l, NN, s1, g1h, b1h, 1.f / NN);
    mma_gemmH<0, 1, true, false><<<dim3(2, gN), 256, SMH_GEMM>>>(
        hbn16h, w116h, w116l, b1, nullptr, nullptr, nullptr, nullptr, h2a16, nullptr, NN, 256, 128);
    mma_gemmH<2, 0, false, true><<<dim3(1, gN), 256, SMH_GEMM>>>(
        h2a16, w216h, w216l, b2, nullptr, hbn16h, hbn16l, v2, nullptr, s2buf, NN, 128, 256);
    bn_apply<0><<<cdiv((long long)NN * 64, 256), 256>>>(v2, hout, nullptr, nullptr, NN, s2buf, g2h, b2h, 1.f / NN);

    // join side stream back into the captured main stream
    cudaStreamWaitEvent(0, ev2, 0);
}

// round 15
// speedup vs baseline: 1.2514x; 1.0480x over previous
#include <cuda_runtime.h>
#include <cuda_bf16.h>
#include <cuda_fp16.h>
#include <math.h>
#include <stdint.h>

#define NN 40000
#define NE 640000
#define DIM 128
#define NH 8
#define DH 16

typedef __nv_bfloat16 bf16;

// ---------------- scratch (device globals: allocation-free) ----------------
__device__ float g_Qh[(size_t)NN * DIM];
__device__ float g_Kh[(size_t)NN * DIM];
__device__ float g_Vh[(size_t)NN * DIM];
__device__ float g_lg[(size_t)NE * NH];
__device__ float g_den[(size_t)NN * NH];
__device__ float g_wV[(size_t)NN * DIM];
__device__ float g_rowV[(size_t)NN * DIM];
__device__ float g_v1[(size_t)NN * DIM];
__device__ float g_v2[(size_t)NN * DIM];
__device__ float g_s1[2 * DIM];
__device__ float g_s2[2 * DIM];
__device__ float g_se[2 * DIM];
// fp16 buffers
__device__ __half g_x16[(size_t)NN * DIM];
__device__ __half g_ea16[(size_t)NE * DIM];
__device__ __half g_et16[(size_t)NE * DIM];
__device__ __half g_we16h[DIM * 2 * DIM];
__device__ __half g_woe16h[DIM * DIM], g_woe16l[DIM * DIM];
__device__ __half g_hatt16[(size_t)NN * DIM];
__device__ __half g_hbn16h[(size_t)NN * DIM], g_hbn16l[(size_t)NN * DIM];
__device__ __half g_h2a16[(size_t)NN * 2 * DIM];
__device__ __half g_woh16h[DIM * DIM], g_woh16l[DIM * DIM];
__device__ __half g_w116h[DIM * 2 * DIM], g_w116l[DIM * 2 * DIM];
__device__ __half g_w216h[2 * DIM * DIM], g_w216l[2 * DIM * DIM];
__device__ __half g_wq16h[DIM * DIM], g_wq16l[DIM * DIM];
__device__ __half g_wk16h[DIM * DIM], g_wk16l[DIM * DIM];
__device__ __half g_wv16h[DIM * DIM], g_wv16l[DIM * DIM];

static inline int cdiv(long long a, long long b) { return (int)((a + b - 1) / b); }

// ---------------- helpers ----------------
__device__ __forceinline__ uint32_t smem_u32(const void* p) {
    uint32_t a;
    asm("{ .reg .u64 t; cvta.to.shared.u64 t, %1; cvt.u32.u64 %0, t; }" : "=r"(a) : "l"(p));
    return a;
}
__device__ __forceinline__ void ldsm4(uint32_t (&r)[4], uint32_t addr) {
    asm volatile("ldmatrix.sync.aligned.m8n8.x4.shared.b16 {%0,%1,%2,%3}, [%4];"
                 : "=r"(r[0]), "=r"(r[1]), "=r"(r[2]), "=r"(r[3]) : "r"(addr));
}
__device__ __forceinline__ void ldsm4t(uint32_t (&r)[4], uint32_t addr) {
    asm volatile("ldmatrix.sync.aligned.m8n8.x4.trans.shared.b16 {%0,%1,%2,%3}, [%4];"
                 : "=r"(r[0]), "=r"(r[1]), "=r"(r[2]), "=r"(r[3]) : "r"(addr));
}
__device__ __forceinline__ void mma16816h(float (&d)[4], const uint32_t (&a)[4], const uint32_t* b) {
    asm volatile("mma.sync.aligned.m16n8k16.row.col.f32.f16.f16.f32 "
                 "{%0,%1,%2,%3}, {%4,%5,%6,%7}, {%8,%9}, {%0,%1,%2,%3};"
                 : "+f"(d[0]), "+f"(d[1]), "+f"(d[2]), "+f"(d[3])
                 : "r"(a[0]), "r"(a[1]), "r"(a[2]), "r"(a[3]), "r"(b[0]), "r"(b[1]));
}
__device__ __forceinline__ uint32_t pack2h(__half a, __half b) {
    return (uint32_t)__half_as_ushort(a) | ((uint32_t)__half_as_ushort(b) << 16);
}
__device__ __forceinline__ float2 up2h(uint32_t u) {
    __half2 h = *(__half2*)&u;
    return __half22float2(h);
}
__device__ __forceinline__ uint32_t packsplith(float a, float b, uint32_t& lo) {
    __half h0 = __float2half_rn(a), h1 = __float2half_rn(b);
    lo = pack2h(__float2half_rn(a - __half2float(h0)),
                __float2half_rn(b - __half2float(h1)));
    return pack2h(h0, h1);
}
__device__ __forceinline__ void cp16(uint32_t dst, const void* src, int sz) {
    asm volatile("cp.async.cg.shared.global [%0], [%1], 16, %2;" :: "r"(dst), "l"(src), "r"(sz));
}
#define CP_COMMIT() asm volatile("cp.async.commit_group;" ::: "memory")
#define CP_WAIT0()  asm volatile("cp.async.wait_group 0;" ::: "memory")
#define CP_WAIT1()  asm volatile("cp.async.wait_group 1;" ::: "memory")

__device__ __forceinline__ void red4(float* p, float a, float b, float c, float d) {
    asm volatile("red.global.add.v4.f32 [%0], {%1,%2,%3,%4};"
                 :: "l"(p), "f"(a), "f"(b), "f"(c), "f"(d) : "memory");
}
__device__ __forceinline__ void redf(float* p, float a) {
    asm volatile("red.global.add.f32 [%0], %1;" :: "l"(p), "f"(a) : "memory");
}

// ---------------- fp16 GEMM core: single A; W hi (+ optional lo) -----------
#define HSTG   27648u
#define HA_O   0u
#define HBHI_O 10240u
#define HBLO_O 18944u
#define SMH_GEMM 55296
#define SMH_EDGE 67584

template <bool WPAIR>
struct GemmCoreH {
    uint32_t sb;
    int tid, lid, wm, wn, m0, n0;
    float acc[4][4][4];

    __device__ __forceinline__ void init(uint8_t* smp, int bm, int bn) {
        sb = smem_u32(smp);
        tid = threadIdx.x; lid = tid & 31;
        int wid = tid >> 5;
        wm = wid >> 2; wn = wid & 3;
        m0 = bm * 128; n0 = bn * 128;
#pragma unroll
        for (int i = 0; i < 4; i++)
#pragma unroll
            for (int j = 0; j < 4; j++)
#pragma unroll
                for (int q = 0; q < 4; q++) acc[i][j][q] = 0.f;
    }
    __device__ __forceinline__ void stage(int buf, const __half* A,
                                          const __half* Whi, const __half* Wlo,
                                          int M, int Ncols, int K, int kb) {
        uint32_t base = sb + (uint32_t)buf * HSTG;
#pragma unroll
        for (int i = 0; i < 2; i++) {
            int c = tid + i * 256;
            int row = c >> 2, gr = c & 3;
            bool ok = (m0 + row) < M;
            size_t go = (size_t)(ok ? m0 + row : 0) * K + kb + gr * 8;
            cp16(base + HA_O + (uint32_t)row * 80 + (uint32_t)gr * 16, A + go, ok ? 16 : 0);
        }
#pragma unroll
        for (int i = 0; i < 2; i++) {
            int c = tid + i * 256;
            int k = c >> 4, gr = c & 15;
            size_t go = (size_t)(kb + k) * Ncols + n0 + gr * 8;
            uint32_t d = base + (uint32_t)k * 272 + (uint32_t)gr * 16;
            cp16(d + HBHI_O, Whi + go, 16);
            if (WPAIR) cp16(d + HBLO_O, Wlo + go, 16);
        }
        CP_COMMIT();
    }
    __device__ __forceinline__ void compute(int buf) {
        uint32_t base = sb + (uint32_t)buf * HSTG;
#pragma unroll
        for (int ks = 0; ks < 32; ks += 16) {
            uint32_t bhi[4][2], blo[4][2];
            const uint32_t brow = (uint32_t)(ks + (lid & 15)) * 272 + (uint32_t)((lid >> 4) * 16);
#pragma unroll
            for (int p = 0; p < 2; p++) {
                uint32_t baddr = base + brow + (uint32_t)(wn * 32 + p * 16) * 2;
                uint32_t r[4];
                ldsm4t(r, baddr + HBHI_O);
                bhi[2 * p][0] = r[0]; bhi[2 * p][1] = r[1];
                bhi[2 * p + 1][0] = r[2]; bhi[2 * p + 1][1] = r[3];
                if (WPAIR) {
                    ldsm4t(r, baddr + HBLO_O);
                    blo[2 * p][0] = r[0]; blo[2 * p][1] = r[1];
                    blo[2 * p + 1][0] = r[2]; blo[2 * p + 1][1] = r[3];
                }
            }
            const uint32_t arow = (uint32_t)(wm * 64 + (lid & 15)) * 80
                                + (uint32_t)ks * 2 + (uint32_t)(lid >> 4) * 16;
#pragma unroll
            for (int mt = 0; mt < 4; mt++) {
                uint32_t a4[4];
                ldsm4(a4, base + HA_O + arow + (uint32_t)mt * (16 * 80));
#pragma unroll
                for (int nt = 0; nt < 4; nt++) {
                    mma16816h(acc[mt][nt], a4, bhi[nt]);
                    if (WPAIR) mma16816h(acc[mt][nt], a4, blo[nt]);
                }
            }
        }
    }
    __device__ __forceinline__ void run(const __half* A, const __half* Whi, const __half* Wlo,
                                        int M, int Ncols, int K) {
        const int nch = K >> 5;
        stage(0, A, Whi, Wlo, M, Ncols, K, 0);
        if (nch > 1) stage(1, A, Whi, Wlo, M, Ncols, K, 32);
        for (int i = 0; i < nch; i++) {
            if (i == nch - 1) { CP_WAIT0(); } else { CP_WAIT1(); }
            __syncthreads();
            compute(i & 1);
            if (i + 2 < nch) {
                __syncthreads();
                stage(i & 1, A, Whi, Wlo, M, Ncols, K, (i + 2) * 32);
            }
        }
    }
};

// ---------------- generic fp16 GEMM ----------------
// RESMODE 0=none 1=f32 2=fp16pair; OUTMODE 0=f32 1=fp16 single; STATS col sums
template <int RESMODE, int OUTMODE, bool RELU, bool STATS>
__global__ void __launch_bounds__(256, 2)
mma_gemmH(const __half* __restrict__ A,
          const __half* __restrict__ Whi, const __half* __restrict__ Wlo,
          const float* __restrict__ bias, const float* __restrict__ resf,
          const __half* __restrict__ reshi, const __half* __restrict__ reslo,
          float* __restrict__ Cf, __half* __restrict__ Ch,
          float* __restrict__ stats, int M, int Ncols, int K)
{
    extern __shared__ __align__(16) uint8_t sm[];
    GemmCoreH<true> g;
    g.init(sm, blockIdx.y, blockIdx.x);
    g.run(A, Whi, Wlo, M, Ncols, K);

    float ts0[4], ts1[4], tq0[4], tq1[4];
    if (STATS) {
#pragma unroll
        for (int nt = 0; nt < 4; nt++) { ts0[nt] = ts1[nt] = tq0[nt] = tq1[nt] = 0.f; }
    }

    const int qr = g.lid >> 2, qc = (g.lid & 3) * 2;
#pragma unroll
    for (int mt = 0; mt < 4; mt++) {
#pragma unroll
        for (int nt = 0; nt < 4; nt++) {
            int col = g.n0 + g.wn * 32 + nt * 8 + qc;
            float b0 = bias[col], b1 = bias[col + 1];
#pragma unroll
            for (int half = 0; half < 2; half++) {
                int row = g.m0 + g.wm * 64 + mt * 16 + qr + half * 8;
                if (row >= M) continue;
                float o0 = g.acc[mt][nt][half * 2 + 0] + b0;
                float o1 = g.acc[mt][nt][half * 2 + 1] + b1;
                size_t off = (size_t)row * Ncols + col;
                if (RESMODE == 1) {
                    float2 rr = *(const float2*)(resf + off);
                    o0 += rr.x; o1 += rr.y;
                } else if (RESMODE == 2) {
                    float2 rh = up2h(*(const uint32_t*)(reshi + off));
                    float2 rl = up2h(*(const uint32_t*)(reslo + off));
                    o0 += rh.x + rl.x; o1 += rh.y + rl.y;
                }
                if (RELU) { o0 = fmaxf(o0, 0.f); o1 = fmaxf(o1, 0.f); }
                if (STATS) {
                    ts0[nt] += o0; ts1[nt] += o1;
                    tq0[nt] = fmaf(o0, o0, tq0[nt]); tq1[nt] = fmaf(o1, o1, tq1[nt]);
                }
                if (OUTMODE == 0) {
                    *(float2*)(Cf + off) = make_float2(o0, o1);
                } else {
                    *(uint32_t*)(Ch + off) = pack2h(__float2half_rn(o0), __float2half_rn(o1));
                }
            }
        }
    }
    if (STATS) {
#pragma unroll
        for (int nt = 0; nt < 4; nt++) {
            float a = ts0[nt], b = ts1[nt], c = tq0[nt], d = tq1[nt];
#pragma unroll
            for (int m = 4; m <= 16; m <<= 1) {
                a += __shfl_xor_sync(0xffffffff, a, m);
                b += __shfl_xor_sync(0xffffffff, b, m);
                c += __shfl_xor_sync(0xffffffff, c, m);
                d += __shfl_xor_sync(0xffffffff, d, m);
            }
            if (qr == 0) {
                int col = g.n0 + g.wn * 32 + nt * 8 + qc;
                redf(stats + col, a);
                redf(stats + col + 1, b);
                redf(stats + DIM + col, c);
                redf(stats + DIM + col + 1, d);
            }
        }
    }
}

// ---------------- fused QKV (fp16 single-A, hi/lo W; blockIdx.x = weight) ---
__global__ void __launch_bounds__(256, 2)
qkv_gemm(const __half* __restrict__ x16,
         const __half* __restrict__ qh, const __half* __restrict__ ql,
         const __half* __restrict__ kh, const __half* __restrict__ kl,
         const __half* __restrict__ vh, const __half* __restrict__ vl,
         const float* __restrict__ bq, const float* __restrict__ bk,
         const float* __restrict__ bv,
         float* __restrict__ Qo, float* __restrict__ Ko, float* __restrict__ Vo)
{
    extern __shared__ __align__(16) uint8_t sm[];
    const __half* Whi = qh; const __half* Wlo = ql;
    const float* bias = bq; float* C = Qo;
    if (blockIdx.x == 1) { Whi = kh; Wlo = kl; bias = bk; C = Ko; }
    else if (blockIdx.x == 2) { Whi = vh; Wlo = vl; bias = bv; C = Vo; }

    GemmCoreH<true> g;
    g.init(sm, blockIdx.y, 0);
    g.run(x16, Whi, Wlo, NN, 128, 128);

    const int qr = g.lid >> 2, qc = (g.lid & 3) * 2;
#pragma unroll
    for (int mt = 0; mt < 4; mt++) {
#pragma unroll
        for (int nt = 0; nt < 4; nt++) {
            int col = g.wn * 32 + nt * 8 + qc;
            float b0 = bias[col], b1 = bias[col + 1];
#pragma unroll
            for (int half = 0; half < 2; half++) {
                int row = g.m0 + g.wm * 64 + mt * 16 + qr + half * 8;
                if (row >= NN) continue;
                *(float2*)(C + (size_t)row * 128 + col) =
                    make_float2(g.acc[mt][nt][half * 2 + 0] + b0,
                                g.acc[mt][nt][half * 2 + 1] + b1);
            }
        }
    }
}

// ---------------- fused Ee GEMM (pure fp16, 1 product) + edge epilogue ------
union U16 { float4 q[4]; float f[16]; };

__global__ void __launch_bounds__(256, 2)
edge_gemm_fused(const __half* __restrict__ ea16,
                const __half* __restrict__ weh,
                const float* __restrict__ bias,
                const int* __restrict__ ei, const float* __restrict__ Aw,
                const float* __restrict__ Qh, const float* __restrict__ Kh,
                __half* __restrict__ et16, float* __restrict__ lg)
{
    extern __shared__ __align__(16) uint8_t sm[];
    __shared__ float sAw[DIM];
    if (threadIdx.x < DIM) sAw[threadIdx.x] = Aw[threadIdx.x];

    GemmCoreH<false> g;
    g.init(sm, blockIdx.y, blockIdx.x);
    g.run(ea16, weh, nullptr, NE, 256, 128);

    __syncthreads();
    float* sC = (float*)sm;
    const int qr = g.lid >> 2, qc = (g.lid & 3) * 2;
#pragma unroll
    for (int mt = 0; mt < 4; mt++) {
#pragma unroll
        for (int nt = 0; nt < 4; nt++) {
            int col = g.wn * 32 + nt * 8 + qc;
            float b0 = bias[g.n0 + col], b1 = bias[g.n0 + col + 1];
#pragma unroll
            for (int half = 0; half < 2; half++) {
                int row = g.wm * 64 + mt * 16 + qr + half * 8;
                *(float2*)(sC + row * 132 + col) =
                    make_float2(g.acc[mt][nt][half * 2 + 0] + b0,
                                g.acc[mt][nt][half * 2 + 1] + b1);
            }
        }
    }
    __syncthreads();

    const int e = threadIdx.x & 127;
    const int ge = g.m0 + e;                    // NE % 128 == 0
    const int src = ei[ge], dst = ei[NE + ge];
#pragma unroll
    for (int u = 0; u < 2; u++) {
        const int hl = (threadIdx.x >> 7) * 2 + u;
        const int h = blockIdx.x * 4 + hl;
        const float* ew = sC + e * 132 + hl * 32;
        U16 K4, Q4, EW, EB, ET;
        const float4* kp = (const float4*)(Kh + (size_t)src * DIM + h * DH);
        const float4* qp = (const float4*)(Qh + (size_t)dst * DIM + h * DH);
#pragma unroll
        for (int q = 0; q < 4; q++) {
            K4.q[q] = kp[q]; Q4.q[q] = qp[q];
            EW.q[q] = *(const float4*)(ew + q * 4);
            EB.q[q] = *(const float4*)(ew + 16 + q * 4);
        }
        float logit = 0.f;
#pragma unroll
        for (int d = 0; d < 16; d++) {
            float s = (K4.f[d] + Q4.f[d]) * EW.f[d];
            float a = fabsf(s);
            float r = (a > 0.f) ? copysignf(sqrtf(a), s) : 0.f;
            float v = fmaxf(r + EB.f[d], 0.f);
            ET.f[d] = v;
            logit = fmaf(v, sAw[d * NH + h], logit);
        }
        logit = fminf(fmaxf(logit, -5.f), 5.f);
        uint32_t hw[8];
#pragma unroll
        for (int q = 0; q < 8; q++)
            hw[q] = pack2h(__float2half_rn(ET.f[2 * q]), __float2half_rn(ET.f[2 * q + 1]));
        __half* pe = et16 + (size_t)ge * DIM + h * DH;
        *(uint4*)pe       = make_uint4(hw[0], hw[1], hw[2], hw[3]);
        *((uint4*)pe + 1) = make_uint4(hw[4], hw[5], hw[6], hw[7]);
        lg[ge * NH + h] = expf(logit);
    }
}

// ---------------- WOe GEMM (fp16, hi/lo W) + residual + fused BN stats ------
__global__ void __launch_bounds__(256, 2)
woe_gemm(const __half* __restrict__ et16,
         const __half* __restrict__ weh, const __half* __restrict__ wel,
         const float* __restrict__ bias, const float* __restrict__ resf,
         float* __restrict__ Cf, float* __restrict__ stats)
{
    extern __shared__ __align__(16) uint8_t sm[];
    GemmCoreH<true> g;
    g.init(sm, blockIdx.y, 0);
    g.run(et16, weh, wel, NE, 128, 128);

    float ts0[4], ts1[4], tq0[4], tq1[4];
#pragma unroll
    for (int nt = 0; nt < 4; nt++) { ts0[nt] = ts1[nt] = tq0[nt] = tq1[nt] = 0.f; }

    const int qr = g.lid >> 2, qc = (g.lid & 3) * 2;
#pragma unroll
    for (int mt = 0; mt < 4; mt++) {
#pragma unroll
        for (int nt = 0; nt < 4; nt++) {
            int col = g.wn * 32 + nt * 8 + qc;
            float b0 = bias[col], b1 = bias[col + 1];
#pragma unroll
            for (int half = 0; half < 2; half++) {
                int row = g.m0 + g.wm * 64 + mt * 16 + qr + half * 8;
                float o0 = g.acc[mt][nt][half * 2 + 0] + b0;
                float o1 = g.acc[mt][nt][half * 2 + 1] + b1;
                size_t off = (size_t)row * 128 + col;
                float2 rr = *(const float2*)(resf + off);
                o0 += rr.x; o1 += rr.y;
                ts0[nt] += o0; ts1[nt] += o1;
                tq0[nt] = fmaf(o0, o0, tq0[nt]); tq1[nt] = fmaf(o1, o1, tq1[nt]);
                *(float2*)(Cf + off) = make_float2(o0, o1);
            }
        }
    }
#pragma unroll
    for (int nt = 0; nt < 4; nt++) {
        float a = ts0[nt], b = ts1[nt], c = tq0[nt], d = tq1[nt];
#pragma unroll
        for (int m = 4; m <= 16; m <<= 1) {
            a += __shfl_xor_sync(0xffffffff, a, m);
            b += __shfl_xor_sync(0xffffffff, b, m);
            c += __shfl_xor_sync(0xffffffff, c, m);
            d += __shfl_xor_sync(0xffffffff, d, m);
        }
        if (qr == 0) {
            int col = g.wn * 32 + nt * 8 + qc;
            redf(stats + col, a);
            redf(stats + col + 1, b);
            redf(stats + DIM + col, c);
            redf(stats + DIM + col + 1, d);
        }
    }
}

// ---------------- misc / edge / node / bn kernels ----------------
__global__ void preconv_h(const float* __restrict__ in, __half* __restrict__ out, long long n)
{
    long long i = ((long long)blockIdx.x * blockDim.x + threadIdx.x) * 4;
    if (i >= n) return;
    float4 v = *(const float4*)(in + i);
    uint2 o;
    o.x = pack2h(__float2half_rn(v.x), __float2half_rn(v.y));
    o.y = pack2h(__float2half_rn(v.z), __float2half_rn(v.w));
    *(uint2*)(out + i) = o;
}

__global__ void preconv_hpair(const float* __restrict__ in, __half* __restrict__ hi,
                              __half* __restrict__ lo, long long n)
{
    long long i = ((long long)blockIdx.x * blockDim.x + threadIdx.x) * 4;
    if (i >= n) return;
    float4 v = *(const float4*)(in + i);
    float vv[4] = {v.x, v.y, v.z, v.w};
    __half hh[4], ll[4];
#pragma unroll
    for (int q = 0; q < 4; q++) {
        hh[q] = __float2half_rn(vv[q]);
        ll[q] = __float2half_rn(vv[q] - __half2float(hh[q]));
    }
    *(uint2*)(hi + i) = make_uint2(pack2h(hh[0], hh[1]), pack2h(hh[2], hh[3]));
    *(uint2*)(lo + i) = make_uint2(pack2h(ll[0], ll[1]), pack2h(ll[2], ll[3]));
}

// denominator + unnormalized scatter; lg holds ex; et single fp16.
__global__ void edge_scatter(const int* __restrict__ ei, const float* __restrict__ lg,
                             float* __restrict__ den, const float* __restrict__ Vh,
                             const __half* __restrict__ et16,
                             float* __restrict__ wV, float* __restrict__ rowV)
{
    int t = blockIdx.x * blockDim.x + threadIdx.x;
    if (t >= NE * NH) return;
    int e = t >> 3, h = t & 7;
    int src = ei[e], dst = ei[NE + e];
    float ex = lg[t];
    redf(&den[dst * NH + h], ex);
    U16 V4, E4;
    const float4* vp = (const float4*)(Vh + (size_t)src * DIM + h * DH);
#pragma unroll
    for (int q = 0; q < 4; q++) V4.q[q] = vp[q];
    const uint4* pe = (const uint4*)(et16 + (size_t)e * DIM + h * DH);
#pragma unroll
    for (int half = 0; half < 2; half++) {
        uint4 E = pe[half];
        uint32_t ew[4] = {E.x, E.y, E.z, E.w};
#pragma unroll
        for (int q = 0; q < 4; q++) {
            float2 f = up2h(ew[q]);
            E4.f[half * 8 + q * 2 + 0] = f.x;
            E4.f[half * 8 + q * 2 + 1] = f.y;
        }
    }
    float* wv = wV + (size_t)dst * DIM + h * DH;
    float* rv = rowV + (size_t)dst * DIM + h * DH;
#pragma unroll
    for (int q = 0; q < 4; q++) {
        red4(wv + q * 4, V4.q[q].x * ex, V4.q[q].y * ex, V4.q[q].z * ex, V4.q[q].w * ex);
        red4(rv + q * 4, E4.f[q * 4] * ex, E4.f[q * 4 + 1] * ex,
             E4.f[q * 4 + 2] * ex, E4.f[q * 4 + 3] * ex);
    }
}

__global__ void node_fix(const float* __restrict__ wV, const float* __restrict__ rowV,
                         const float* __restrict__ den,
                         const float* __restrict__ VeRow, const float* __restrict__ log_deg,
                         const float* __restrict__ deg_coef, __half* __restrict__ hatt16)
{
    int t = blockIdx.x * blockDim.x + threadIdx.x;
    if (t >= NN * 64) return;
    int n = t >> 6, c0 = (t & 63) * 2, h = c0 >> 4, co = c0 & 15;
    size_t off = (size_t)n * DIM + c0;
    float inv = 1.f / (den[n * NH + h] + 1e-16f);
    float a0 = wV[off], a1 = wV[off + 1];
    const float* rv = rowV + (size_t)n * DIM + h * DH;
#pragma unroll
    for (int d2 = 0; d2 < 16; d2++) {
        float r = rv[d2];
        a0 = fmaf(r, VeRow[d2 * DIM + h * DH + co], a0);
        a1 = fmaf(r, VeRow[d2 * DIM + h * DH + co + 1], a1);
    }
    a0 *= inv; a1 *= inv;
    float ld = log_deg[n];
    float o0 = a0 * (deg_coef[2 * c0] + ld * deg_coef[2 * c0 + 1]);
    float o1 = a1 * (deg_coef[2 * c0 + 2] + ld * deg_coef[2 * c0 + 3]);
    *(uint32_t*)(hatt16 + off) = pack2h(__float2half_rn(o0), __float2half_rn(o1));
}

// OUTM 0 = fp32, 1 = fp16 hi/lo pair
template <int OUTM>
__global__ void bn_apply(const float* __restrict__ v, float* __restrict__ outf,
                         __half* __restrict__ outhi, __half* __restrict__ outlo, int M,
                         const float* __restrict__ sums,
                         const float* __restrict__ g, const float* __restrict__ b, float invM)
{
    long long i = ((long long)blockIdx.x * blockDim.x + threadIdx.x) * 2;
    if (i >= (long long)M * DIM) return;
    int c = (int)(i & (DIM - 1));
    float m0 = sums[c] * invM, m1 = sums[c + 1] * invM;
    float var0 = fmaf(-m0, m0, sums[DIM + c] * invM);
    float var1 = fmaf(-m1, m1, sums[DIM + c + 1] * invM);
    float2 vv = *(const float2*)(v + i);
    float o0 = (vv.x - m0) * rsqrtf(var0 + 1e-5f) * g[c] + b[c];
    float o1 = (vv.y - m1) * rsqrtf(var1 + 1e-5f) * g[c + 1] + b[c + 1];
    if (OUTM == 0) {
        *(float2*)(outf + i) = make_float2(o0, o1);
    } else {
        uint32_t lw, hw = packsplith(o0, o1, lw);
        *(uint32_t*)(outhi + i) = hw;
        *(uint32_t*)(outlo + i) = lw;
    }
}

// ---------------- launch ----------------
#define SYM(var, sym) cudaGetSymbolAddress((void**)&var, sym)

extern "C" void kernel_launch(void* const* d_in, const int* in_sizes, int n_in,
                              void* d_out, int out_size)
{
    const float* x         = (const float*)d_in[0];
    const float* edge_attr = (const float*)d_in[1];
    const int*   ei        = (const int*)d_in[2];
    const float* log_deg   = (const float*)d_in[3];
    const float* Wq = (const float*)d_in[4],  *bq  = (const float*)d_in[5];
    const float* Wk = (const float*)d_in[6],  *bk  = (const float*)d_in[7];
    const float* We = (const float*)d_in[8],  *be  = (const float*)d_in[9];
    const float* Wv = (const float*)d_in[10], *bv  = (const float*)d_in[11];
    const float* Aw = (const float*)d_in[12], *VeRow = (const float*)d_in[13];
    const float* WOh = (const float*)d_in[14], *bOh = (const float*)d_in[15];
    const float* WOe = (const float*)d_in[16], *bOe = (const float*)d_in[17];
    const float* deg_coef = (const float*)d_in[18];
    const float* g1h = (const float*)d_in[19], *b1h = (const float*)d_in[20];
    const float* g1e = (const float*)d_in[21], *b1e = (const float*)d_in[22];
    const float* g2h = (const float*)d_in[23], *b2h = (const float*)d_in[24];
    const float* W1 = (const float*)d_in[25], *b1 = (const float*)d_in[26];
    const float* W2 = (const float*)d_in[27], *b2 = (const float*)d_in[28];

    float *Qh, *Kh, *Vh, *lg, *den, *wV, *rowV, *v1, *v2, *s1, *s2buf, *se;
    SYM(Qh, g_Qh); SYM(Kh, g_Kh); SYM(Vh, g_Vh);
    SYM(lg, g_lg); SYM(den, g_den);
    SYM(wV, g_wV); SYM(rowV, g_rowV);
    SYM(v1, g_v1); SYM(v2, g_v2);
    SYM(s1, g_s1); SYM(s2buf, g_s2); SYM(se, g_se);
    __half *x16, *ea16, *et16, *we16h, *woe16h, *woe16l;
    SYM(x16, g_x16); SYM(ea16, g_ea16); SYM(et16, g_et16);
    SYM(we16h, g_we16h);
    SYM(woe16h, g_woe16h); SYM(woe16l, g_woe16l);
    __half *hatt16, *hbn16h, *hbn16l, *h2a16, *woh16h, *woh16l, *w116h, *w116l, *w216h, *w216l;
    SYM(hatt16, g_hatt16); SYM(hbn16h, g_hbn16h); SYM(hbn16l, g_hbn16l);
    SYM(h2a16, g_h2a16);
    SYM(woh16h, g_woh16h); SYM(woh16l, g_woh16l);
    SYM(w116h, g_w116h); SYM(w116l, g_w116l);
    SYM(w216h, g_w216h); SYM(w216l, g_w216l);
    __half *wq16h, *wq16l, *wk16h, *wk16l, *wv16h, *wv16l;
    SYM(wq16h, g_wq16h); SYM(wq16l, g_wq16l);
    SYM(wk16h, g_wk16h); SYM(wk16l, g_wk16l);
    SYM(wv16h, g_wv16h); SYM(wv16l, g_wv16l);

    float* hout = (float*)d_out;
    float* eout = (float*)d_out + (size_t)NN * DIM;

    cudaFuncSetAttribute(qkv_gemm, cudaFuncAttributeMaxDynamicSharedMemorySize, SMH_GEMM);
    cudaFuncSetAttribute(edge_gemm_fused, cudaFuncAttributeMaxDynamicSharedMemorySize, SMH_EDGE);
    cudaFuncSetAttribute(woe_gemm, cudaFuncAttributeMaxDynamicSharedMemorySize, SMH_GEMM);
    cudaFuncSetAttribute(mma_gemmH<1, 0, false, true >, cudaFuncAttributeMaxDynamicSharedMemorySize, SMH_GEMM);
    cudaFuncSetAttribute(mma_gemmH<0, 1, true,  false>, cudaFuncAttributeMaxDynamicSharedMemorySize, SMH_GEMM);
    cudaFuncSetAttribute(mma_gemmH<2, 0, false, true >, cudaFuncAttributeMaxDynamicSharedMemorySize, SMH_GEMM);

    // lazily-created side stream + events
    static cudaStream_t sside = nullptr;
    static cudaEvent_t ev0 = nullptr, evA = nullptr, ev1 = nullptr, ev2 = nullptr;
    if (!sside) {
        cudaStreamCreateWithFlags(&sside, cudaStreamNonBlocking);
        cudaEventCreateWithFlags(&ev0, cudaEventDisableTiming);
        cudaEventCreateWithFlags(&evA, cudaEventDisableTiming);
        cudaEventCreateWithFlags(&ev1, cudaEventDisableTiming);
        cudaEventCreateWithFlags(&ev2, cudaEventDisableTiming);
    }

    // fork side stream; big edge_attr fp16 preconv there
    cudaEventRecord(ev0, 0);
    cudaStreamWaitEvent(sside, ev0, 0);
    preconv_h<<<cdiv((long long)NE * DIM / 4, 256), 256, 0, sside>>>(edge_attr, ea16, (long long)NE * DIM);
    cudaEventRecord(evA, sside);

    // main: small preconvs + memsets + QKV
    preconv_h<<<cdiv((long long)NN * DIM / 4, 256), 256>>>(x, x16, (long long)NN * DIM);
    preconv_hpair<<<cdiv(DIM * DIM / 4, 256), 256>>>(Wq, wq16h, wq16l, DIM * DIM);
    preconv_hpair<<<cdiv(DIM * DIM / 4, 256), 256>>>(Wk, wk16h, wk16l, DIM * DIM);
    preconv_hpair<<<cdiv(DIM * DIM / 4, 256), 256>>>(Wv, wv16h, wv16l, DIM * DIM);
    preconv_h<<<cdiv(DIM * 2 * DIM / 4, 256), 256>>>(We, we16h, DIM * 2 * DIM);
    preconv_hpair<<<cdiv(DIM * DIM / 4, 256), 256>>>(WOe, woe16h, woe16l, DIM * DIM);
    preconv_hpair<<<cdiv(DIM * DIM / 4, 256), 256>>>(WOh, woh16h, woh16l, DIM * DIM);
    preconv_hpair<<<cdiv(DIM * 2 * DIM / 4, 256), 256>>>(W1, w116h, w116l, DIM * 2 * DIM);
    preconv_hpair<<<cdiv(2 * DIM * DIM / 4, 256), 256>>>(W2, w216h, w216l, 2 * DIM * DIM);

    cudaMemsetAsync(wV, 0, (size_t)NN * DIM * sizeof(float));
    cudaMemsetAsync(rowV, 0, (size_t)NN * DIM * sizeof(float));
    cudaMemsetAsync(den, 0, (size_t)NN * NH * sizeof(float));
    cudaMemsetAsync(s1, 0, 2 * DIM * sizeof(float));
    cudaMemsetAsync(s2buf, 0, 2 * DIM * sizeof(float));
    cudaMemsetAsync(se, 0, 2 * DIM * sizeof(float));

    const int gN = cdiv(NN, 128), gE = cdiv(NE, 128);

    qkv_gemm<<<dim3(3, gN), 256, SMH_GEMM>>>(x16, wq16h, wq16l, wk16h, wk16l,
                                             wv16h, wv16l, bq, bk, bv, Qh, Kh, Vh);

    cudaStreamWaitEvent(0, evA, 0);
    edge_gemm_fused<<<dim3(2, gE), 256, SMH_EDGE>>>(ea16, we16h, be,
                                                    ei, Aw, Qh, Kh, et16, lg);
    cudaEventRecord(ev1, 0);

    // side stream: e-path (WOe fp16 + stats, BN apply into eout)
    cudaStreamWaitEvent(sside, ev1, 0);
    woe_gemm<<<dim3(1, gE), 256, SMH_GEMM, sside>>>(et16, woe16h, woe16l, bOe, edge_attr, eout, se);
    bn_apply<0><<<cdiv((long long)NE * 64, 256), 256, 0, sside>>>(
        eout, eout, nullptr, nullptr, NE, se, g1e, b1e, 1.f / NE);
    cudaEventRecord(ev2, sside);

    // main stream: h-path (fp16 single-A GEMMs)
    edge_scatter<<<cdiv(NE * NH, 256), 256>>>(ei, lg, den, Vh, et16, wV, rowV);
    node_fix<<<cdiv(NN * 64, 256), 256>>>(wV, rowV, den, VeRow, log_deg, deg_coef, hatt16);
    mma_gemmH<1, 0, false, true><<<dim3(1, gN), 256, SMH_GEMM>>>(
        hatt16, woh16h, woh16l, bOh, x, nullptr, nullptr, v1, nullptr, s1, NN, 128, 128);
    bn_apply<1><<<cdiv((long long)NN * 64, 256), 256>>>(v1, nullptr, hbn16h, hbn16l, NN, s1, g1h, b1h, 1.f / NN);
    mma_gemmH<0, 1, true, false><<<dim3(2, gN), 256, SMH_GEMM>>>(
        hbn16h, w116h, w116l, b1, nullptr, nullptr, nullptr, nullptr, h2a16, nullptr, NN, 256, 128);
    mma_gemmH<2, 0, false, true><<<dim3(1, gN), 256, SMH_GEMM>>>(
        h2a16, w216h, w216l, b2, nullptr, hbn16h, hbn16l, v2, nullptr, s2buf, NN, 128, 256);
    bn_apply<0><<<cdiv((long long)NN * 64, 256), 256>>>(v2, hout, nullptr, nullptr, NN, s2buf, g2h, b2h, 1.f / NN);

    // join side stream back into the captured main stream
    cudaStreamWaitEvent(0, ev2, 0);
}

// round 16
// speedup vs baseline: 1.2570x; 1.0045x over previous
#include <cuda_runtime.h>
#include <cuda_bf16.h>
#include <cuda_fp16.h>
#include <math.h>
#include <stdint.h>

#define NN 40000
#define NE 640000
#define DIM 128
#define NH 8
#define DH 16

typedef __nv_bfloat16 bf16;

// ---------------- scratch (device globals: allocation-free) ----------------
__device__ float g_Qh[(size_t)NN * DIM];
__device__ float g_Kh[(size_t)NN * DIM];
__device__ float g_Vh[(size_t)NN * DIM];
__device__ float g_lg[(size_t)NE * NH];
__device__ float g_den[(size_t)NN * NH];
__device__ float g_wV[(size_t)NN * DIM];
__device__ float g_rowV[(size_t)NN * DIM];
__device__ float g_v1[(size_t)NN * DIM];
__device__ float g_v2[(size_t)NN * DIM];
__device__ float g_s1[2 * DIM];
__device__ float g_s2[2 * DIM];
__device__ float g_se[2 * DIM];
// fp16 buffers
__device__ __half g_x16[(size_t)NN * DIM];
__device__ __half g_ea16[(size_t)NE * DIM];
__device__ __half g_et16[(size_t)NE * DIM];
__device__ __half g_we16h[DIM * 2 * DIM];
__device__ __half g_woe16h[DIM * DIM], g_woe16l[DIM * DIM];
__device__ __half g_hatt16[(size_t)NN * DIM];
__device__ __half g_hbn16h[(size_t)NN * DIM], g_hbn16l[(size_t)NN * DIM];
__device__ __half g_h2a16[(size_t)NN * 2 * DIM];
__device__ __half g_woh16h[DIM * DIM];
__device__ __half g_w116h[DIM * 2 * DIM];
__device__ __half g_w216h[2 * DIM * DIM];
__device__ __half g_wq16h[DIM * DIM], g_wq16l[DIM * DIM];
__device__ __half g_wk16h[DIM * DIM], g_wk16l[DIM * DIM];
__device__ __half g_wv16h[DIM * DIM], g_wv16l[DIM * DIM];

static inline int cdiv(long long a, long long b) { return (int)((a + b - 1) / b); }

// ---------------- helpers ----------------
__device__ __forceinline__ uint32_t smem_u32(const void* p) {
    uint32_t a;
    asm("{ .reg .u64 t; cvta.to.shared.u64 t, %1; cvt.u32.u64 %0, t; }" : "=r"(a) : "l"(p));
    return a;
}
__device__ __forceinline__ void ldsm4(uint32_t (&r)[4], uint32_t addr) {
    asm volatile("ldmatrix.sync.aligned.m8n8.x4.shared.b16 {%0,%1,%2,%3}, [%4];"
                 : "=r"(r[0]), "=r"(r[1]), "=r"(r[2]), "=r"(r[3]) : "r"(addr));
}
__device__ __forceinline__ void ldsm4t(uint32_t (&r)[4], uint32_t addr) {
    asm volatile("ldmatrix.sync.aligned.m8n8.x4.trans.shared.b16 {%0,%1,%2,%3}, [%4];"
                 : "=r"(r[0]), "=r"(r[1]), "=r"(r[2]), "=r"(r[3]) : "r"(addr));
}
__device__ __forceinline__ void mma16816h(float (&d)[4], const uint32_t (&a)[4], const uint32_t* b) {
    asm volatile("mma.sync.aligned.m16n8k16.row.col.f32.f16.f16.f32 "
                 "{%0,%1,%2,%3}, {%4,%5,%6,%7}, {%8,%9}, {%0,%1,%2,%3};"
                 : "+f"(d[0]), "+f"(d[1]), "+f"(d[2]), "+f"(d[3])
                 : "r"(a[0]), "r"(a[1]), "r"(a[2]), "r"(a[3]), "r"(b[0]), "r"(b[1]));
}
__device__ __forceinline__ uint32_t pack2h(__half a, __half b) {
    return (uint32_t)__half_as_ushort(a) | ((uint32_t)__half_as_ushort(b) << 16);
}
__device__ __forceinline__ float2 up2h(uint32_t u) {
    __half2 h = *(__half2*)&u;
    return __half22float2(h);
}
__device__ __forceinline__ uint32_t packsplith(float a, float b, uint32_t& lo) {
    __half h0 = __float2half_rn(a), h1 = __float2half_rn(b);
    lo = pack2h(__float2half_rn(a - __half2float(h0)),
                __float2half_rn(b - __half2float(h1)));
    return pack2h(h0, h1);
}
__device__ __forceinline__ void cp16(uint32_t dst, const void* src, int sz) {
    asm volatile("cp.async.cg.shared.global [%0], [%1], 16, %2;" :: "r"(dst), "l"(src), "r"(sz));
}
#define CP_COMMIT() asm volatile("cp.async.commit_group;" ::: "memory")
#define CP_WAIT0()  asm volatile("cp.async.wait_group 0;" ::: "memory")
#define CP_WAIT1()  asm volatile("cp.async.wait_group 1;" ::: "memory")

__device__ __forceinline__ void red4(float* p, float a, float b, float c, float d) {
    asm volatile("red.global.add.v4.f32 [%0], {%1,%2,%3,%4};"
                 :: "l"(p), "f"(a), "f"(b), "f"(c), "f"(d) : "memory");
}
__device__ __forceinline__ void redf(float* p, float a) {
    asm volatile("red.global.add.f32 [%0], %1;" :: "l"(p), "f"(a) : "memory");
}

// ---------------- fp16 GEMM core: single A; W hi (+ optional lo) -----------
#define HSTG   27648u
#define HA_O   0u
#define HBHI_O 10240u
#define HBLO_O 18944u
#define SMH_GEMM 55296
#define SMH_EDGE 67584

template <bool WPAIR>
struct GemmCoreH {
    uint32_t sb;
    int tid, lid, wm, wn, m0, n0;
    float acc[4][4][4];

    __device__ __forceinline__ void init(uint8_t* smp, int bm, int bn) {
        sb = smem_u32(smp);
        tid = threadIdx.x; lid = tid & 31;
        int wid = tid >> 5;
        wm = wid >> 2; wn = wid & 3;
        m0 = bm * 128; n0 = bn * 128;
#pragma unroll
        for (int i = 0; i < 4; i++)
#pragma unroll
            for (int j = 0; j < 4; j++)
#pragma unroll
                for (int q = 0; q < 4; q++) acc[i][j][q] = 0.f;
    }
    __device__ __forceinline__ void stage(int buf, const __half* A,
                                          const __half* Whi, const __half* Wlo,
                                          int M, int Ncols, int K, int kb) {
        uint32_t base = sb + (uint32_t)buf * HSTG;
#pragma unroll
        for (int i = 0; i < 2; i++) {
            int c = tid + i * 256;
            int row = c >> 2, gr = c & 3;
            bool ok = (m0 + row) < M;
            size_t go = (size_t)(ok ? m0 + row : 0) * K + kb + gr * 8;
            cp16(base + HA_O + (uint32_t)row * 80 + (uint32_t)gr * 16, A + go, ok ? 16 : 0);
        }
#pragma unroll
        for (int i = 0; i < 2; i++) {
            int c = tid + i * 256;
            int k = c >> 4, gr = c & 15;
            size_t go = (size_t)(kb + k) * Ncols + n0 + gr * 8;
            uint32_t d = base + (uint32_t)k * 272 + (uint32_t)gr * 16;
            cp16(d + HBHI_O, Whi + go, 16);
            if (WPAIR) cp16(d + HBLO_O, Wlo + go, 16);
        }
        CP_COMMIT();
    }
    __device__ __forceinline__ void compute(int buf) {
        uint32_t base = sb + (uint32_t)buf * HSTG;
#pragma unroll
        for (int ks = 0; ks < 32; ks += 16) {
            uint32_t bhi[4][2], blo[4][2];
            const uint32_t brow = (uint32_t)(ks + (lid & 15)) * 272 + (uint32_t)((lid >> 4) * 16);
#pragma unroll
            for (int p = 0; p < 2; p++) {
                uint32_t baddr = base + brow + (uint32_t)(wn * 32 + p * 16) * 2;
                uint32_t r[4];
                ldsm4t(r, baddr + HBHI_O);
                bhi[2 * p][0] = r[0]; bhi[2 * p][1] = r[1];
                bhi[2 * p + 1][0] = r[2]; bhi[2 * p + 1][1] = r[3];
                if (WPAIR) {
                    ldsm4t(r, baddr + HBLO_O);
                    blo[2 * p][0] = r[0]; blo[2 * p][1] = r[1];
                    blo[2 * p + 1][0] = r[2]; blo[2 * p + 1][1] = r[3];
                }
            }
            const uint32_t arow = (uint32_t)(wm * 64 + (lid & 15)) * 80
                                + (uint32_t)ks * 2 + (uint32_t)(lid >> 4) * 16;
#pragma unroll
            for (int mt = 0; mt < 4; mt++) {
                uint32_t a4[4];
                ldsm4(a4, base + HA_O + arow + (uint32_t)mt * (16 * 80));
#pragma unroll
                for (int nt = 0; nt < 4; nt++) {
                    mma16816h(acc[mt][nt], a4, bhi[nt]);
                    if (WPAIR) mma16816h(acc[mt][nt], a4, blo[nt]);
                }
            }
        }
    }
    __device__ __forceinline__ void run(const __half* A, const __half* Whi, const __half* Wlo,
                                        int M, int Ncols, int K) {
        const int nch = K >> 5;
        stage(0, A, Whi, Wlo, M, Ncols, K, 0);
        if (nch > 1) stage(1, A, Whi, Wlo, M, Ncols, K, 32);
        for (int i = 0; i < nch; i++) {
            if (i == nch - 1) { CP_WAIT0(); } else { CP_WAIT1(); }
            __syncthreads();
            compute(i & 1);
            if (i + 2 < nch) {
                __syncthreads();
                stage(i & 1, A, Whi, Wlo, M, Ncols, K, (i + 2) * 32);
            }
        }
    }
};

// ---------------- generic fp16 GEMM ----------------
// RESMODE 0=none 1=f32 2=fp16pair; OUTMODE 0=f32 1=fp16 single; STATS col sums
template <int RESMODE, int OUTMODE, bool RELU, bool STATS, bool WPAIR>
__global__ void __launch_bounds__(256, 2)
mma_gemmH(const __half* __restrict__ A,
          const __half* __restrict__ Whi, const __half* __restrict__ Wlo,
          const float* __restrict__ bias, const float* __restrict__ resf,
          const __half* __restrict__ reshi, const __half* __restrict__ reslo,
          float* __restrict__ Cf, __half* __restrict__ Ch,
          float* __restrict__ stats, int M, int Ncols, int K)
{
    extern __shared__ __align__(16) uint8_t sm[];
    GemmCoreH<WPAIR> g;
    g.init(sm, blockIdx.y, blockIdx.x);
    g.run(A, Whi, Wlo, M, Ncols, K);

    float ts0[4], ts1[4], tq0[4], tq1[4];
    if (STATS) {
#pragma unroll
        for (int nt = 0; nt < 4; nt++) { ts0[nt] = ts1[nt] = tq0[nt] = tq1[nt] = 0.f; }
    }

    const int qr = g.lid >> 2, qc = (g.lid & 3) * 2;
#pragma unroll
    for (int mt = 0; mt < 4; mt++) {
#pragma unroll
        for (int nt = 0; nt < 4; nt++) {
            int col = g.n0 + g.wn * 32 + nt * 8 + qc;
            float b0 = bias[col], b1 = bias[col + 1];
#pragma unroll
            for (int half = 0; half < 2; half++) {
                int row = g.m0 + g.wm * 64 + mt * 16 + qr + half * 8;
                if (row >= M) continue;
                float o0 = g.acc[mt][nt][half * 2 + 0] + b0;
                float o1 = g.acc[mt][nt][half * 2 + 1] + b1;
                size_t off = (size_t)row * Ncols + col;
                if (RESMODE == 1) {
                    float2 rr = *(const float2*)(resf + off);
                    o0 += rr.x; o1 += rr.y;
                } else if (RESMODE == 2) {
                    float2 rh = up2h(*(const uint32_t*)(reshi + off));
                    float2 rl = up2h(*(const uint32_t*)(reslo + off));
                    o0 += rh.x + rl.x; o1 += rh.y + rl.y;
                }
                if (RELU) { o0 = fmaxf(o0, 0.f); o1 = fmaxf(o1, 0.f); }
                if (STATS) {
                    ts0[nt] += o0; ts1[nt] += o1;
                    tq0[nt] = fmaf(o0, o0, tq0[nt]); tq1[nt] = fmaf(o1, o1, tq1[nt]);
                }
                if (OUTMODE == 0) {
                    *(float2*)(Cf + off) = make_float2(o0, o1);
                } else {
                    *(uint32_t*)(Ch + off) = pack2h(__float2half_rn(o0), __float2half_rn(o1));
                }
            }
        }
    }
    if (STATS) {
#pragma unroll
        for (int nt = 0; nt < 4; nt++) {
            float a = ts0[nt], b = ts1[nt], c = tq0[nt], d = tq1[nt];
#pragma unroll
            for (int m = 4; m <= 16; m <<= 1) {
                a += __shfl_xor_sync(0xffffffff, a, m);
                b += __shfl_xor_sync(0xffffffff, b, m);
                c += __shfl_xor_sync(0xffffffff, c, m);
                d += __shfl_xor_sync(0xffffffff, d, m);
            }
            if (qr == 0) {
                int col = g.n0 + g.wn * 32 + nt * 8 + qc;
                redf(stats + col, a);
                redf(stats + col + 1, b);
                redf(stats + DIM + col, c);
                redf(stats + DIM + col + 1, d);
            }
        }
    }
}

// ---------------- fused QKV (fp16 single-A, hi/lo W; blockIdx.x = weight) ---
__global__ void __launch_bounds__(256, 2)
qkv_gemm(const __half* __restrict__ x16,
         const __half* __restrict__ qh, const __half* __restrict__ ql,
         const __half* __restrict__ kh, const __half* __restrict__ kl,
         const __half* __restrict__ vh, const __half* __restrict__ vl,
         const float* __restrict__ bq, const float* __restrict__ bk,
         const float* __restrict__ bv,
         float* __restrict__ Qo, float* __restrict__ Ko, float* __restrict__ Vo)
{
    extern __shared__ __align__(16) uint8_t sm[];
    const __half* Whi = qh; const __half* Wlo = ql;
    const float* bias = bq; float* C = Qo;
    if (blockIdx.x == 1) { Whi = kh; Wlo = kl; bias = bk; C = Ko; }
    else if (blockIdx.x == 2) { Whi = vh; Wlo = vl; bias = bv; C = Vo; }

    GemmCoreH<true> g;
    g.init(sm, blockIdx.y, 0);
    g.run(x16, Whi, Wlo, NN, 128, 128);

    const int qr = g.lid >> 2, qc = (g.lid & 3) * 2;
#pragma unroll
    for (int mt = 0; mt < 4; mt++) {
#pragma unroll
        for (int nt = 0; nt < 4; nt++) {
            int col = g.wn * 32 + nt * 8 + qc;
            float b0 = bias[col], b1 = bias[col + 1];
#pragma unroll
            for (int half = 0; half < 2; half++) {
                int row = g.m0 + g.wm * 64 + mt * 16 + qr + half * 8;
                if (row >= NN) continue;
                *(float2*)(C + (size_t)row * 128 + col) =
                    make_float2(g.acc[mt][nt][half * 2 + 0] + b0,
                                g.acc[mt][nt][half * 2 + 1] + b1);
            }
        }
    }
}

// ---------------- fused Ee GEMM (pure fp16, 1 product) + edge epilogue ------
union U16 { float4 q[4]; float f[16]; };

__global__ void __launch_bounds__(256, 2)
edge_gemm_fused(const __half* __restrict__ ea16,
                const __half* __restrict__ weh,
                const float* __restrict__ bias,
                const int* __restrict__ ei, const float* __restrict__ Aw,
                const float* __restrict__ Qh, const float* __restrict__ Kh,
                __half* __restrict__ et16, float* __restrict__ lg)
{
    extern __shared__ __align__(16) uint8_t sm[];
    __shared__ float sAw[DIM];
    if (threadIdx.x < DIM) sAw[threadIdx.x] = Aw[threadIdx.x];

    GemmCoreH<false> g;
    g.init(sm, blockIdx.y, blockIdx.x);
    g.run(ea16, weh, nullptr, NE, 256, 128);

    __syncthreads();
    float* sC = (float*)sm;
    const int qr = g.lid >> 2, qc = (g.lid & 3) * 2;
#pragma unroll
    for (int mt = 0; mt < 4; mt++) {
#pragma unroll
        for (int nt = 0; nt < 4; nt++) {
            int col = g.wn * 32 + nt * 8 + qc;
            float b0 = bias[g.n0 + col], b1 = bias[g.n0 + col + 1];
#pragma unroll
            for (int half = 0; half < 2; half++) {
                int row = g.wm * 64 + mt * 16 + qr + half * 8;
                *(float2*)(sC + row * 132 + col) =
                    make_float2(g.acc[mt][nt][half * 2 + 0] + b0,
                                g.acc[mt][nt][half * 2 + 1] + b1);
            }
        }
    }
    __syncthreads();

    const int e = threadIdx.x & 127;
    const int ge = g.m0 + e;                    // NE % 128 == 0
    const int src = ei[ge], dst = ei[NE + ge];
#pragma unroll
    for (int u = 0; u < 2; u++) {
        const int hl = (threadIdx.x >> 7) * 2 + u;
        const int h = blockIdx.x * 4 + hl;
        const float* ew = sC + e * 132 + hl * 32;
        U16 K4, Q4, EW, EB, ET;
        const float4* kp = (const float4*)(Kh + (size_t)src * DIM + h * DH);
        const float4* qp = (const float4*)(Qh + (size_t)dst * DIM + h * DH);
#pragma unroll
        for (int q = 0; q < 4; q++) {
            K4.q[q] = kp[q]; Q4.q[q] = qp[q];
            EW.q[q] = *(const float4*)(ew + q * 4);
            EB.q[q] = *(const float4*)(ew + 16 + q * 4);
        }
        float logit = 0.f;
#pragma unroll
        for (int d = 0; d < 16; d++) {
            float s = (K4.f[d] + Q4.f[d]) * EW.f[d];
            float a = fabsf(s);
            float r = (a > 0.f) ? copysignf(sqrtf(a), s) : 0.f;
            float v = fmaxf(r + EB.f[d], 0.f);
            ET.f[d] = v;
            logit = fmaf(v, sAw[d * NH + h], logit);
        }
        logit = fminf(fmaxf(logit, -5.f), 5.f);
        uint32_t hw[8];
#pragma unroll
        for (int q = 0; q < 8; q++)
            hw[q] = pack2h(__float2half_rn(ET.f[2 * q]), __float2half_rn(ET.f[2 * q + 1]));
        __half* pe = et16 + (size_t)ge * DIM + h * DH;
        *(uint4*)pe       = make_uint4(hw[0], hw[1], hw[2], hw[3]);
        *((uint4*)pe + 1) = make_uint4(hw[4], hw[5], hw[6], hw[7]);
        lg[ge * NH + h] = expf(logit);
    }
}

// ---------------- WOe GEMM (fp16, hi/lo W) + residual + fused BN stats ------
__global__ void __launch_bounds__(256, 2)
woe_gemm(const __half* __restrict__ et16,
         const __half* __restrict__ weh, const __half* __restrict__ wel,
         const float* __restrict__ bias, const float* __restrict__ resf,
         float* __restrict__ Cf, float* __restrict__ stats)
{
    extern __shared__ __align__(16) uint8_t sm[];
    GemmCoreH<true> g;
    g.init(sm, blockIdx.y, 0);
    g.run(et16, weh, wel, NE, 128, 128);

    float ts0[4], ts1[4], tq0[4], tq1[4];
#pragma unroll
    for (int nt = 0; nt < 4; nt++) { ts0[nt] = ts1[nt] = tq0[nt] = tq1[nt] = 0.f; }

    const int qr = g.lid >> 2, qc = (g.lid & 3) * 2;
#pragma unroll
    for (int mt = 0; mt < 4; mt++) {
#pragma unroll
        for (int nt = 0; nt < 4; nt++) {
            int col = g.wn * 32 + nt * 8 + qc;
            float b0 = bias[col], b1 = bias[col + 1];
#pragma unroll
            for (int half = 0; half < 2; half++) {
                int row = g.m0 + g.wm * 64 + mt * 16 + qr + half * 8;
                float o0 = g.acc[mt][nt][half * 2 + 0] + b0;
                float o1 = g.acc[mt][nt][half * 2 + 1] + b1;
                size_t off = (size_t)row * 128 + col;
                float2 rr = *(const float2*)(resf + off);
                o0 += rr.x; o1 += rr.y;
                ts0[nt] += o0; ts1[nt] += o1;
                tq0[nt] = fmaf(o0, o0, tq0[nt]); tq1[nt] = fmaf(o1, o1, tq1[nt]);
                *(float2*)(Cf + off) = make_float2(o0, o1);
            }
        }
    }
#pragma unroll
    for (int nt = 0; nt < 4; nt++) {
        float a = ts0[nt], b = ts1[nt], c = tq0[nt], d = tq1[nt];
#pragma unroll
        for (int m = 4; m <= 16; m <<= 1) {
            a += __shfl_xor_sync(0xffffffff, a, m);
            b += __shfl_xor_sync(0xffffffff, b, m);
            c += __shfl_xor_sync(0xffffffff, c, m);
            d += __shfl_xor_sync(0xffffffff, d, m);
        }
        if (qr == 0) {
            int col = g.wn * 32 + nt * 8 + qc;
            redf(stats + col, a);
            redf(stats + col + 1, b);
            redf(stats + DIM + col, c);
            redf(stats + DIM + col + 1, d);
        }
    }
}

// ---------------- misc / edge / node / bn kernels ----------------
__global__ void preconv_h(const float* __restrict__ in, __half* __restrict__ out, long long n)
{
    long long i = ((long long)blockIdx.x * blockDim.x + threadIdx.x) * 4;
    if (i >= n) return;
    float4 v = *(const float4*)(in + i);
    uint2 o;
    o.x = pack2h(__float2half_rn(v.x), __float2half_rn(v.y));
    o.y = pack2h(__float2half_rn(v.z), __float2half_rn(v.w));
    *(uint2*)(out + i) = o;
}

__global__ void preconv_hpair(const float* __restrict__ in, __half* __restrict__ hi,
                              __half* __restrict__ lo, long long n)
{
    long long i = ((long long)blockIdx.x * blockDim.x + threadIdx.x) * 4;
    if (i >= n) return;
    float4 v = *(const float4*)(in + i);
    float vv[4] = {v.x, v.y, v.z, v.w};
    __half hh[4], ll[4];
#pragma unroll
    for (int q = 0; q < 4; q++) {
        hh[q] = __float2half_rn(vv[q]);
        ll[q] = __float2half_rn(vv[q] - __half2float(hh[q]));
    }
    *(uint2*)(hi + i) = make_uint2(pack2h(hh[0], hh[1]), pack2h(hh[2], hh[3]));
    *(uint2*)(lo + i) = make_uint2(pack2h(ll[0], ll[1]), pack2h(ll[2], ll[3]));
}

// denominator + unnormalized scatter; lg holds ex; et single fp16.
__global__ void edge_scatter(const int* __restrict__ ei, const float* __restrict__ lg,
                             float* __restrict__ den, const float* __restrict__ Vh,
                             const __half* __restrict__ et16,
                             float* __restrict__ wV, float* __restrict__ rowV)
{
    int t = blockIdx.x * blockDim.x + threadIdx.x;
    if (t >= NE * NH) return;
    int e = t >> 3, h = t & 7;
    int src = ei[e], dst = ei[NE + e];
    float ex = lg[t];
    redf(&den[dst * NH + h], ex);
    U16 V4, E4;
    const float4* vp = (const float4*)(Vh + (size_t)src * DIM + h * DH);
#pragma unroll
    for (int q = 0; q < 4; q++) V4.q[q] = vp[q];
    const uint4* pe = (const uint4*)(et16 + (size_t)e * DIM + h * DH);
#pragma unroll
    for (int half = 0; half < 2; half++) {
        uint4 E = pe[half];
        uint32_t ew[4] = {E.x, E.y, E.z, E.w};
#pragma unroll
        for (int q = 0; q < 4; q++) {
            float2 f = up2h(ew[q]);
            E4.f[half * 8 + q * 2 + 0] = f.x;
            E4.f[half * 8 + q * 2 + 1] = f.y;
        }
    }
    float* wv = wV + (size_t)dst * DIM + h * DH;
    float* rv = rowV + (size_t)dst * DIM + h * DH;
#pragma unroll
    for (int q = 0; q < 4; q++) {
        red4(wv + q * 4, V4.q[q].x * ex, V4.q[q].y * ex, V4.q[q].z * ex, V4.q[q].w * ex);
        red4(rv + q * 4, E4.f[q * 4] * ex, E4.f[q * 4 + 1] * ex,
             E4.f[q * 4 + 2] * ex, E4.f[q * 4 + 3] * ex);
    }
}

__global__ void node_fix(const float* __restrict__ wV, const float* __restrict__ rowV,
                         const float* __restrict__ den,
                         const float* __restrict__ VeRow, const float* __restrict__ log_deg,
                         const float* __restrict__ deg_coef, __half* __restrict__ hatt16)
{
    int t = blockIdx.x * blockDim.x + threadIdx.x;
    if (t >= NN * 64) return;
    int n = t >> 6, c0 = (t & 63) * 2, h = c0 >> 4, co = c0 & 15;
    size_t off = (size_t)n * DIM + c0;
    float inv = 1.f / (den[n * NH + h] + 1e-16f);
    float a0 = wV[off], a1 = wV[off + 1];
    const float* rv = rowV + (size_t)n * DIM + h * DH;
#pragma unroll
    for (int d2 = 0; d2 < 16; d2++) {
        float r = rv[d2];
        a0 = fmaf(r, VeRow[d2 * DIM + h * DH + co], a0);
        a1 = fmaf(r, VeRow[d2 * DIM + h * DH + co + 1], a1);
    }
    a0 *= inv; a1 *= inv;
    float ld = log_deg[n];
    float o0 = a0 * (deg_coef[2 * c0] + ld * deg_coef[2 * c0 + 1]);
    float o1 = a1 * (deg_coef[2 * c0 + 2] + ld * deg_coef[2 * c0 + 3]);
    *(uint32_t*)(hatt16 + off) = pack2h(__float2half_rn(o0), __float2half_rn(o1));
}

// OUTM 0 = fp32, 1 = fp16 hi/lo pair
template <int OUTM>
__global__ void bn_apply(const float* __restrict__ v, float* __restrict__ outf,
                         __half* __restrict__ outhi, __half* __restrict__ outlo, int M,
                         const float* __restrict__ sums,
                         const float* __restrict__ g, const float* __restrict__ b, float invM)
{
    long long i = ((long long)blockIdx.x * blockDim.x + threadIdx.x) * 2;
    if (i >= (long long)M * DIM) return;
    int c = (int)(i & (DIM - 1));
    float m0 = sums[c] * invM, m1 = sums[c + 1] * invM;
    float var0 = fmaf(-m0, m0, sums[DIM + c] * invM);
    float var1 = fmaf(-m1, m1, sums[DIM + c + 1] * invM);
    float2 vv = *(const float2*)(v + i);
    float o0 = (vv.x - m0) * rsqrtf(var0 + 1e-5f) * g[c] + b[c];
    float o1 = (vv.y - m1) * rsqrtf(var1 + 1e-5f) * g[c + 1] + b[c + 1];
    if (OUTM == 0) {
        *(float2*)(outf + i) = make_float2(o0, o1);
    } else {
        uint32_t lw, hw = packsplith(o0, o1, lw);
        *(uint32_t*)(outhi + i) = hw;
        *(uint32_t*)(outlo + i) = lw;
    }
}

// ---------------- launch ----------------
#define SYM(var, sym) cudaGetSymbolAddress((void**)&var, sym)

extern "C" void kernel_launch(void* const* d_in, const int* in_sizes, int n_in,
                              void* d_out, int out_size)
{
    const float* x         = (const float*)d_in[0];
    const float* edge_attr = (const float*)d_in[1];
    const int*   ei        = (const int*)d_in[2];
    const float* log_deg   = (const float*)d_in[3];
    const float* Wq = (const float*)d_in[4],  *bq  = (const float*)d_in[5];
    const float* Wk = (const float*)d_in[6],  *bk  = (const float*)d_in[7];
    const float* We = (const float*)d_in[8],  *be  = (const float*)d_in[9];
    const float* Wv = (const float*)d_in[10], *bv  = (const float*)d_in[11];
    const float* Aw = (const float*)d_in[12], *VeRow = (const float*)d_in[13];
    const float* WOh = (const float*)d_in[14], *bOh = (const float*)d_in[15];
    const float* WOe = (const float*)d_in[16], *bOe = (const float*)d_in[17];
    const float* deg_coef = (const float*)d_in[18];
    const float* g1h = (const float*)d_in[19], *b1h = (const float*)d_in[20];
    const float* g1e = (const float*)d_in[21], *b1e = (const float*)d_in[22];
    const float* g2h = (const float*)d_in[23], *b2h = (const float*)d_in[24];
    const float* W1 = (const float*)d_in[25], *b1 = (const float*)d_in[26];
    const float* W2 = (const float*)d_in[27], *b2 = (const float*)d_in[28];

    float *Qh, *Kh, *Vh, *lg, *den, *wV, *rowV, *v1, *v2, *s1, *s2buf, *se;
    SYM(Qh, g_Qh); SYM(Kh, g_Kh); SYM(Vh, g_Vh);
    SYM(lg, g_lg); SYM(den, g_den);
    SYM(wV, g_wV); SYM(rowV, g_rowV);
    SYM(v1, g_v1); SYM(v2, g_v2);
    SYM(s1, g_s1); SYM(s2buf, g_s2); SYM(se, g_se);
    __half *x16, *ea16, *et16, *we16h, *woe16h, *woe16l;
    SYM(x16, g_x16); SYM(ea16, g_ea16); SYM(et16, g_et16);
    SYM(we16h, g_we16h);
    SYM(woe16h, g_woe16h); SYM(woe16l, g_woe16l);
    __half *hatt16, *hbn16h, *hbn16l, *h2a16, *woh16h, *w116h, *w216h;
    SYM(hatt16, g_hatt16); SYM(hbn16h, g_hbn16h); SYM(hbn16l, g_hbn16l);
    SYM(h2a16, g_h2a16);
    SYM(woh16h, g_woh16h);
    SYM(w116h, g_w116h);
    SYM(w216h, g_w216h);
    __half *wq16h, *wq16l, *wk16h, *wk16l, *wv16h, *wv16l;
    SYM(wq16h, g_wq16h); SYM(wq16l, g_wq16l);
    SYM(wk16h, g_wk16h); SYM(wk16l, g_wk16l);
    SYM(wv16h, g_wv16h); SYM(wv16l, g_wv16l);

    float* hout = (float*)d_out;
    float* eout = (float*)d_out + (size_t)NN * DIM;

    cudaFuncSetAttribute(qkv_gemm, cudaFuncAttributeMaxDynamicSharedMemorySize, SMH_GEMM);
    cudaFuncSetAttribute(edge_gemm_fused, cudaFuncAttributeMaxDynamicSharedMemorySize, SMH_EDGE);
    cudaFuncSetAttribute(woe_gemm, cudaFuncAttributeMaxDynamicSharedMemorySize, SMH_GEMM);
    cudaFuncSetAttribute(mma_gemmH<1, 0, false, true,  false>, cudaFuncAttributeMaxDynamicSharedMemorySize, SMH_GEMM);
    cudaFuncSetAttribute(mma_gemmH<0, 1, true,  false, false>, cudaFuncAttributeMaxDynamicSharedMemorySize, SMH_GEMM);
    cudaFuncSetAttribute(mma_gemmH<2, 0, false, true,  false>, cudaFuncAttributeMaxDynamicSharedMemorySize, SMH_GEMM);

    // lazily-created side stream + events
    static cudaStream_t sside = nullptr;
    static cudaEvent_t ev0 = nullptr, evA = nullptr, ev1 = nullptr, ev2 = nullptr;
    if (!sside) {
        cudaStreamCreateWithFlags(&sside, cudaStreamNonBlocking);
        cudaEventCreateWithFlags(&ev0, cudaEventDisableTiming);
        cudaEventCreateWithFlags(&evA, cudaEventDisableTiming);
        cudaEventCreateWithFlags(&ev1, cudaEventDisableTiming);
        cudaEventCreateWithFlags(&ev2, cudaEventDisableTiming);
    }

    // fork side stream; big edge_attr fp16 preconv there
    cudaEventRecord(ev0, 0);
    cudaStreamWaitEvent(sside, ev0, 0);
    preconv_h<<<cdiv((long long)NE * DIM / 4, 256), 256, 0, sside>>>(edge_attr, ea16, (long long)NE * DIM);
    cudaEventRecord(evA, sside);

    // main: small preconvs + memsets + QKV
    preconv_h<<<cdiv((long long)NN * DIM / 4, 256), 256>>>(x, x16, (long long)NN * DIM);
    preconv_hpair<<<cdiv(DIM * DIM / 4, 256), 256>>>(Wq, wq16h, wq16l, DIM * DIM);
    preconv_hpair<<<cdiv(DIM * DIM / 4, 256), 256>>>(Wk, wk16h, wk16l, DIM * DIM);
    preconv_hpair<<<cdiv(DIM * DIM / 4, 256), 256>>>(Wv, wv16h, wv16l, DIM * DIM);
    preconv_h<<<cdiv(DIM * 2 * DIM / 4, 256), 256>>>(We, we16h, DIM * 2 * DIM);
    preconv_hpair<<<cdiv(DIM * DIM / 4, 256), 256>>>(WOe, woe16h, woe16l, DIM * DIM);
    preconv_h<<<cdiv(DIM * DIM / 4, 256), 256>>>(WOh, woh16h, DIM * DIM);
    preconv_h<<<cdiv(DIM * 2 * DIM / 4, 256), 256>>>(W1, w116h, DIM * 2 * DIM);
    preconv_h<<<cdiv(2 * DIM * DIM / 4, 256), 256>>>(W2, w216h, 2 * DIM * DIM);

    cudaMemsetAsync(wV, 0, (size_t)NN * DIM * sizeof(float));
    cudaMemsetAsync(rowV, 0, (size_t)NN * DIM * sizeof(float));
    cudaMemsetAsync(den, 0, (size_t)NN * NH * sizeof(float));
    cudaMemsetAsync(s1, 0, 2 * DIM * sizeof(float));
    cudaMemsetAsync(s2buf, 0, 2 * DIM * sizeof(float));
    cudaMemsetAsync(se, 0, 2 * DIM * sizeof(float));

    const int gN = cdiv(NN, 128), gE = cdiv(NE, 128);

    qkv_gemm<<<dim3(3, gN), 256, SMH_GEMM>>>(x16, wq16h, wq16l, wk16h, wk16l,
                                             wv16h, wv16l, bq, bk, bv, Qh, Kh, Vh);

    cudaStreamWaitEvent(0, evA, 0);
    edge_gemm_fused<<<dim3(2, gE), 256, SMH_EDGE>>>(ea16, we16h, be,
                                                    ei, Aw, Qh, Kh, et16, lg);
    cudaEventRecord(ev1, 0);

    // side stream: e-path (WOe fp16 + stats, BN apply into eout)
    cudaStreamWaitEvent(sside, ev1, 0);
    woe_gemm<<<dim3(1, gE), 256, SMH_GEMM, sside>>>(et16, woe16h, woe16l, bOe, edge_attr, eout, se);
    bn_apply<0><<<cdiv((long long)NE * 64, 256), 256, 0, sside>>>(
        eout, eout, nullptr, nullptr, NE, se, g1e, b1e, 1.f / NE);
    cudaEventRecord(ev2, sside);

    // main stream: h-path (fp16 single-A, hi-only-W GEMMs)
    edge_scatter<<<cdiv(NE * NH, 256), 256>>>(ei, lg, den, Vh, et16, wV, rowV);
    node_fix<<<cdiv(NN * 64, 256), 256>>>(wV, rowV, den, VeRow, log_deg, deg_coef, hatt16);
    mma_gemmH<1, 0, false, true, false><<<dim3(1, gN), 256, SMH_GEMM>>>(
        hatt16, woh16h, nullptr, bOh, x, nullptr, nullptr, v1, nullptr, s1, NN, 128, 128);
    bn_apply<1><<<cdiv((long long)NN * 64, 256), 256>>>(v1, nullptr, hbn16h, hbn16l, NN, s1, g1h, b1h, 1.f / NN);
    mma_gemmH<0, 1, true, false, false><<<dim3(2, gN), 256, SMH_GEMM>>>(
        hbn16h, w116h, nullptr, b1, nullptr, nullptr, nullptr, nullptr, h2a16, nullptr, NN, 256, 128);
    mma_gemmH<2, 0, false, true, false><<<dim3(1, gN), 256, SMH_GEMM>>>(
        h2a16, w216h, nullptr, b2, nullptr, hbn16h, hbn16l, v2, nullptr, s2buf, NN, 128, 256);
    bn_apply<0><<<cdiv((long long)NN * 64, 256), 256>>>(v2, hout, nullptr, nullptr, NN, s2buf, g2h, b2h, 1.f / NN);

    // join side stream back into the captured main stream
    cudaStreamWaitEvent(0, ev2, 0);
}

// round 17
// speedup vs baseline: 1.2798x; 1.0181x over previous
#include <cuda_runtime.h>
#include <cuda_bf16.h>
#include <cuda_fp16.h>
#include <math.h>
#include <stdint.h>

#define NN 40000
#define NE 640000
#define DIM 128
#define NH 8
#define DH 16

static inline int cdiv(long long a, long long b) { return (int)((a + b - 1) / b); }

// ---------------- scratch (device globals: allocation-free) ----------------
__device__ float g_Qh[(size_t)NN * DIM];
__device__ float g_Kh[(size_t)NN * DIM];
__device__ float g_Vh[(size_t)NN * DIM];
__device__ float g_lg[(size_t)NE * NH];
__device__ float g_den[(size_t)NN * NH];
__device__ float g_wV[(size_t)NN * DIM];
__device__ float g_rowV[(size_t)NN * DIM];
__device__ float g_v1[(size_t)NN * DIM];
__device__ float g_v2[(size_t)NN * DIM];
__device__ float g_s1[2 * DIM];
__device__ float g_s2[2 * DIM];
__device__ float g_se[2 * DIM];
// fp16 buffers
__device__ __half g_x16[(size_t)NN * DIM];
__device__ __half g_ea16[(size_t)NE * DIM];   // edge_attr fp16; REUSED as pre-BN eout
__device__ __half g_et16[(size_t)NE * DIM];
__device__ __half g_we16h[DIM * 2 * DIM];
__device__ __half g_woe16h[DIM * DIM];
__device__ __half g_hatt16[(size_t)NN * DIM];
__device__ __half g_hbn16h[(size_t)NN * DIM], g_hbn16l[(size_t)NN * DIM];
__device__ __half g_h2a16[(size_t)NN * 2 * DIM];
__device__ __half g_woh16h[DIM * DIM];
__device__ __half g_w116h[DIM * 2 * DIM];
__device__ __half g_w216h[2 * DIM * DIM];
__device__ __half g_wq16h[DIM * DIM], g_wq16l[DIM * DIM];
__device__ __half g_wk16h[DIM * DIM], g_wk16l[DIM * DIM];
__device__ __half g_wv16h[DIM * DIM], g_wv16l[DIM * DIM];

// ---------------- helpers ----------------
__device__ __forceinline__ uint32_t smem_u32(const void* p) {
    uint32_t a;
    asm("{ .reg .u64 t; cvta.to.shared.u64 t, %1; cvt.u32.u64 %0, t; }" : "=r"(a) : "l"(p));
    return a;
}
__device__ __forceinline__ void ldsm4(uint32_t (&r)[4], uint32_t addr) {
    asm volatile("ldmatrix.sync.aligned.m8n8.x4.shared.b16 {%0,%1,%2,%3}, [%4];"
                 : "=r"(r[0]), "=r"(r[1]), "=r"(r[2]), "=r"(r[3]) : "r"(addr));
}
__device__ __forceinline__ void ldsm4t(uint32_t (&r)[4], uint32_t addr) {
    asm volatile("ldmatrix.sync.aligned.m8n8.x4.trans.shared.b16 {%0,%1,%2,%3}, [%4];"
                 : "=r"(r[0]), "=r"(r[1]), "=r"(r[2]), "=r"(r[3]) : "r"(addr));
}
__device__ __forceinline__ void mma16816h(float (&d)[4], const uint32_t (&a)[4], const uint32_t* b) {
    asm volatile("mma.sync.aligned.m16n8k16.row.col.f32.f16.f16.f32 "
                 "{%0,%1,%2,%3}, {%4,%5,%6,%7}, {%8,%9}, {%0,%1,%2,%3};"
                 : "+f"(d[0]), "+f"(d[1]), "+f"(d[2]), "+f"(d[3])
                 : "r"(a[0]), "r"(a[1]), "r"(a[2]), "r"(a[3]), "r"(b[0]), "r"(b[1]));
}
__device__ __forceinline__ uint32_t pack2h(__half a, __half b) {
    return (uint32_t)__half_as_ushort(a) | ((uint32_t)__half_as_ushort(b) << 16);
}
__device__ __forceinline__ float2 up2h(uint32_t u) {
    __half2 h = *(__half2*)&u;
    return __half22float2(h);
}
__device__ __forceinline__ uint32_t packsplith(float a, float b, uint32_t& lo) {
    __half h0 = __float2half_rn(a), h1 = __float2half_rn(b);
    lo = pack2h(__float2half_rn(a - __half2float(h0)),
                __float2half_rn(b - __half2float(h1)));
    return pack2h(h0, h1);
}
__device__ __forceinline__ void cp16(uint32_t dst, const void* src, int sz) {
    asm volatile("cp.async.cg.shared.global [%0], [%1], 16, %2;" :: "r"(dst), "l"(src), "r"(sz));
}
#define CP_COMMIT() asm volatile("cp.async.commit_group;" ::: "memory")
#define CP_WAIT0()  asm volatile("cp.async.wait_group 0;" ::: "memory")
#define CP_WAIT1()  asm volatile("cp.async.wait_group 1;" ::: "memory")

__device__ __forceinline__ void red4(float* p, float a, float b, float c, float d) {
    asm volatile("red.global.add.v4.f32 [%0], {%1,%2,%3,%4};"
                 :: "l"(p), "f"(a), "f"(b), "f"(c), "f"(d) : "memory");
}
__device__ __forceinline__ void redf(float* p, float a) {
    asm volatile("red.global.add.f32 [%0], %1;" :: "l"(p), "f"(a) : "memory");
}

// ---------------- fp16 GEMM core: single A; W hi (+ optional lo) -----------
#define HSTG   27648u
#define HA_O   0u
#define HBHI_O 10240u
#define HBLO_O 18944u
#define SMH_GEMM 55296
#define SMH_EDGE 67584

template <bool WPAIR>
struct GemmCoreH {
    uint32_t sb;
    int tid, lid, wm, wn, m0, n0;
    float acc[4][4][4];

    __device__ __forceinline__ void init(uint8_t* smp, int bm, int bn) {
        sb = smem_u32(smp);
        tid = threadIdx.x; lid = tid & 31;
        int wid = tid >> 5;
        wm = wid >> 2; wn = wid & 3;
        m0 = bm * 128; n0 = bn * 128;
#pragma unroll
        for (int i = 0; i < 4; i++)
#pragma unroll
            for (int j = 0; j < 4; j++)
#pragma unroll
                for (int q = 0; q < 4; q++) acc[i][j][q] = 0.f;
    }
    __device__ __forceinline__ void stage(int buf, const __half* A,
                                          const __half* Whi, const __half* Wlo,
                                          int M, int Ncols, int K, int kb) {
        uint32_t base = sb + (uint32_t)buf * HSTG;
#pragma unroll
        for (int i = 0; i < 2; i++) {
            int c = tid + i * 256;
            int row = c >> 2, gr = c & 3;
            bool ok = (m0 + row) < M;
            size_t go = (size_t)(ok ? m0 + row : 0) * K + kb + gr * 8;
            cp16(base + HA_O + (uint32_t)row * 80 + (uint32_t)gr * 16, A + go, ok ? 16 : 0);
        }
#pragma unroll
        for (int i = 0; i < 2; i++) {
            int c = tid + i * 256;
            int k = c >> 4, gr = c & 15;
            size_t go = (size_t)(kb + k) * Ncols + n0 + gr * 8;
            uint32_t d = base + (uint32_t)k * 272 + (uint32_t)gr * 16;
            cp16(d + HBHI_O, Whi + go, 16);
            if (WPAIR) cp16(d + HBLO_O, Wlo + go, 16);
        }
        CP_COMMIT();
    }
    __device__ __forceinline__ void compute(int buf) {
        uint32_t base = sb + (uint32_t)buf * HSTG;
#pragma unroll
        for (int ks = 0; ks < 32; ks += 16) {
            uint32_t bhi[4][2], blo[4][2];
            const uint32_t brow = (uint32_t)(ks + (lid & 15)) * 272 + (uint32_t)((lid >> 4) * 16);
#pragma unroll
            for (int p = 0; p < 2; p++) {
                uint32_t baddr = base + brow + (uint32_t)(wn * 32 + p * 16) * 2;
                uint32_t r[4];
                ldsm4t(r, baddr + HBHI_O);
                bhi[2 * p][0] = r[0]; bhi[2 * p][1] = r[1];
                bhi[2 * p + 1][0] = r[2]; bhi[2 * p + 1][1] = r[3];
                if (WPAIR) {
                    ldsm4t(r, baddr + HBLO_O);
                    blo[2 * p][0] = r[0]; blo[2 * p][1] = r[1];
                    blo[2 * p + 1][0] = r[2]; blo[2 * p + 1][1] = r[3];
                }
            }
            const uint32_t arow = (uint32_t)(wm * 64 + (lid & 15)) * 80
                                + (uint32_t)ks * 2 + (uint32_t)(lid >> 4) * 16;
#pragma unroll
            for (int mt = 0; mt < 4; mt++) {
                uint32_t a4[4];
                ldsm4(a4, base + HA_O + arow + (uint32_t)mt * (16 * 80));
#pragma unroll
                for (int nt = 0; nt < 4; nt++) {
                    mma16816h(acc[mt][nt], a4, bhi[nt]);
                    if (WPAIR) mma16816h(acc[mt][nt], a4, blo[nt]);
                }
            }
        }
    }
    __device__ __forceinline__ void run(const __half* A, const __half* Whi, const __half* Wlo,
                                        int M, int Ncols, int K) {
        const int nch = K >> 5;
        stage(0, A, Whi, Wlo, M, Ncols, K, 0);
        if (nch > 1) stage(1, A, Whi, Wlo, M, Ncols, K, 32);
        for (int i = 0; i < nch; i++) {
            if (i == nch - 1) { CP_WAIT0(); } else { CP_WAIT1(); }
            __syncthreads();
            compute(i & 1);
            if (i + 2 < nch) {
                __syncthreads();
                stage(i & 1, A, Whi, Wlo, M, Ncols, K, (i + 2) * 32);
            }
        }
    }
};

// ---------------- generic fp16 GEMM ----------------
// RESMODE 0=none 1=f32 2=fp16pair; OUTMODE 0=f32 1=fp16 single; STATS col sums
template <int RESMODE, int OUTMODE, bool RELU, bool STATS, bool WPAIR>
__global__ void __launch_bounds__(256, 2)
mma_gemmH(const __half* __restrict__ A,
          const __half* __restrict__ Whi, const __half* __restrict__ Wlo,
          const float* __restrict__ bias, const float* __restrict__ resf,
          const __half* __restrict__ reshi, const __half* __restrict__ reslo,
          float* __restrict__ Cf, __half* __restrict__ Ch,
          float* __restrict__ stats, int M, int Ncols, int K)
{
    extern __shared__ __align__(16) uint8_t sm[];
    GemmCoreH<WPAIR> g;
    g.init(sm, blockIdx.y, blockIdx.x);
    g.run(A, Whi, Wlo, M, Ncols, K);

    float ts0[4], ts1[4], tq0[4], tq1[4];
    if (STATS) {
#pragma unroll
        for (int nt = 0; nt < 4; nt++) { ts0[nt] = ts1[nt] = tq0[nt] = tq1[nt] = 0.f; }
    }

    const int qr = g.lid >> 2, qc = (g.lid & 3) * 2;
#pragma unroll
    for (int mt = 0; mt < 4; mt++) {
#pragma unroll
        for (int nt = 0; nt < 4; nt++) {
            int col = g.n0 + g.wn * 32 + nt * 8 + qc;
            float b0 = bias[col], b1 = bias[col + 1];
#pragma unroll
            for (int half = 0; half < 2; half++) {
                int row = g.m0 + g.wm * 64 + mt * 16 + qr + half * 8;
                if (row >= M) continue;
                float o0 = g.acc[mt][nt][half * 2 + 0] + b0;
                float o1 = g.acc[mt][nt][half * 2 + 1] + b1;
                size_t off = (size_t)row * Ncols + col;
                if (RESMODE == 1) {
                    float2 rr = *(const float2*)(resf + off);
                    o0 += rr.x; o1 += rr.y;
                } else if (RESMODE == 2) {
                    float2 rh = up2h(*(const uint32_t*)(reshi + off));
                    float2 rl = up2h(*(const uint32_t*)(reslo + off));
                    o0 += rh.x + rl.x; o1 += rh.y + rl.y;
                }
                if (RELU) { o0 = fmaxf(o0, 0.f); o1 = fmaxf(o1, 0.f); }
                if (STATS) {
                    ts0[nt] += o0; ts1[nt] += o1;
                    tq0[nt] = fmaf(o0, o0, tq0[nt]); tq1[nt] = fmaf(o1, o1, tq1[nt]);
                }
                if (OUTMODE == 0) {
                    *(float2*)(Cf + off) = make_float2(o0, o1);
                } else {
                    *(uint32_t*)(Ch + off) = pack2h(__float2half_rn(o0), __float2half_rn(o1));
                }
            }
        }
    }
    if (STATS) {
#pragma unroll
        for (int nt = 0; nt < 4; nt++) {
            float a = ts0[nt], b = ts1[nt], c = tq0[nt], d = tq1[nt];
#pragma unroll
            for (int m = 4; m <= 16; m <<= 1) {
                a += __shfl_xor_sync(0xffffffff, a, m);
                b += __shfl_xor_sync(0xffffffff, b, m);
                c += __shfl_xor_sync(0xffffffff, c, m);
                d += __shfl_xor_sync(0xffffffff, d, m);
            }
            if (qr == 0) {
                int col = g.n0 + g.wn * 32 + nt * 8 + qc;
                redf(stats + col, a);
                redf(stats + col + 1, b);
                redf(stats + DIM + col, c);
                redf(stats + DIM + col + 1, d);
            }
        }
    }
}

// ---------------- fused QKV (fp16 single-A, hi/lo W; blockIdx.x = weight) ---
__global__ void __launch_bounds__(256, 2)
qkv_gemm(const __half* __restrict__ x16,
         const __half* __restrict__ qh, const __half* __restrict__ ql,
         const __half* __restrict__ kh, const __half* __restrict__ kl,
         const __half* __restrict__ vh, const __half* __restrict__ vl,
         const float* __restrict__ bq, const float* __restrict__ bk,
         const float* __restrict__ bv,
         float* __restrict__ Qo, float* __restrict__ Ko, float* __restrict__ Vo)
{
    extern __shared__ __align__(16) uint8_t sm[];
    const __half* Whi = qh; const __half* Wlo = ql;
    const float* bias = bq; float* C = Qo;
    if (blockIdx.x == 1) { Whi = kh; Wlo = kl; bias = bk; C = Ko; }
    else if (blockIdx.x == 2) { Whi = vh; Wlo = vl; bias = bv; C = Vo; }

    GemmCoreH<true> g;
    g.init(sm, blockIdx.y, 0);
    g.run(x16, Whi, Wlo, NN, 128, 128);

    const int qr = g.lid >> 2, qc = (g.lid & 3) * 2;
#pragma unroll
    for (int mt = 0; mt < 4; mt++) {
#pragma unroll
        for (int nt = 0; nt < 4; nt++) {
            int col = g.wn * 32 + nt * 8 + qc;
            float b0 = bias[col], b1 = bias[col + 1];
#pragma unroll
            for (int half = 0; half < 2; half++) {
                int row = g.m0 + g.wm * 64 + mt * 16 + qr + half * 8;
                if (row >= NN) continue;
                *(float2*)(C + (size_t)row * 128 + col) =
                    make_float2(g.acc[mt][nt][half * 2 + 0] + b0,
                                g.acc[mt][nt][half * 2 + 1] + b1);
            }
        }
    }
}

// ---------------- fused Ee GEMM (pure fp16, 1 product) + edge epilogue ------
union U16 { float4 q[4]; float f[16]; };

__global__ void __launch_bounds__(256, 2)
edge_gemm_fused(const __half* __restrict__ ea16,
                const __half* __restrict__ weh,
                const float* __restrict__ bias,
                const int* __restrict__ ei, const float* __restrict__ Aw,
                const float* __restrict__ Qh, const float* __restrict__ Kh,
                __half* __restrict__ et16, float* __restrict__ lg)
{
    extern __shared__ __align__(16) uint8_t sm[];
    __shared__ float sAw[DIM];
    if (threadIdx.x < DIM) sAw[threadIdx.x] = Aw[threadIdx.x];

    GemmCoreH<false> g;
    g.init(sm, blockIdx.y, blockIdx.x);
    g.run(ea16, weh, nullptr, NE, 256, 128);

    __syncthreads();
    float* sC = (float*)sm;
    const int qr = g.lid >> 2, qc = (g.lid & 3) * 2;
#pragma unroll
    for (int mt = 0; mt < 4; mt++) {
#pragma unroll
        for (int nt = 0; nt < 4; nt++) {
            int col = g.wn * 32 + nt * 8 + qc;
            float b0 = bias[g.n0 + col], b1 = bias[g.n0 + col + 1];
#pragma unroll
            for (int half = 0; half < 2; half++) {
                int row = g.wm * 64 + mt * 16 + qr + half * 8;
                *(float2*)(sC + row * 132 + col) =
                    make_float2(g.acc[mt][nt][half * 2 + 0] + b0,
                                g.acc[mt][nt][half * 2 + 1] + b1);
            }
        }
    }
    __syncthreads();

    const int e = threadIdx.x & 127;
    const int ge = g.m0 + e;                    // NE % 128 == 0
    const int src = ei[ge], dst = ei[NE + ge];
#pragma unroll
    for (int u = 0; u < 2; u++) {
        const int hl = (threadIdx.x >> 7) * 2 + u;
        const int h = blockIdx.x * 4 + hl;
        const float* ew = sC + e * 132 + hl * 32;
        U16 K4, Q4, EW, EB, ET;
        const float4* kp = (const float4*)(Kh + (size_t)src * DIM + h * DH);
        const float4* qp = (const float4*)(Qh + (size_t)dst * DIM + h * DH);
#pragma unroll
        for (int q = 0; q < 4; q++) {
            K4.q[q] = kp[q]; Q4.q[q] = qp[q];
            EW.q[q] = *(const float4*)(ew + q * 4);
            EB.q[q] = *(const float4*)(ew + 16 + q * 4);
        }
        float logit = 0.f;
#pragma unroll
        for (int d = 0; d < 16; d++) {
            float s = (K4.f[d] + Q4.f[d]) * EW.f[d];
            float a = fabsf(s);
            float r = (a > 0.f) ? copysignf(sqrtf(a), s) : 0.f;
            float v = fmaxf(r + EB.f[d], 0.f);
            ET.f[d] = v;
            logit = fmaf(v, sAw[d * NH + h], logit);
        }
        logit = fminf(fmaxf(logit, -5.f), 5.f);
        uint32_t hw[8];
#pragma unroll
        for (int q = 0; q < 8; q++)
            hw[q] = pack2h(__float2half_rn(ET.f[2 * q]), __float2half_rn(ET.f[2 * q + 1]));
        __half* pe = et16 + (size_t)ge * DIM + h * DH;
        *(uint4*)pe       = make_uint4(hw[0], hw[1], hw[2], hw[3]);
        *((uint4*)pe + 1) = make_uint4(hw[4], hw[5], hw[6], hw[7]);
        lg[ge * NH + h] = expf(logit);
    }
}

// ---------------- WOe GEMM (fp16, hi-only W) + residual + stats; fp16 out ---
__global__ void __launch_bounds__(256, 2)
woe_gemm(const __half* __restrict__ et16,
         const __half* __restrict__ weh,
         const float* __restrict__ bias, const float* __restrict__ resf,
         __half* __restrict__ Ch, float* __restrict__ stats)
{
    extern __shared__ __align__(16) uint8_t sm[];
    GemmCoreH<false> g;
    g.init(sm, blockIdx.y, 0);
    g.run(et16, weh, nullptr, NE, 128, 128);

    float ts0[4], ts1[4], tq0[4], tq1[4];
#pragma unroll
    for (int nt = 0; nt < 4; nt++) { ts0[nt] = ts1[nt] = tq0[nt] = tq1[nt] = 0.f; }

    const int qr = g.lid >> 2, qc = (g.lid & 3) * 2;
#pragma unroll
    for (int mt = 0; mt < 4; mt++) {
#pragma unroll
        for (int nt = 0; nt < 4; nt++) {
            int col = g.wn * 32 + nt * 8 + qc;
            float b0 = bias[col], b1 = bias[col + 1];
#pragma unroll
            for (int half = 0; half < 2; half++) {
                int row = g.m0 + g.wm * 64 + mt * 16 + qr + half * 8;
                float o0 = g.acc[mt][nt][half * 2 + 0] + b0;
                float o1 = g.acc[mt][nt][half * 2 + 1] + b1;
                size_t off = (size_t)row * 128 + col;
                float2 rr = *(const float2*)(resf + off);
                o0 += rr.x; o1 += rr.y;
                ts0[nt] += o0; ts1[nt] += o1;
                tq0[nt] = fmaf(o0, o0, tq0[nt]); tq1[nt] = fmaf(o1, o1, tq1[nt]);
                *(uint32_t*)(Ch + off) = pack2h(__float2half_rn(o0), __float2half_rn(o1));
            }
        }
    }
#pragma unroll
    for (int nt = 0; nt < 4; nt++) {
        float a = ts0[nt], b = ts1[nt], c = tq0[nt], d = tq1[nt];
#pragma unroll
        for (int m = 4; m <= 16; m <<= 1) {
            a += __shfl_xor_sync(0xffffffff, a, m);
            b += __shfl_xor_sync(0xffffffff, b, m);
            c += __shfl_xor_sync(0xffffffff, c, m);
            d += __shfl_xor_sync(0xffffffff, d, m);
        }
        if (qr == 0) {
            int col = g.wn * 32 + nt * 8 + qc;
            redf(stats + col, a);
            redf(stats + col + 1, b);
            redf(stats + DIM + col, c);
            redf(stats + DIM + col + 1, d);
        }
    }
}

// ---------------- misc / edge / node / bn kernels ----------------
__global__ void preconv_h(const float* __restrict__ in, __half* __restrict__ out, long long n)
{
    long long i = ((long long)blockIdx.x * blockDim.x + threadIdx.x) * 4;
    if (i >= n) return;
    float4 v = *(const float4*)(in + i);
    uint2 o;
    o.x = pack2h(__float2half_rn(v.x), __float2half_rn(v.y));
    o.y = pack2h(__float2half_rn(v.z), __float2half_rn(v.w));
    *(uint2*)(out + i) = o;
}

__global__ void preconv_hpair(const float* __restrict__ in, __half* __restrict__ hi,
                              __half* __restrict__ lo, long long n)
{
    long long i = ((long long)blockIdx.x * blockDim.x + threadIdx.x) * 4;
    if (i >= n) return;
    float4 v = *(const float4*)(in + i);
    float vv[4] = {v.x, v.y, v.z, v.w};
    __half hh[4], ll[4];
#pragma unroll
    for (int q = 0; q < 4; q++) {
        hh[q] = __float2half_rn(vv[q]);
        ll[q] = __float2half_rn(vv[q] - __half2float(hh[q]));
    }
    *(uint2*)(hi + i) = make_uint2(pack2h(hh[0], hh[1]), pack2h(hh[2], hh[3]));
    *(uint2*)(lo + i) = make_uint2(pack2h(ll[0], ll[1]), pack2h(ll[2], ll[3]));
}

// denominator + unnormalized scatter; lg holds ex; et single fp16.
__global__ void edge_scatter(const int* __restrict__ ei, const float* __restrict__ lg,
                             float* __restrict__ den, const float* __restrict__ Vh,
                             const __half* __restrict__ et16,
                             float* __restrict__ wV, float* __restrict__ rowV)
{
    int t = blockIdx.x * blockDim.x + threadIdx.x;
    if (t >= NE * NH) return;
    int e = t >> 3, h = t & 7;
    int src = ei[e], dst = ei[NE + e];
    float ex = lg[t];
    redf(&den[dst * NH + h], ex);
    U16 V4, E4;
    const float4* vp = (const float4*)(Vh + (size_t)src * DIM + h * DH);
#pragma unroll
    for (int q = 0; q < 4; q++) V4.q[q] = vp[q];
    const uint4* pe = (const uint4*)(et16 + (size_t)e * DIM + h * DH);
#pragma unroll
    for (int half = 0; half < 2; half++) {
        uint4 E = pe[half];
        uint32_t ew[4] = {E.x, E.y, E.z, E.w};
#pragma unroll
        for (int q = 0; q < 4; q++) {
            float2 f = up2h(ew[q]);
            E4.f[half * 8 + q * 2 + 0] = f.x;
            E4.f[half * 8 + q * 2 + 1] = f.y;
        }
    }
    float* wv = wV + (size_t)dst * DIM + h * DH;
    float* rv = rowV + (size_t)dst * DIM + h * DH;
#pragma unroll
    for (int q = 0; q < 4; q++) {
        red4(wv + q * 4, V4.q[q].x * ex, V4.q[q].y * ex, V4.q[q].z * ex, V4.q[q].w * ex);
        red4(rv + q * 4, E4.f[q * 4] * ex, E4.f[q * 4 + 1] * ex,
             E4.f[q * 4 + 2] * ex, E4.f[q * 4 + 3] * ex);
    }
}

__global__ void node_fix(const float* __restrict__ wV, const float* __restrict__ rowV,
                         const float* __restrict__ den,
                         const float* __restrict__ VeRow, const float* __restrict__ log_deg,
                         const float* __restrict__ deg_coef, __half* __restrict__ hatt16)
{
    int t = blockIdx.x * blockDim.x + threadIdx.x;
    if (t >= NN * 64) return;
    int n = t >> 6, c0 = (t & 63) * 2, h = c0 >> 4, co = c0 & 15;
    size_t off = (size_t)n * DIM + c0;
    float inv = 1.f / (den[n * NH + h] + 1e-16f);
    float a0 = wV[off], a1 = wV[off + 1];
    const float* rv = rowV + (size_t)n * DIM + h * DH;
#pragma unroll
    for (int d2 = 0; d2 < 16; d2++) {
        float r = rv[d2];
        a0 = fmaf(r, VeRow[d2 * DIM + h * DH + co], a0);
        a1 = fmaf(r, VeRow[d2 * DIM + h * DH + co + 1], a1);
    }
    a0 *= inv; a1 *= inv;
    float ld = log_deg[n];
    float o0 = a0 * (deg_coef[2 * c0] + ld * deg_coef[2 * c0 + 1]);
    float o1 = a1 * (deg_coef[2 * c0 + 2] + ld * deg_coef[2 * c0 + 3]);
    *(uint32_t*)(hatt16 + off) = pack2h(__float2half_rn(o0), __float2half_rn(o1));
}

// INM 0 = fp32 in, 1 = fp16 in; OUTM 0 = fp32 out, 1 = fp16 hi/lo pair out
template <int INM, int OUTM>
__global__ void bn_apply(const float* __restrict__ vf, const __half* __restrict__ vh,
                         float* __restrict__ outf,
                         __half* __restrict__ outhi, __half* __restrict__ outlo, int M,
                         const float* __restrict__ sums,
                         const float* __restrict__ g, const float* __restrict__ b, float invM)
{
    long long i = ((long long)blockIdx.x * blockDim.x + threadIdx.x) * 2;
    if (i >= (long long)M * DIM) return;
    int c = (int)(i & (DIM - 1));
    float m0 = sums[c] * invM, m1 = sums[c + 1] * invM;
    float var0 = fmaf(-m0, m0, sums[DIM + c] * invM);
    float var1 = fmaf(-m1, m1, sums[DIM + c + 1] * invM);
    float2 vv;
    if (INM == 0) vv = *(const float2*)(vf + i);
    else          vv = up2h(*(const uint32_t*)(vh + i));
    float o0 = (vv.x - m0) * rsqrtf(var0 + 1e-5f) * g[c] + b[c];
    float o1 = (vv.y - m1) * rsqrtf(var1 + 1e-5f) * g[c + 1] + b[c + 1];
    if (OUTM == 0) {
        *(float2*)(outf + i) = make_float2(o0, o1);
    } else {
        uint32_t lw, hw = packsplith(o0, o1, lw);
        *(uint32_t*)(outhi + i) = hw;
        *(uint32_t*)(outlo + i) = lw;
    }
}

// ---------------- launch ----------------
#define SYM(var, sym) cudaGetSymbolAddress((void**)&var, sym)

extern "C" void kernel_launch(void* const* d_in, const int* in_sizes, int n_in,
                              void* d_out, int out_size)
{
    const float* x         = (const float*)d_in[0];
    const float* edge_attr = (const float*)d_in[1];
    const int*   ei        = (const int*)d_in[2];
    const float* log_deg   = (const float*)d_in[3];
    const float* Wq = (const float*)d_in[4],  *bq  = (const float*)d_in[5];
    const float* Wk = (const float*)d_in[6],  *bk  = (const float*)d_in[7];
    const float* We = (const float*)d_in[8],  *be  = (const float*)d_in[9];
    const float* Wv = (const float*)d_in[10], *bv  = (const float*)d_in[11];
    const float* Aw = (const float*)d_in[12], *VeRow = (const float*)d_in[13];
    const float* WOh = (const float*)d_in[14], *bOh = (const float*)d_in[15];
    const float* WOe = (const float*)d_in[16], *bOe = (const float*)d_in[17];
    const float* deg_coef = (const float*)d_in[18];
    const float* g1h = (const float*)d_in[19], *b1h = (const float*)d_in[20];
    const float* g1e = (const float*)d_in[21], *b1e = (const float*)d_in[22];
    const float* g2h = (const float*)d_in[23], *b2h = (const float*)d_in[24];
    const float* W1 = (const float*)d_in[25], *b1 = (const float*)d_in[26];
    const float* W2 = (const float*)d_in[27], *b2 = (const float*)d_in[28];

    float *Qh, *Kh, *Vh, *lg, *den, *wV, *rowV, *v1, *v2, *s1, *s2buf, *se;
    SYM(Qh, g_Qh); SYM(Kh, g_Kh); SYM(Vh, g_Vh);
    SYM(lg, g_lg); SYM(den, g_den);
    SYM(wV, g_wV); SYM(rowV, g_rowV);
    SYM(v1, g_v1); SYM(v2, g_v2);
    SYM(s1, g_s1); SYM(s2buf, g_s2); SYM(se, g_se);
    __half *x16, *ea16, *et16, *we16h, *woe16h;
    SYM(x16, g_x16); SYM(ea16, g_ea16); SYM(et16, g_et16);
    SYM(we16h, g_we16h); SYM(woe16h, g_woe16h);
    __half *hatt16, *hbn16h, *hbn16l, *h2a16, *woh16h, *w116h, *w216h;
    SYM(hatt16, g_hatt16); SYM(hbn16h, g_hbn16h); SYM(hbn16l, g_hbn16l);
    SYM(h2a16, g_h2a16);
    SYM(woh16h, g_woh16h);
    SYM(w116h, g_w116h);
    SYM(w216h, g_w216h);
    __half *wq16h, *wq16l, *wk16h, *wk16l, *wv16h, *wv16l;
    SYM(wq16h, g_wq16h); SYM(wq16l, g_wq16l);
    SYM(wk16h, g_wk16h); SYM(wk16l, g_wk16l);
    SYM(wv16h, g_wv16h); SYM(wv16l, g_wv16l);

    float* hout = (float*)d_out;
    float* eout = (float*)d_out + (size_t)NN * DIM;

    cudaFuncSetAttribute(qkv_gemm, cudaFuncAttributeMaxDynamicSharedMemorySize, SMH_GEMM);
    cudaFuncSetAttribute(edge_gemm_fused, cudaFuncAttributeMaxDynamicSharedMemorySize, SMH_EDGE);
    cudaFuncSetAttribute(woe_gemm, cudaFuncAttributeMaxDynamicSharedMemorySize, SMH_GEMM);
    cudaFuncSetAttribute(mma_gemmH<1, 0, false, true,  false>, cudaFuncAttributeMaxDynamicSharedMemorySize, SMH_GEMM);
    cudaFuncSetAttribute(mma_gemmH<0, 1, true,  false, false>, cudaFuncAttributeMaxDynamicSharedMemorySize, SMH_GEMM);
    cudaFuncSetAttribute(mma_gemmH<2, 0, false, true,  false>, cudaFuncAttributeMaxDynamicSharedMemorySize, SMH_GEMM);

    // lazily-created side stream + events
    static cudaStream_t sside = nullptr;
    static cudaEvent_t ev0 = nullptr, evA = nullptr, ev1 = nullptr, ev2 = nullptr;
    if (!sside) {
        cudaStreamCreateWithFlags(&sside, cudaStreamNonBlocking);
        cudaEventCreateWithFlags(&ev0, cudaEventDisableTiming);
        cudaEventCreateWithFlags(&evA, cudaEventDisableTiming);
        cudaEventCreateWithFlags(&ev1, cudaEventDisableTiming);
        cudaEventCreateWithFlags(&ev2, cudaEventDisableTiming);
    }

    // fork side stream; big edge_attr fp16 preconv there
    cudaEventRecord(ev0, 0);
    cudaStreamWaitEvent(sside, ev0, 0);
    preconv_h<<<cdiv((long long)NE * DIM / 4, 256), 256, 0, sside>>>(edge_attr, ea16, (long long)NE * DIM);
    cudaEventRecord(evA, sside);

    // main: small preconvs + memsets + QKV
    preconv_h<<<cdiv((long long)NN * DIM / 4, 256), 256>>>(x, x16, (long long)NN * DIM);
    preconv_hpair<<<cdiv(DIM * DIM / 4, 256), 256>>>(Wq, wq16h, wq16l, DIM * DIM);
    preconv_hpair<<<cdiv(DIM * DIM / 4, 256), 256>>>(Wk, wk16h, wk16l, DIM * DIM);
    preconv_hpair<<<cdiv(DIM * DIM / 4, 256), 256>>>(Wv, wv16h, wv16l, DIM * DIM);
    preconv_h<<<cdiv(DIM * 2 * DIM / 4, 256), 256>>>(We, we16h, DIM * 2 * DIM);
    preconv_h<<<cdiv(DIM * DIM / 4, 256), 256>>>(WOe, woe16h, DIM * DIM);
    preconv_h<<<cdiv(DIM * DIM / 4, 256), 256>>>(WOh, woh16h, DIM * DIM);
    preconv_h<<<cdiv(DIM * 2 * DIM / 4, 256), 256>>>(W1, w116h, DIM * 2 * DIM);
    preconv_h<<<cdiv(2 * DIM * DIM / 4, 256), 256>>>(W2, w216h, 2 * DIM * DIM);

    cudaMemsetAsync(wV, 0, (size_t)NN * DIM * sizeof(float));
    cudaMemsetAsync(rowV, 0, (size_t)NN * DIM * sizeof(float));
    cudaMemsetAsync(den, 0, (size_t)NN * NH * sizeof(float));
    cudaMemsetAsync(s1, 0, 2 * DIM * sizeof(float));
    cudaMemsetAsync(s2buf, 0, 2 * DIM * sizeof(float));
    cudaMemsetAsync(se, 0, 2 * DIM * sizeof(float));

    const int gN = cdiv(NN, 128), gE = cdiv(NE, 128);

    qkv_gemm<<<dim3(3, gN), 256, SMH_GEMM>>>(x16, wq16h, wq16l, wk16h, wk16l,
                                             wv16h, wv16l, bq, bk, bv, Qh, Kh, Vh);

    cudaStreamWaitEvent(0, evA, 0);
    edge_gemm_fused<<<dim3(2, gE), 256, SMH_EDGE>>>(ea16, we16h, be,
                                                    ei, Aw, Qh, Kh, et16, lg);
    cudaEventRecord(ev1, 0);

    // side stream: e-path — WOe (hi-only W, fp16 pre-BN out into dead ea16),
    // then BN apply reads fp16 and writes final fp32 eout
    cudaStreamWaitEvent(sside, ev1, 0);
    woe_gemm<<<dim3(1, gE), 256, SMH_GEMM, sside>>>(et16, woe16h, bOe, edge_attr, ea16, se);
    bn_apply<1, 0><<<cdiv((long long)NE * 64, 256), 256, 0, sside>>>(
        nullptr, ea16, eout, nullptr, nullptr, NE, se, g1e, b1e, 1.f / NE);
    cudaEventRecord(ev2, sside);

    // main stream: h-path (fp16 single-A, hi-only-W GEMMs)
    edge_scatter<<<cdiv(NE * NH, 256), 256>>>(ei, lg, den, Vh, et16, wV, rowV);
    node_fix<<<cdiv(NN * 64, 256), 256>>>(wV, rowV, den, VeRow, log_deg, deg_coef, hatt16);
    mma_gemmH<1, 0, false, true, false><<<dim3(1, gN), 256, SMH_GEMM>>>(
        hatt16, woh16h, nullptr, bOh, x, nullptr, nullptr, v1, nullptr, s1, NN, 128, 128);
    bn_apply<0, 1><<<cdiv((long long)NN * 64, 256), 256>>>(
        v1, nullptr, nullptr, hbn16h, hbn16l, NN, s1, g1h, b1h, 1.f / NN);
    mma_gemmH<0, 1, true, false, false><<<dim3(2, gN), 256, SMH_GEMM>>>(
        hbn16h, w116h, nullptr, b1, nullptr, nullptr, nullptr, nullptr, h2a16, nullptr, NN, 256, 128);
    mma_gemmH<2, 0, false, true, false><<<dim3(1, gN), 256, SMH_GEMM>>>(
        h2a16, w216h, nullptr, b2, nullptr, hbn16h, hbn16l, v2, nullptr, s2buf, NN, 128, 256);
    bn_apply<0, 0><<<cdiv((long long)NN * 64, 256), 256>>>(
        v2, nullptr, hout, nullptr, nullptr, NN, s2buf, g2h, b2h, 1.f / NN);

    // join side stream back into the captured main stream
    cudaStreamWaitEvent(0, ev2, 0);
}